// round 10
// baseline (speedup 1.0000x reference)
#include <cuda_runtime.h>
#include <math.h>

// ---------------------------------------------------------------------------
// Problem constants
// ---------------------------------------------------------------------------
#define TTS   21      // Tm = CAP-1 decode steps
#define CAPL  22
#define BBS   128     // batch
#define PPS   196     // pixels
#define ENCD  2048
#define DHID  1024
#define VOC   32000

static constexpr long long O_PRED = 0;
static constexpr long long O_CAPS = (long long)BBS * TTS * VOC;   // 86,016,000
static constexpr long long O_DECL = O_CAPS + (long long)BBS * CAPL;
static constexpr long long O_SORT = O_DECL + BBS;
static constexpr long long O_RPOS = O_SORT + BBS;
static constexpr long long O_PPOS = O_RPOS + (long long)BBS * TTS;

// ---------------------------------------------------------------------------
// Static device scratch (no runtime allocation allowed)
// ---------------------------------------------------------------------------
__device__ float d_encs [(size_t)BBS * PPS * ENCD];   // sorted encoder
__device__ float d_att1 [(size_t)BBS * PPS * DHID];   // att1
__device__ float d_econ [(size_t)TTS * BBS * 4 * DHID]; // embed @ Wih_e^T
__device__ float d_embg [(size_t)TTS * BBS * DHID];   // gathered embeddings
__device__ float d_W1cat[4096 * 2048];                // [Wih(:,1024:2048) | Whh]
__device__ float d_W2cat[(size_t)4096 * 4096];        // [l2_Wih | l2_Whh]
__device__ float d_W3cat[3072 * 1024];                // [dec_att_W ; f_beta_W]
__device__ float d_b1sum[4096];
__device__ float d_b2sum[4096];
__device__ float d_b3cat[3072];
__device__ float d_base1[BBS * 4096];                 // biases + mean_enc contrib
__device__ float d_gates[BBS * 4096];
__device__ float d_x1   [BBS * 2048];                 // [h2_state | h1_state]
__device__ float d_x2   [BBS * 4096];                 // [att | h1n | h2_state]
__device__ float d_ag   [BBS * 3072];                 // [att2 | gate logits]
__device__ float d_c1   [BBS * DHID];
__device__ float d_c2   [BBS * DHID];
__device__ float d_mean [BBS * ENCD];
__device__ float d_h2all[(size_t)TTS * BBS * DHID];   // h2n (active rows only)
__device__ int   d_sort  [BBS];
__device__ int   d_declen[BBS];
__device__ int   d_tokens[TTS * BBS];
__device__ int   d_nact  [TTS];                       // active prefix size per t
__device__ int   d_rowidx[TTS * BBS];                 // compact -> t*BBS+b
__device__ int   d_outrow[TTS * BBS];                 // compact -> b*TTS+t
__device__ int   d_cnt;                               // number of active pairs

// ---------------------------------------------------------------------------
// Math helpers
// ---------------------------------------------------------------------------
__device__ __forceinline__ float sigf(float x) {
    return 1.0f / (1.0f + __expf(-x));
}
__device__ __forceinline__ float tanh_fast(float x) {
    return 1.0f - 2.0f / (__expf(2.0f * x) + 1.0f);
}

// Packed fp32x2 FMA (sm_100+): one fma-pipe slot, two FMAs.
__device__ __forceinline__ void ffma2(unsigned long long& acc,
                                      unsigned long long a,
                                      unsigned long long b) {
    asm("fma.rn.f32x2 %0, %1, %2, %0;" : "+l"(acc) : "l"(a), "l"(b));
}
__device__ __forceinline__ unsigned long long pack_dup(float x) {
    unsigned long long r;
    asm("mov.b64 %0, {%1, %1};" : "=l"(r) : "f"(x));
    return r;
}
__device__ __forceinline__ void unpack2(unsigned long long v,
                                        float& lo, float& hi) {
    asm("mov.b64 {%0, %1}, %2;" : "=f"(lo), "=f"(hi) : "l"(v));
}

// ---------------------------------------------------------------------------
// Setup: stable descending argsort; caps/dec_len/sort/rel_pos out; active
// prefix sizes and compact active-row lists.
// ---------------------------------------------------------------------------
__global__ void setup_kernel(const int* __restrict__ caplen,
                             const int* __restrict__ caps,
                             float* __restrict__ out) {
    __shared__ int lens_s[BBS];
    __shared__ int sort_s[BBS];
    __shared__ int dl_s[BBS];
    int i = threadIdx.x;
    int li = caplen[i];
    lens_s[i] = li;
    __syncthreads();
    int rank = 0;
    for (int j = 0; j < BBS; ++j) {
        int lj = lens_s[j];
        if (lj > li || (lj == li && j < i)) rank++;
    }
    sort_s[rank] = i;
    __syncthreads();
    int src = sort_s[i];
    d_sort[i] = src;
    int dl = lens_s[src] - 1;
    d_declen[i] = dl;
    dl_s[i] = dl;
    out[O_DECL + i] = (float)dl;
    out[O_SORT + i] = (float)src;
    for (int t = 0; t < CAPL; ++t) {
        int tok = caps[src * CAPL + t];
        out[O_CAPS + (long long)i * CAPL + t] = (float)tok;
        if (t < TTS) d_tokens[t * BBS + i] = tok;
    }
    float dlf = (float)dl;
    for (int s = 0; s < TTS; ++s)
        out[O_RPOS + (long long)i * TTS + s] =
            (s < dl) ? ((float)(s + 1) / dlf) : 0.0f;
    __syncthreads();
    if (i == 0) {
        int c = 0;
        for (int t = 0; t < TTS; ++t) {
            int n = 0;
            while (n < BBS && dl_s[n] > t) n++;   // dl_s sorted descending
            d_nact[t] = n;
            for (int b = 0; b < n; ++b) {
                d_rowidx[c] = t * BBS + b;
                d_outrow[c] = b * TTS + t;
                c++;
            }
        }
        d_cnt = c;
    }
}

// ---------------------------------------------------------------------------
// Gather sorted encoder rows (float4)
// ---------------------------------------------------------------------------
__global__ void gather_enc_kernel(const float* __restrict__ enc) {
    int g = blockIdx.x * 256 + threadIdx.x;
    const int V4ROW = ENCD / 4;                      // 512
    int r = g / V4ROW;
    int w = g % V4ROW;
    int b = r / PPS, p = r % PPS;
    int srow = d_sort[b] * PPS + p;
    const float4* src = (const float4*)enc;
    float4* dst = (float4*)d_encs;
    dst[(size_t)r * V4ROW + w] = src[(size_t)srow * V4ROW + w];
}

// ---------------------------------------------------------------------------
// mean over pixels: one thread per (b,e)
// ---------------------------------------------------------------------------
__global__ void mean_kernel() {
    int idx = blockIdx.x * 256 + threadIdx.x;
    int b = idx / ENCD, e = idx % ENCD;
    const float* base = d_encs + (size_t)b * PPS * ENCD + e;
    float s = 0.f;
    #pragma unroll 4
    for (int p = 0; p < PPS; ++p) s += base[(size_t)p * ENCD];
    d_mean[idx] = s * (1.0f / (float)PPS);
}

// ---------------------------------------------------------------------------
// Weight concatenation copies (float4) + bias sums
// ---------------------------------------------------------------------------
__global__ void w1copy_kernel(const float* __restrict__ l1Wih,
                              const float* __restrict__ l1Whh) {
    int g = blockIdx.x * 256 + threadIdx.x;
    int j = g / (2048 / 4);
    int c = (g % (2048 / 4)) * 4;
    float4 v;
    if (c < 1024) v = *(const float4*)(l1Wih + (size_t)j * 4096 + 1024 + c);
    else          v = *(const float4*)(l1Whh + (size_t)j * 1024 + (c - 1024));
    *(float4*)(d_W1cat + (size_t)j * 2048 + c) = v;
}

__global__ void w2copy_kernel(const float* __restrict__ l2Wih,
                              const float* __restrict__ l2Whh) {
    int g = blockIdx.x * 256 + threadIdx.x;
    int j = g / (4096 / 4);
    int c = (g % (4096 / 4)) * 4;
    float4 v;
    if (c < 3072) v = *(const float4*)(l2Wih + (size_t)j * 3072 + c);
    else          v = *(const float4*)(l2Whh + (size_t)j * 1024 + (c - 3072));
    *(float4*)(d_W2cat + (size_t)j * 4096 + c) = v;
}

__global__ void w3copy_kernel(const float* __restrict__ daW,
                              const float* __restrict__ fbW) {
    int g = blockIdx.x * 256 + threadIdx.x;
    int j = g / (1024 / 4);
    int c = (g % (1024 / 4)) * 4;
    float4 v;
    if (j < 1024) v = *(const float4*)(daW + (size_t)j * 1024 + c);
    else          v = *(const float4*)(fbW + (size_t)(j - 1024) * 1024 + c);
    *(float4*)(d_W3cat + (size_t)j * 1024 + c) = v;
}

__global__ void bias_kernel(const float* __restrict__ l1bih,
                            const float* __restrict__ l1bhh,
                            const float* __restrict__ l2bih,
                            const float* __restrict__ l2bhh,
                            const float* __restrict__ dab,
                            const float* __restrict__ fbb) {
    int j = blockIdx.x * 256 + threadIdx.x;
    d_b1sum[j] = l1bih[j] + l1bhh[j];
    d_b2sum[j] = l2bih[j] + l2bhh[j];
    if (j < 3072) d_b3cat[j] = (j < 1024) ? dab[j] : fbb[j - 1024];
}

// ---------------------------------------------------------------------------
// Gather token embeddings: one block per (t,b) row
// ---------------------------------------------------------------------------
__global__ void embg_kernel(const float* __restrict__ emb) {
    int m = blockIdx.x;
    int tok = d_tokens[m];
    const float4* src = (const float4*)(emb + (size_t)tok * DHID);
    float4* dst = (float4*)(d_embg + (size_t)m * DHID);
    dst[threadIdx.x] = src[threadIdx.x];
}

// ---------------------------------------------------------------------------
// Zero initial states / zero the whole predictions region
// ---------------------------------------------------------------------------
__global__ void zero_states_kernel() {
    int idx = blockIdx.x * 256 + threadIdx.x;        // 0 .. 524287
    d_x2[idx] = 0.f;
    if (idx < BBS * 2048) d_x1[idx] = 0.f;
    if (idx < BBS * DHID) { d_c1[idx] = 0.f; d_c2[idx] = 0.f; }
}

__global__ void zero_pred_kernel(float* __restrict__ out) {
    size_t g = (size_t)blockIdx.x * 256 + threadIdx.x;  // float4 index
    ((float4*)out)[g] = make_float4(0.f, 0.f, 0.f, 0.f);
}

// ---------------------------------------------------------------------------
// Big GEMM: 128x128 tile, BK=16, 256 threads, 8x8 microtile, conflict-free
// 4+4 split fragments, packed f32x2 FMA inner loop (2 FLOPs per fma-slot).
// C[m,n] = sum_k A[m,k]*B[n,k]
// MODE 0: plain   MODE 1: +bias[n]
// MODE 2: +bias, A-rows gathered via d_rowidx, stores scattered via d_outrow,
//         rows >= d_cnt skipped (predictions path).
// ---------------------------------------------------------------------------
template<int MODE>
__global__ void __launch_bounds__(256, 2)
gemm128(const float* __restrict__ A,
        const float* __restrict__ Bm,
        const float* __restrict__ bias,
        float* __restrict__ C,
        int N, int K, int lda, int ldb, int ldc) {
    __shared__ float As[16][132];
    __shared__ float Bs[16][132];
    const int tid = threadIdx.x;
    const int m0 = blockIdx.y * 128;
    const int n0 = blockIdx.x * 128;
    int count = 0;
    if (MODE == 2) {
        count = d_cnt;
        if (m0 >= count) return;
    }
    const int lr = tid >> 1;            // load row 0..127
    const int lc = (tid & 1) * 8;       // col base 0 or 8
    int arow = m0 + lr;
    if (MODE == 2) arow = (m0 + lr < count) ? d_rowidx[m0 + lr] : d_rowidx[0];
    const float* Aptr = A + (size_t)arow * lda + lc;
    const float* Bptr = Bm + (size_t)(n0 + lr) * ldb + lc;

    const int ty = tid >> 4;            // 0..15 (m)
    const int tx = tid & 15;            // 0..15 (n)

    unsigned long long acc[8][4];
    #pragma unroll
    for (int i = 0; i < 8; ++i)
        #pragma unroll
        for (int j = 0; j < 4; ++j) acc[i][j] = 0ull;

    for (int k0 = 0; k0 < K; k0 += 16) {
        float4 a0 = *(const float4*)(Aptr + k0);
        float4 a1 = *(const float4*)(Aptr + k0 + 4);
        float4 b0 = *(const float4*)(Bptr + k0);
        float4 b1 = *(const float4*)(Bptr + k0 + 4);
        As[lc + 0][lr] = a0.x; As[lc + 1][lr] = a0.y;
        As[lc + 2][lr] = a0.z; As[lc + 3][lr] = a0.w;
        As[lc + 4][lr] = a1.x; As[lc + 5][lr] = a1.y;
        As[lc + 6][lr] = a1.z; As[lc + 7][lr] = a1.w;
        Bs[lc + 0][lr] = b0.x; Bs[lc + 1][lr] = b0.y;
        Bs[lc + 2][lr] = b0.z; Bs[lc + 3][lr] = b0.w;
        Bs[lc + 4][lr] = b1.x; Bs[lc + 5][lr] = b1.y;
        Bs[lc + 6][lr] = b1.z; Bs[lc + 7][lr] = b1.w;
        __syncthreads();
        #pragma unroll
        for (int kk = 0; kk < 16; ++kk) {
            union { float4 v; float f[4]; } au0, au1;
            union { float4 v; unsigned long long u[2]; } bu0, bu1;
            au0.v = *(const float4*)&As[kk][ty * 4];
            au1.v = *(const float4*)&As[kk][64 + ty * 4];
            bu0.v = *(const float4*)&Bs[kk][tx * 4];
            bu1.v = *(const float4*)&Bs[kk][64 + tx * 4];
            #pragma unroll
            for (int i = 0; i < 8; ++i) {
                unsigned long long aa =
                    pack_dup(i < 4 ? au0.f[i] : au1.f[i - 4]);
                ffma2(acc[i][0], aa, bu0.u[0]);
                ffma2(acc[i][1], aa, bu0.u[1]);
                ffma2(acc[i][2], aa, bu1.u[0]);
                ffma2(acc[i][3], aa, bu1.u[1]);
            }
        }
        __syncthreads();
    }

    float bv[8];
    #pragma unroll
    for (int j = 0; j < 8; ++j) {
        int n = (j < 4) ? (n0 + tx * 4 + j) : (n0 + 64 + tx * 4 + j - 4);
        bv[j] = (MODE >= 1) ? bias[n] : 0.f;
    }

    #pragma unroll
    for (int i = 0; i < 8; ++i) {
        int mi = (i < 4) ? (ty * 4 + i) : (64 + ty * 4 + i - 4);
        int m = m0 + mi;
        long long crow = m;
        if (MODE == 2) {
            if (m >= count) continue;
            crow = d_outrow[m];
        }
        float c[8];
        unpack2(acc[i][0], c[0], c[1]);
        unpack2(acc[i][1], c[2], c[3]);
        unpack2(acc[i][2], c[4], c[5]);
        unpack2(acc[i][3], c[6], c[7]);
        float* dst = C + crow * (long long)ldc + n0;
        float4 v0, v1;
        v0.x = c[0] + bv[0]; v0.y = c[1] + bv[1];
        v0.z = c[2] + bv[2]; v0.w = c[3] + bv[3];
        v1.x = c[4] + bv[4]; v1.y = c[5] + bv[5];
        v1.z = c[6] + bv[6]; v1.w = c[7] + bv[7];
        *(float4*)(dst + tx * 4)      = v0;
        *(float4*)(dst + 64 + tx * 4) = v1;
    }
}

// ---------------------------------------------------------------------------
// Skinny GEMM: 32x128 tile, BK=16, 128 threads, 4x8 microtile, conflict-free
// split fragments, packed f32x2 FMA, register prefetch. fp32.
// MODE 0: +bias[n]    MODE 1: +add0[m,n] + add1[m,n]  (stride ldc)
// t >= 0: early-exit blocks whose rows are entirely inactive (m0 >= nact[t]).
// ---------------------------------------------------------------------------
template<int MODE>
__global__ void __launch_bounds__(128)
gemm32(const float* __restrict__ A,
       const float* __restrict__ Bm,
       const float* __restrict__ bias,
       const float* __restrict__ add0,
       const float* __restrict__ add1,
       float* __restrict__ C,
       int N, int K, int lda, int ldb, int ldc, int t) {
    const int m0 = blockIdx.y * 32;
    if (t >= 0 && m0 >= d_nact[t]) return;
    __shared__ float As[16][36];
    __shared__ float Bs[16][132];
    const int tid = threadIdx.x;
    const int n0 = blockIdx.x * 128;

    const int ar = tid >> 2;            // A load row 0..31
    const int ac = (tid & 3) * 4;       // A col 0,4,8,12
    const float* Aptr = A + (size_t)(m0 + ar) * lda + ac;
    const float* Bptr = Bm + (size_t)(n0 + tid) * ldb;

    const int ty = tid >> 4;            // 0..7  (m)
    const int tx = tid & 15;            // 0..15 (n)

    unsigned long long acc[4][4];
    #pragma unroll
    for (int i = 0; i < 4; ++i)
        #pragma unroll
        for (int j = 0; j < 4; ++j) acc[i][j] = 0ull;

    float4 pav = *(const float4*)(Aptr);
    float4 pb[4];
    #pragma unroll
    for (int j = 0; j < 4; ++j) pb[j] = *(const float4*)(Bptr + j * 4);

    for (int k0 = 0; k0 < K; k0 += 16) {
        As[ac + 0][ar] = pav.x; As[ac + 1][ar] = pav.y;
        As[ac + 2][ar] = pav.z; As[ac + 3][ar] = pav.w;
        #pragma unroll
        for (int j = 0; j < 4; ++j) {
            Bs[j * 4 + 0][tid] = pb[j].x; Bs[j * 4 + 1][tid] = pb[j].y;
            Bs[j * 4 + 2][tid] = pb[j].z; Bs[j * 4 + 3][tid] = pb[j].w;
        }
        __syncthreads();
        if (k0 + 16 < K) {
            pav = *(const float4*)(Aptr + k0 + 16);
            #pragma unroll
            for (int j = 0; j < 4; ++j)
                pb[j] = *(const float4*)(Bptr + k0 + 16 + j * 4);
        }
        #pragma unroll
        for (int kk = 0; kk < 16; ++kk) {
            union { float4 v; float f[4]; } au;
            union { float4 v; unsigned long long u[2]; } bu0, bu1;
            au.v  = *(const float4*)&As[kk][ty * 4];
            bu0.v = *(const float4*)&Bs[kk][tx * 4];
            bu1.v = *(const float4*)&Bs[kk][64 + tx * 4];
            #pragma unroll
            for (int i = 0; i < 4; ++i) {
                unsigned long long aa = pack_dup(au.f[i]);
                ffma2(acc[i][0], aa, bu0.u[0]);
                ffma2(acc[i][1], aa, bu0.u[1]);
                ffma2(acc[i][2], aa, bu1.u[0]);
                ffma2(acc[i][3], aa, bu1.u[1]);
            }
        }
        __syncthreads();
    }

    float bv[8];
    #pragma unroll
    for (int j = 0; j < 8; ++j) {
        int n = (j < 4) ? (n0 + tx * 4 + j) : (n0 + 64 + tx * 4 + j - 4);
        bv[j] = (MODE == 0) ? bias[n] : 0.f;
    }

    #pragma unroll
    for (int i = 0; i < 4; ++i) {
        int m = m0 + ty * 4 + i;
        float c[8];
        unpack2(acc[i][0], c[0], c[1]);
        unpack2(acc[i][1], c[2], c[3]);
        unpack2(acc[i][2], c[4], c[5]);
        unpack2(acc[i][3], c[6], c[7]);
        float* dst = C + (size_t)m * ldc + n0;
        float add[8];
        if (MODE == 1) {
            const float* a0p = add0 + (size_t)m * ldc + n0;
            const float* a1p = add1 + (size_t)m * ldc + n0;
            #pragma unroll
            for (int j = 0; j < 4; ++j) {
                add[j]     = a0p[tx * 4 + j]      + a1p[tx * 4 + j];
                add[j + 4] = a0p[64 + tx * 4 + j] + a1p[64 + tx * 4 + j];
            }
        } else {
            #pragma unroll
            for (int j = 0; j < 8; ++j) add[j] = bv[j];
        }
        float4 v0, v1;
        v0.x = c[0] + add[0]; v0.y = c[1] + add[1];
        v0.z = c[2] + add[2]; v0.w = c[3] + add[3];
        v1.x = c[4] + add[4]; v1.y = c[5] + add[5];
        v1.z = c[6] + add[6]; v1.w = c[7] + add[7];
        *(float4*)(dst + tx * 4)      = v0;
        *(float4*)(dst + 64 + tx * 4) = v1;
    }
}

// ---------------------------------------------------------------------------
// LSTM pointwise kernels (gate order: i, f, g, o). Inactive rows skipped.
// ---------------------------------------------------------------------------
__global__ void lstm1_kernel(int t) {
    int idx = blockIdx.x * 256 + threadIdx.x;
    int b = idx / DHID, k = idx % DHID;
    if (t >= d_declen[b]) return;
    const float* g = d_gates + (size_t)b * 4096;
    float ig = g[k], fg = g[1024 + k], gg = g[2048 + k], og = g[3072 + k];
    float c = d_c1[idx];
    float cn = sigf(fg) * c + sigf(ig) * tanhf(gg);
    float hn = sigf(og) * tanhf(cn);
    d_c1[idx] = cn;
    d_x1[(size_t)b * 2048 + 1024 + k] = hn;          // carried h1 state
    d_x2[(size_t)b * 4096 + 2048 + k] = hn;          // h1n for att2/gates2
}

__global__ void lstm2_kernel(int t) {
    int idx = blockIdx.x * 256 + threadIdx.x;
    int b = idx / DHID, k = idx % DHID;
    if (t >= d_declen[b]) return;
    const float* g = d_gates + (size_t)b * 4096;
    float ig = g[k], fg = g[1024 + k], gg = g[2048 + k], og = g[3072 + k];
    float c = d_c2[idx];
    float cn = sigf(fg) * c + sigf(ig) * tanhf(gg);
    float hn = sigf(og) * tanhf(cn);
    d_c2[idx] = cn;
    d_h2all[(size_t)(t * BBS + b) * DHID + k] = hn;
    d_x1[(size_t)b * 2048 + k] = hn;                 // carried h2 state
    d_x2[(size_t)b * 4096 + 3072 + k] = hn;
}

// ---------------------------------------------------------------------------
// Fused attention: scores = tanh(att1 + att2) . w + b0; softmax over p;
// awe = alpha @ enc; x2.att = sigmoid(gate_logits) * awe.  One block per b.
// ---------------------------------------------------------------------------
__global__ void attn_kernel(const float* __restrict__ fullW,
                            const float* __restrict__ fullb, int t) {
    const int b = blockIdx.x;
    if (t >= d_declen[b]) return;
    __shared__ float s_a2[DHID];
    __shared__ float s_w [DHID];
    __shared__ float s_sc[PPS];
    __shared__ float s_red[256];
    const int tid = threadIdx.x;
    const int lane = tid & 31, warp = tid >> 5;

    for (int i = tid; i < DHID; i += 256) {
        s_a2[i] = d_ag[(size_t)b * 3072 + i];
        s_w[i]  = fullW[i];
    }
    __syncthreads();

    const float b0 = fullb[0];
    for (int p = warp; p < PPS; p += 8) {
        const float* row = d_att1 + ((size_t)b * PPS + p) * DHID;
        float s = 0.f;
        #pragma unroll 8
        for (int a = lane; a < DHID; a += 32)
            s += tanh_fast(row[a] + s_a2[a]) * s_w[a];
        #pragma unroll
        for (int o = 16; o > 0; o >>= 1)
            s += __shfl_down_sync(0xffffffffu, s, o);
        if (lane == 0) s_sc[p] = s + b0;
    }
    __syncthreads();

    s_red[tid] = (tid < PPS) ? s_sc[tid] : -INFINITY;
    __syncthreads();
    for (int s = 128; s > 0; s >>= 1) {
        if (tid < s) s_red[tid] = fmaxf(s_red[tid], s_red[tid + s]);
        __syncthreads();
    }
    float mx = s_red[0];
    __syncthreads();
    float e = 0.f;
    if (tid < PPS) e = __expf(s_sc[tid] - mx);
    s_red[tid] = e;
    __syncthreads();
    for (int s = 128; s > 0; s >>= 1) {
        if (tid < s) s_red[tid] += s_red[tid + s];
        __syncthreads();
    }
    float inv = 1.0f / s_red[0];
    __syncthreads();
    if (tid < PPS) s_sc[tid] = e * inv;
    __syncthreads();

    const float* encb = d_encs + (size_t)b * PPS * ENCD;
    for (int ei = tid; ei < ENCD; ei += 256) {
        float acc = 0.f;
        const float* col = encb + ei;
        #pragma unroll 4
        for (int p = 0; p < PPS; ++p)
            acc = fmaf(s_sc[p], col[(size_t)p * ENCD], acc);
        float gate = sigf(d_ag[(size_t)b * 3072 + 1024 + ei]);
        d_x2[(size_t)b * 4096 + ei] = gate * acc;
    }
}

// ---------------------------------------------------------------------------
// predicted_pos: one warp per (t,b) row
// ---------------------------------------------------------------------------
__global__ void rpm_kernel(const float* __restrict__ rpmW,
                           float* __restrict__ out) {
    int m = blockIdx.x * 8 + (threadIdx.x >> 5);
    if (m >= TTS * BBS) return;
    int lane = threadIdx.x & 31;
    int t = m / BBS, b = m % BBS;
    const float* h = d_h2all + (size_t)m * DHID;
    float s = 0.f;
    #pragma unroll 8
    for (int k = lane; k < DHID; k += 32) s += h[k] * rpmW[k];
    #pragma unroll
    for (int o = 16; o > 0; o >>= 1)
        s += __shfl_down_sync(0xffffffffu, s, o);
    if (lane == 0)
        out[O_PPOS + (long long)b * TTS + t] =
            (t < d_declen[b]) ? sigf(s) : 0.f;
}

// ---------------------------------------------------------------------------
// Launch
// ---------------------------------------------------------------------------
extern "C" void kernel_launch(void* const* d_in, const int* in_sizes, int n_in,
                              void* d_out, int out_size) {
    const float* enc_out = (const float*)d_in[0];
    const int*   caps    = (const int*)  d_in[1];
    const int*   caplen  = (const int*)  d_in[2];
    const float* emb     = (const float*)d_in[3];
    const float* eaW     = (const float*)d_in[4];
    const float* eab     = (const float*)d_in[5];
    const float* daW     = (const float*)d_in[6];
    const float* dab     = (const float*)d_in[7];
    const float* faW     = (const float*)d_in[8];
    const float* fab     = (const float*)d_in[9];
    const float* fbW     = (const float*)d_in[10];
    const float* fbb     = (const float*)d_in[11];
    const float* l1Wih   = (const float*)d_in[12];
    const float* l1Whh   = (const float*)d_in[13];
    const float* l1bih   = (const float*)d_in[14];
    const float* l1bhh   = (const float*)d_in[15];
    const float* l2Wih   = (const float*)d_in[16];
    const float* l2Whh   = (const float*)d_in[17];
    const float* l2bih   = (const float*)d_in[18];
    const float* l2bhh   = (const float*)d_in[19];
    const float* ramW    = (const float*)d_in[20];
    const float* ramb    = (const float*)d_in[21];
    const float* rpmW    = (const float*)d_in[22];
    float* out = (float*)d_out;

    float* p_encs;  cudaGetSymbolAddress((void**)&p_encs,  d_encs);
    float* p_att1;  cudaGetSymbolAddress((void**)&p_att1,  d_att1);
    float* p_econ;  cudaGetSymbolAddress((void**)&p_econ,  d_econ);
    float* p_embg;  cudaGetSymbolAddress((void**)&p_embg,  d_embg);
    float* p_W1;    cudaGetSymbolAddress((void**)&p_W1,    d_W1cat);
    float* p_W2;    cudaGetSymbolAddress((void**)&p_W2,    d_W2cat);
    float* p_W3;    cudaGetSymbolAddress((void**)&p_W3,    d_W3cat);
    float* p_b1;    cudaGetSymbolAddress((void**)&p_b1,    d_b1sum);
    float* p_b2;    cudaGetSymbolAddress((void**)&p_b2,    d_b2sum);
    float* p_b3;    cudaGetSymbolAddress((void**)&p_b3,    d_b3cat);
    float* p_base1; cudaGetSymbolAddress((void**)&p_base1, d_base1);
    float* p_gates; cudaGetSymbolAddress((void**)&p_gates, d_gates);
    float* p_x1;    cudaGetSymbolAddress((void**)&p_x1,    d_x1);
    float* p_x2;    cudaGetSymbolAddress((void**)&p_x2,    d_x2);
    float* p_ag;    cudaGetSymbolAddress((void**)&p_ag,    d_ag);
    float* p_mean;  cudaGetSymbolAddress((void**)&p_mean,  d_mean);
    float* p_h2;    cudaGetSymbolAddress((void**)&p_h2,    d_h2all);

    // 1-3: sort, gather encoder, mean
    setup_kernel<<<1, BBS>>>(caplen, caps, out);
    gather_enc_kernel<<<50176, 256>>>(enc_out);
    mean_kernel<<<(BBS * ENCD) / 256, 256>>>();

    // 4: att1 = enc_sorted @ enc_att_W.T + b  (25088 x 1024, K=2048)
    //    (kept in the ncu-profiled launch slot for a clean A/B)
    gemm128<1><<<dim3(1024 / 128, (BBS * PPS) / 128), 256>>>(
        p_encs, eaW, eab, p_att1, 1024, 2048, 2048, 2048, 1024);

    // 5: zero whole predictions region (inactive rows stay 0)
    zero_pred_kernel<<<84000, 256>>>(out + O_PRED);

    // 6-9: bias sums + weight concatenations
    bias_kernel<<<16, 256>>>(l1bih, l1bhh, l2bih, l2bhh, dab, fbb);
    w1copy_kernel<<<8192, 256>>>(l1Wih, l1Whh);
    w2copy_kernel<<<16384, 256>>>(l2Wih, l2Whh);
    w3copy_kernel<<<3072, 256>>>(daW, fbW);

    // 10: token embedding gather
    embg_kernel<<<TTS * BBS, 256>>>(emb);

    // 11: base1 = mean_enc @ Wih[:,2048:].T + (bih+bhh)  (128 x 4096, K=2048)
    gemm32<0><<<dim3(4096 / 128, 4), 128>>>(
        p_mean, l1Wih + 2048, p_b1, nullptr, nullptr, p_base1,
        4096, 2048, 2048, 4096, 4096, -1);

    // 12: econ = embg @ Wih[:,0:1024].T  (2688 x 4096, K=1024)
    gemm128<0><<<dim3(4096 / 128, (TTS * BBS) / 128), 256>>>(
        p_embg, l1Wih, nullptr, p_econ, 4096, 1024, 1024, 4096, 4096);

    // 13: zero states
    zero_states_kernel<<<(BBS * 4096) / 256, 256>>>();

    // 14: sequential decode (blocks/rows past the active prefix exit early)
    for (int t = 0; t < TTS; ++t) {
        gemm32<1><<<dim3(4096 / 128, 4), 128>>>(
            p_x1, p_W1, nullptr, p_base1, p_econ + (size_t)t * BBS * 4096,
            p_gates, 4096, 2048, 2048, 2048, 4096, t);

        lstm1_kernel<<<(BBS * DHID) / 256, 256>>>(t);

        gemm32<0><<<dim3(3072 / 128, 4), 128>>>(
            p_x2 + 2048, p_W3, p_b3, nullptr, nullptr, p_ag,
            3072, 1024, 4096, 1024, 3072, t);

        attn_kernel<<<BBS, 256>>>(faW, fab, t);

        gemm32<0><<<dim3(4096 / 128, 4), 128>>>(
            p_x2, p_W2, p_b2, nullptr, nullptr, p_gates,
            4096, 4096, 4096, 4096, 4096, t);

        lstm2_kernel<<<(BBS * DHID) / 256, 256>>>(t);
    }

    // 15: predictions = h2all[active] @ ram_W.T + ram_b (compact, scattered)
    gemm128<2><<<dim3(VOC / 128, (TTS * BBS + 127) / 128), 256>>>(
        p_h2, ramW, ramb, out + O_PRED, VOC, 1024, 1024, 1024, VOC);

    // 16: predicted_pos
    rpm_kernel<<<(TTS * BBS + 7) / 8, 256>>>(rpmW, out);
}

// round 11
// speedup vs baseline: 1.2501x; 1.2501x over previous
#include <cuda_runtime.h>
#include <math.h>

// ---------------------------------------------------------------------------
// Problem constants
// ---------------------------------------------------------------------------
#define TTS   21      // Tm = CAP-1 decode steps
#define CAPL  22
#define BBS   128     // batch
#define PPS   196     // pixels
#define ENCD  2048
#define DHID  1024
#define VOC   32000

static constexpr long long O_PRED = 0;
static constexpr long long O_CAPS = (long long)BBS * TTS * VOC;   // 86,016,000
static constexpr long long O_DECL = O_CAPS + (long long)BBS * CAPL;
static constexpr long long O_SORT = O_DECL + BBS;
static constexpr long long O_RPOS = O_SORT + BBS;
static constexpr long long O_PPOS = O_RPOS + (long long)BBS * TTS;

// ---------------------------------------------------------------------------
// Static device scratch (no runtime allocation allowed)
// ---------------------------------------------------------------------------
__device__ float d_encs [(size_t)BBS * PPS * ENCD];   // sorted encoder
__device__ float d_att1 [(size_t)BBS * PPS * DHID];   // att1
__device__ float d_econ [(size_t)TTS * BBS * 4 * DHID]; // embed @ Wih_e^T
__device__ float d_embg [(size_t)TTS * BBS * DHID];   // gathered embeddings
__device__ float d_W1cat[4096 * 2048];                // [Wih(:,1024:2048) | Whh]
__device__ float d_W2cat[(size_t)4096 * 4096];        // [l2_Wih | l2_Whh]
__device__ float d_W3cat[3072 * 1024];                // [dec_att_W ; f_beta_W]
__device__ float d_b1sum[4096];
__device__ float d_b2sum[4096];
__device__ float d_b3cat[3072];
__device__ float d_base1[BBS * 4096];                 // biases + mean_enc contrib
__device__ float d_gp   [4 * BBS * 4096];             // split-K partials (reused)
__device__ float d_ap   [2 * BBS * 3072];             // att2/gate split-K partials
__device__ float d_x1   [BBS * 2048];                 // [h2_state | h1_state]
__device__ float d_x2   [BBS * 4096];                 // [att | h1n | h2_state]
__device__ float d_c1   [BBS * DHID];
__device__ float d_c2   [BBS * DHID];
__device__ float d_mean [BBS * ENCD];
__device__ float d_h2all[(size_t)TTS * BBS * DHID];   // h2n (active rows only)
__device__ int   d_sort  [BBS];
__device__ int   d_declen[BBS];
__device__ int   d_tokens[TTS * BBS];
__device__ int   d_nact  [TTS];                       // active prefix size per t
__device__ int   d_rowidx[TTS * BBS];                 // compact -> t*BBS+b
__device__ int   d_outrow[TTS * BBS];                 // compact -> b*TTS+t
__device__ int   d_cnt;                               // number of active pairs

// ---------------------------------------------------------------------------
// Math helpers
// ---------------------------------------------------------------------------
__device__ __forceinline__ float sigf(float x) {
    return 1.0f / (1.0f + __expf(-x));
}
__device__ __forceinline__ float tanh_fast(float x) {
    return 1.0f - 2.0f / (__expf(2.0f * x) + 1.0f);
}

// ---------------------------------------------------------------------------
// Setup: stable descending argsort; caps/dec_len/sort/rel_pos out; active
// prefix sizes and compact active-row lists.
// ---------------------------------------------------------------------------
__global__ void setup_kernel(const int* __restrict__ caplen,
                             const int* __restrict__ caps,
                             float* __restrict__ out) {
    __shared__ int lens_s[BBS];
    __shared__ int sort_s[BBS];
    __shared__ int dl_s[BBS];
    int i = threadIdx.x;
    int li = caplen[i];
    lens_s[i] = li;
    __syncthreads();
    int rank = 0;
    for (int j = 0; j < BBS; ++j) {
        int lj = lens_s[j];
        if (lj > li || (lj == li && j < i)) rank++;
    }
    sort_s[rank] = i;
    __syncthreads();
    int src = sort_s[i];
    d_sort[i] = src;
    int dl = lens_s[src] - 1;
    d_declen[i] = dl;
    dl_s[i] = dl;
    out[O_DECL + i] = (float)dl;
    out[O_SORT + i] = (float)src;
    for (int t = 0; t < CAPL; ++t) {
        int tok = caps[src * CAPL + t];
        out[O_CAPS + (long long)i * CAPL + t] = (float)tok;
        if (t < TTS) d_tokens[t * BBS + i] = tok;
    }
    float dlf = (float)dl;
    for (int s = 0; s < TTS; ++s)
        out[O_RPOS + (long long)i * TTS + s] =
            (s < dl) ? ((float)(s + 1) / dlf) : 0.0f;
    __syncthreads();
    if (i == 0) {
        int c = 0;
        for (int t = 0; t < TTS; ++t) {
            int n = 0;
            while (n < BBS && dl_s[n] > t) n++;   // dl_s sorted descending
            d_nact[t] = n;
            for (int b = 0; b < n; ++b) {
                d_rowidx[c] = t * BBS + b;
                d_outrow[c] = b * TTS + t;
                c++;
            }
        }
        d_cnt = c;
    }
}

// ---------------------------------------------------------------------------
// Gather sorted encoder rows (float4)
// ---------------------------------------------------------------------------
__global__ void gather_enc_kernel(const float* __restrict__ enc) {
    int g = blockIdx.x * 256 + threadIdx.x;
    const int V4ROW = ENCD / 4;                      // 512
    int r = g / V4ROW;
    int w = g % V4ROW;
    int b = r / PPS, p = r % PPS;
    int srow = d_sort[b] * PPS + p;
    const float4* src = (const float4*)enc;
    float4* dst = (float4*)d_encs;
    dst[(size_t)r * V4ROW + w] = src[(size_t)srow * V4ROW + w];
}

// ---------------------------------------------------------------------------
// mean over pixels: one thread per (b,e)
// ---------------------------------------------------------------------------
__global__ void mean_kernel() {
    int idx = blockIdx.x * 256 + threadIdx.x;
    int b = idx / ENCD, e = idx % ENCD;
    const float* base = d_encs + (size_t)b * PPS * ENCD + e;
    float s = 0.f;
    #pragma unroll 4
    for (int p = 0; p < PPS; ++p) s += base[(size_t)p * ENCD];
    d_mean[idx] = s * (1.0f / (float)PPS);
}

// ---------------------------------------------------------------------------
// Weight concatenation copies (float4) + bias sums
// ---------------------------------------------------------------------------
__global__ void w1copy_kernel(const float* __restrict__ l1Wih,
                              const float* __restrict__ l1Whh) {
    int g = blockIdx.x * 256 + threadIdx.x;
    int j = g / (2048 / 4);
    int c = (g % (2048 / 4)) * 4;
    float4 v;
    if (c < 1024) v = *(const float4*)(l1Wih + (size_t)j * 4096 + 1024 + c);
    else          v = *(const float4*)(l1Whh + (size_t)j * 1024 + (c - 1024));
    *(float4*)(d_W1cat + (size_t)j * 2048 + c) = v;
}

__global__ void w2copy_kernel(const float* __restrict__ l2Wih,
                              const float* __restrict__ l2Whh) {
    int g = blockIdx.x * 256 + threadIdx.x;
    int j = g / (4096 / 4);
    int c = (g % (4096 / 4)) * 4;
    float4 v;
    if (c < 3072) v = *(const float4*)(l2Wih + (size_t)j * 3072 + c);
    else          v = *(const float4*)(l2Whh + (size_t)j * 1024 + (c - 3072));
    *(float4*)(d_W2cat + (size_t)j * 4096 + c) = v;
}

__global__ void w3copy_kernel(const float* __restrict__ daW,
                              const float* __restrict__ fbW) {
    int g = blockIdx.x * 256 + threadIdx.x;
    int j = g / (1024 / 4);
    int c = (g % (1024 / 4)) * 4;
    float4 v;
    if (j < 1024) v = *(const float4*)(daW + (size_t)j * 1024 + c);
    else          v = *(const float4*)(fbW + (size_t)(j - 1024) * 1024 + c);
    *(float4*)(d_W3cat + (size_t)j * 1024 + c) = v;
}

__global__ void bias_kernel(const float* __restrict__ l1bih,
                            const float* __restrict__ l1bhh,
                            const float* __restrict__ l2bih,
                            const float* __restrict__ l2bhh,
                            const float* __restrict__ dab,
                            const float* __restrict__ fbb) {
    int j = blockIdx.x * 256 + threadIdx.x;
    d_b1sum[j] = l1bih[j] + l1bhh[j];
    d_b2sum[j] = l2bih[j] + l2bhh[j];
    if (j < 3072) d_b3cat[j] = (j < 1024) ? dab[j] : fbb[j - 1024];
}

// ---------------------------------------------------------------------------
// Gather token embeddings: one block per (t,b) row
// ---------------------------------------------------------------------------
__global__ void embg_kernel(const float* __restrict__ emb) {
    int m = blockIdx.x;
    int tok = d_tokens[m];
    const float4* src = (const float4*)(emb + (size_t)tok * DHID);
    float4* dst = (float4*)(d_embg + (size_t)m * DHID);
    dst[threadIdx.x] = src[threadIdx.x];
}

// ---------------------------------------------------------------------------
// Zero initial states / zero the whole predictions region
// ---------------------------------------------------------------------------
__global__ void zero_states_kernel() {
    int idx = blockIdx.x * 256 + threadIdx.x;        // 0 .. 524287
    d_x2[idx] = 0.f;
    if (idx < BBS * 2048) d_x1[idx] = 0.f;
    if (idx < BBS * DHID) { d_c1[idx] = 0.f; d_c2[idx] = 0.f; }
}

__global__ void zero_pred_kernel(float* __restrict__ out) {
    size_t g = (size_t)blockIdx.x * 256 + threadIdx.x;  // float4 index
    ((float4*)out)[g] = make_float4(0.f, 0.f, 0.f, 0.f);
}

// ---------------------------------------------------------------------------
// Big GEMM (R8-best): 128x128 tile, BK=16, 256 threads, 8x8 microtile with
// conflict-free 4+4 split fragments + register prefetch. fp32.
// MODE 0: plain   MODE 1: +bias[n]
// MODE 2: +bias, A-rows gathered via d_rowidx, stores scattered via d_outrow.
// ---------------------------------------------------------------------------
template<int MODE>
__global__ void __launch_bounds__(256, 2)
gemm128(const float* __restrict__ A,
        const float* __restrict__ Bm,
        const float* __restrict__ bias,
        float* __restrict__ C,
        int N, int K, int lda, int ldb, int ldc) {
    __shared__ float As[16][132];
    __shared__ float Bs[16][132];
    const int tid = threadIdx.x;
    const int m0 = blockIdx.y * 128;
    const int n0 = blockIdx.x * 128;
    int count = 0;
    if (MODE == 2) {
        count = d_cnt;
        if (m0 >= count) return;
    }
    const int lr = tid >> 1;            // load row 0..127
    const int lc = (tid & 1) * 8;       // col base 0 or 8
    int arow = m0 + lr;
    if (MODE == 2) arow = (m0 + lr < count) ? d_rowidx[m0 + lr] : d_rowidx[0];
    const float* Aptr = A + (size_t)arow * lda + lc;
    const float* Bptr = Bm + (size_t)(n0 + lr) * ldb + lc;

    const int ty = tid >> 4;            // 0..15 (m)
    const int tx = tid & 15;            // 0..15 (n)

    float acc[8][8];
    #pragma unroll
    for (int i = 0; i < 8; ++i)
        #pragma unroll
        for (int j = 0; j < 8; ++j) acc[i][j] = 0.f;

    float4 pa0 = *(const float4*)(Aptr);
    float4 pa1 = *(const float4*)(Aptr + 4);
    float4 pb0 = *(const float4*)(Bptr);
    float4 pb1 = *(const float4*)(Bptr + 4);

    for (int k0 = 0; k0 < K; k0 += 16) {
        As[lc + 0][lr] = pa0.x; As[lc + 1][lr] = pa0.y;
        As[lc + 2][lr] = pa0.z; As[lc + 3][lr] = pa0.w;
        As[lc + 4][lr] = pa1.x; As[lc + 5][lr] = pa1.y;
        As[lc + 6][lr] = pa1.z; As[lc + 7][lr] = pa1.w;
        Bs[lc + 0][lr] = pb0.x; Bs[lc + 1][lr] = pb0.y;
        Bs[lc + 2][lr] = pb0.z; Bs[lc + 3][lr] = pb0.w;
        Bs[lc + 4][lr] = pb1.x; Bs[lc + 5][lr] = pb1.y;
        Bs[lc + 6][lr] = pb1.z; Bs[lc + 7][lr] = pb1.w;
        __syncthreads();
        if (k0 + 16 < K) {
            pa0 = *(const float4*)(Aptr + k0 + 16);
            pa1 = *(const float4*)(Aptr + k0 + 20);
            pb0 = *(const float4*)(Bptr + k0 + 16);
            pb1 = *(const float4*)(Bptr + k0 + 20);
        }
        #pragma unroll
        for (int kk = 0; kk < 16; ++kk) {
            float a[8], b[8];
            *(float4*)(a)     = *(const float4*)&As[kk][ty * 4];
            *(float4*)(a + 4) = *(const float4*)&As[kk][64 + ty * 4];
            *(float4*)(b)     = *(const float4*)&Bs[kk][tx * 4];
            *(float4*)(b + 4) = *(const float4*)&Bs[kk][64 + tx * 4];
            #pragma unroll
            for (int i = 0; i < 8; ++i)
                #pragma unroll
                for (int j = 0; j < 8; ++j)
                    acc[i][j] = fmaf(a[i], b[j], acc[i][j]);
        }
        __syncthreads();
    }

    float bv[8];
    #pragma unroll
    for (int j = 0; j < 8; ++j) {
        int n = (j < 4) ? (n0 + tx * 4 + j) : (n0 + 64 + tx * 4 + j - 4);
        bv[j] = (MODE >= 1) ? bias[n] : 0.f;
    }

    #pragma unroll
    for (int i = 0; i < 8; ++i) {
        int mi = (i < 4) ? (ty * 4 + i) : (64 + ty * 4 + i - 4);
        int m = m0 + mi;
        long long crow = m;
        if (MODE == 2) {
            if (m >= count) continue;
            crow = d_outrow[m];
        }
        float* dst = C + crow * (long long)ldc + n0;
        float4 v0, v1;
        v0.x = acc[i][0] + bv[0]; v0.y = acc[i][1] + bv[1];
        v0.z = acc[i][2] + bv[2]; v0.w = acc[i][3] + bv[3];
        v1.x = acc[i][4] + bv[4]; v1.y = acc[i][5] + bv[5];
        v1.z = acc[i][6] + bv[6]; v1.w = acc[i][7] + bv[7];
        *(float4*)(dst + tx * 4)      = v0;
        *(float4*)(dst + 64 + tx * 4) = v1;
    }
}

// ---------------------------------------------------------------------------
// Skinny split-K GEMM: 32x128 tile, BK=16, 128 threads, 4x8 micro,
// conflict-free split fragments, register prefetch. Each z-block computes a
// K-chunk partial into its own slab of C (slab stride BBS*N). No epilogue.
// BIAS=true adds bias (used only for base1, single z-block).
// t >= 0: early-exit blocks whose rows are entirely inactive.
// ---------------------------------------------------------------------------
template<bool BIAS>
__global__ void __launch_bounds__(128)
gemm32sk(const float* __restrict__ A,
         const float* __restrict__ Bm,
         const float* __restrict__ bias,
         float* __restrict__ C,
         int N, int Kc, int lda, int ldb, int t) {
    const int m0 = blockIdx.y * 32;
    if (t >= 0 && m0 >= d_nact[t]) return;
    __shared__ float As[16][36];
    __shared__ float Bs[16][132];
    const int tid = threadIdx.x;
    const int n0 = blockIdx.x * 128;
    const int ko = blockIdx.z * Kc;

    const int ar = tid >> 2;            // A load row 0..31
    const int ac = (tid & 3) * 4;       // A col 0,4,8,12
    const float* Aptr = A + (size_t)(m0 + ar) * lda + ko + ac;
    const float* Bptr = Bm + (size_t)(n0 + tid) * ldb + ko;
    float* Cs = C + (size_t)blockIdx.z * BBS * N;

    const int ty = tid >> 4;            // 0..7  (m)
    const int tx = tid & 15;            // 0..15 (n)

    float acc[4][8];
    #pragma unroll
    for (int i = 0; i < 4; ++i)
        #pragma unroll
        for (int j = 0; j < 8; ++j) acc[i][j] = 0.f;

    float4 pav = *(const float4*)(Aptr);
    float4 pb[4];
    #pragma unroll
    for (int j = 0; j < 4; ++j) pb[j] = *(const float4*)(Bptr + j * 4);

    for (int k0 = 0; k0 < Kc; k0 += 16) {
        As[ac + 0][ar] = pav.x; As[ac + 1][ar] = pav.y;
        As[ac + 2][ar] = pav.z; As[ac + 3][ar] = pav.w;
        #pragma unroll
        for (int j = 0; j < 4; ++j) {
            Bs[j * 4 + 0][tid] = pb[j].x; Bs[j * 4 + 1][tid] = pb[j].y;
            Bs[j * 4 + 2][tid] = pb[j].z; Bs[j * 4 + 3][tid] = pb[j].w;
        }
        __syncthreads();
        if (k0 + 16 < Kc) {
            pav = *(const float4*)(Aptr + k0 + 16);
            #pragma unroll
            for (int j = 0; j < 4; ++j)
                pb[j] = *(const float4*)(Bptr + k0 + 16 + j * 4);
        }
        #pragma unroll
        for (int kk = 0; kk < 16; ++kk) {
            float a[4], b[8];
            *(float4*)(a)     = *(const float4*)&As[kk][ty * 4];
            *(float4*)(b)     = *(const float4*)&Bs[kk][tx * 4];
            *(float4*)(b + 4) = *(const float4*)&Bs[kk][64 + tx * 4];
            #pragma unroll
            for (int i = 0; i < 4; ++i)
                #pragma unroll
                for (int j = 0; j < 8; ++j)
                    acc[i][j] = fmaf(a[i], b[j], acc[i][j]);
        }
        __syncthreads();
    }

    float bv[8];
    #pragma unroll
    for (int j = 0; j < 8; ++j) {
        int n = (j < 4) ? (n0 + tx * 4 + j) : (n0 + 64 + tx * 4 + j - 4);
        bv[j] = BIAS ? bias[n] : 0.f;
    }

    #pragma unroll
    for (int i = 0; i < 4; ++i) {
        int m = m0 + ty * 4 + i;
        float* dst = Cs + (size_t)m * N + n0;
        float4 v0, v1;
        v0.x = acc[i][0] + bv[0]; v0.y = acc[i][1] + bv[1];
        v0.z = acc[i][2] + bv[2]; v0.w = acc[i][3] + bv[3];
        v1.x = acc[i][4] + bv[4]; v1.y = acc[i][5] + bv[5];
        v1.z = acc[i][6] + bv[6]; v1.w = acc[i][7] + bv[7];
        *(float4*)(dst + tx * 4)      = v0;
        *(float4*)(dst + 64 + tx * 4) = v1;
    }
}

// ---------------------------------------------------------------------------
// LSTM pointwise kernels. Sum split-K partials + per-step adds inline.
// lstm1: g = base1 + econ[t] + sum_{s<4} gp[s]
// lstm2: g = b2sum + sum_{s<4} gp[s]
// ---------------------------------------------------------------------------
__global__ void lstm1_kernel(int t, const float* __restrict__ econ_t) {
    int idx = blockIdx.x * 256 + threadIdx.x;
    int b = idx / DHID, k = idx % DHID;
    if (t >= d_declen[b]) return;
    size_t base = (size_t)b * 4096;
    float g4[4];
    #pragma unroll
    for (int q = 0; q < 4; ++q) {
        int j = q * 1024 + k;
        float v = d_base1[base + j] + econ_t[base + j];
        v += d_gp[0 * BBS * 4096 + base + j];
        v += d_gp[1 * BBS * 4096 + base + j];
        v += d_gp[2 * BBS * 4096 + base + j];
        v += d_gp[3 * BBS * 4096 + base + j];
        g4[q] = v;
    }
    float c = d_c1[idx];
    float cn = sigf(g4[1]) * c + sigf(g4[0]) * tanhf(g4[2]);
    float hn = sigf(g4[3]) * tanhf(cn);
    d_c1[idx] = cn;
    d_x1[(size_t)b * 2048 + 1024 + k] = hn;          // carried h1 state
    d_x2[(size_t)b * 4096 + 2048 + k] = hn;          // h1n for att2/gates2
}

__global__ void lstm2_kernel(int t) {
    int idx = blockIdx.x * 256 + threadIdx.x;
    int b = idx / DHID, k = idx % DHID;
    if (t >= d_declen[b]) return;
    size_t base = (size_t)b * 4096;
    float g4[4];
    #pragma unroll
    for (int q = 0; q < 4; ++q) {
        int j = q * 1024 + k;
        float v = d_b2sum[j];
        v += d_gp[0 * BBS * 4096 + base + j];
        v += d_gp[1 * BBS * 4096 + base + j];
        v += d_gp[2 * BBS * 4096 + base + j];
        v += d_gp[3 * BBS * 4096 + base + j];
        g4[q] = v;
    }
    float c = d_c2[idx];
    float cn = sigf(g4[1]) * c + sigf(g4[0]) * tanhf(g4[2]);
    float hn = sigf(g4[3]) * tanhf(cn);
    d_c2[idx] = cn;
    d_h2all[(size_t)(t * BBS + b) * DHID + k] = hn;
    d_x1[(size_t)b * 2048 + k] = hn;                 // carried h2 state
    d_x2[(size_t)b * 4096 + 3072 + k] = hn;
}

// ---------------------------------------------------------------------------
// Fused attention. att2/gate logits = b3 + sum of 2 split-K partials (d_ap).
// scores = tanh(att1 + att2).w + b0; softmax; awe = alpha@enc;
// x2.att = sigmoid(gate)*awe.  One block per b.
// ---------------------------------------------------------------------------
__global__ void attn_kernel(const float* __restrict__ fullW,
                            const float* __restrict__ fullb, int t) {
    const int b = blockIdx.x;
    if (t >= d_declen[b]) return;
    __shared__ float s_a2[DHID];
    __shared__ float s_w [DHID];
    __shared__ float s_sc[PPS];
    __shared__ float s_red[256];
    const int tid = threadIdx.x;
    const int lane = tid & 31, warp = tid >> 5;
    const size_t abase = (size_t)b * 3072;

    for (int i = tid; i < DHID; i += 256) {
        s_a2[i] = d_b3cat[i] + d_ap[abase + i]
                + d_ap[(size_t)BBS * 3072 + abase + i];
        s_w[i]  = fullW[i];
    }
    __syncthreads();

    const float b0 = fullb[0];
    for (int p = warp; p < PPS; p += 8) {
        const float* row = d_att1 + ((size_t)b * PPS + p) * DHID;
        float s = 0.f;
        #pragma unroll 8
        for (int a = lane; a < DHID; a += 32)
            s += tanh_fast(row[a] + s_a2[a]) * s_w[a];
        #pragma unroll
        for (int o = 16; o > 0; o >>= 1)
            s += __shfl_down_sync(0xffffffffu, s, o);
        if (lane == 0) s_sc[p] = s + b0;
    }
    __syncthreads();

    s_red[tid] = (tid < PPS) ? s_sc[tid] : -INFINITY;
    __syncthreads();
    for (int s = 128; s > 0; s >>= 1) {
        if (tid < s) s_red[tid] = fmaxf(s_red[tid], s_red[tid + s]);
        __syncthreads();
    }
    float mx = s_red[0];
    __syncthreads();
    float e = 0.f;
    if (tid < PPS) e = __expf(s_sc[tid] - mx);
    s_red[tid] = e;
    __syncthreads();
    for (int s = 128; s > 0; s >>= 1) {
        if (tid < s) s_red[tid] += s_red[tid + s];
        __syncthreads();
    }
    float inv = 1.0f / s_red[0];
    __syncthreads();
    if (tid < PPS) s_sc[tid] = e * inv;
    __syncthreads();

    const float* encb = d_encs + (size_t)b * PPS * ENCD;
    for (int ei = tid; ei < ENCD; ei += 256) {
        float acc = 0.f;
        const float* col = encb + ei;
        #pragma unroll 4
        for (int p = 0; p < PPS; ++p)
            acc = fmaf(s_sc[p], col[(size_t)p * ENCD], acc);
        float gl = d_b3cat[1024 + ei] + d_ap[abase + 1024 + ei]
                 + d_ap[(size_t)BBS * 3072 + abase + 1024 + ei];
        d_x2[(size_t)b * 4096 + ei] = sigf(gl) * acc;
    }
}

// ---------------------------------------------------------------------------
// predicted_pos: one warp per (t,b) row
// ---------------------------------------------------------------------------
__global__ void rpm_kernel(const float* __restrict__ rpmW,
                           float* __restrict__ out) {
    int m = blockIdx.x * 8 + (threadIdx.x >> 5);
    if (m >= TTS * BBS) return;
    int lane = threadIdx.x & 31;
    int t = m / BBS, b = m % BBS;
    const float* h = d_h2all + (size_t)m * DHID;
    float s = 0.f;
    #pragma unroll 8
    for (int k = lane; k < DHID; k += 32) s += h[k] * rpmW[k];
    #pragma unroll
    for (int o = 16; o > 0; o >>= 1)
        s += __shfl_down_sync(0xffffffffu, s, o);
    if (lane == 0)
        out[O_PPOS + (long long)b * TTS + t] =
            (t < d_declen[b]) ? sigf(s) : 0.f;
}

// ---------------------------------------------------------------------------
// Launch
// ---------------------------------------------------------------------------
extern "C" void kernel_launch(void* const* d_in, const int* in_sizes, int n_in,
                              void* d_out, int out_size) {
    const float* enc_out = (const float*)d_in[0];
    const int*   caps    = (const int*)  d_in[1];
    const int*   caplen  = (const int*)  d_in[2];
    const float* emb     = (const float*)d_in[3];
    const float* eaW     = (const float*)d_in[4];
    const float* eab     = (const float*)d_in[5];
    const float* daW     = (const float*)d_in[6];
    const float* dab     = (const float*)d_in[7];
    const float* faW     = (const float*)d_in[8];
    const float* fab     = (const float*)d_in[9];
    const float* fbW     = (const float*)d_in[10];
    const float* fbb     = (const float*)d_in[11];
    const float* l1Wih   = (const float*)d_in[12];
    const float* l1Whh   = (const float*)d_in[13];
    const float* l1bih   = (const float*)d_in[14];
    const float* l1bhh   = (const float*)d_in[15];
    const float* l2Wih   = (const float*)d_in[16];
    const float* l2Whh   = (const float*)d_in[17];
    const float* l2bih   = (const float*)d_in[18];
    const float* l2bhh   = (const float*)d_in[19];
    const float* ramW    = (const float*)d_in[20];
    const float* ramb    = (const float*)d_in[21];
    const float* rpmW    = (const float*)d_in[22];
    float* out = (float*)d_out;

    float* p_encs;  cudaGetSymbolAddress((void**)&p_encs,  d_encs);
    float* p_att1;  cudaGetSymbolAddress((void**)&p_att1,  d_att1);
    float* p_econ;  cudaGetSymbolAddress((void**)&p_econ,  d_econ);
    float* p_embg;  cudaGetSymbolAddress((void**)&p_embg,  d_embg);
    float* p_W1;    cudaGetSymbolAddress((void**)&p_W1,    d_W1cat);
    float* p_W2;    cudaGetSymbolAddress((void**)&p_W2,    d_W2cat);
    float* p_W3;    cudaGetSymbolAddress((void**)&p_W3,    d_W3cat);
    float* p_b1;    cudaGetSymbolAddress((void**)&p_b1,    d_b1sum);
    float* p_base1; cudaGetSymbolAddress((void**)&p_base1, d_base1);
    float* p_gp;    cudaGetSymbolAddress((void**)&p_gp,    d_gp);
    float* p_ap;    cudaGetSymbolAddress((void**)&p_ap,    d_ap);
    float* p_x1;    cudaGetSymbolAddress((void**)&p_x1,    d_x1);
    float* p_x2;    cudaGetSymbolAddress((void**)&p_x2,    d_x2);
    float* p_mean;  cudaGetSymbolAddress((void**)&p_mean,  d_mean);
    float* p_h2;    cudaGetSymbolAddress((void**)&p_h2,    d_h2all);

    // 1-3: sort, gather encoder, mean
    setup_kernel<<<1, BBS>>>(caplen, caps, out);
    gather_enc_kernel<<<50176, 256>>>(enc_out);
    mean_kernel<<<(BBS * ENCD) / 256, 256>>>();

    // 4: att1 = enc_sorted @ enc_att_W.T + b  (25088 x 1024, K=2048)
    //    (kept in the ncu-profiled launch slot for a clean A/B)
    gemm128<1><<<dim3(1024 / 128, (BBS * PPS) / 128), 256>>>(
        p_encs, eaW, eab, p_att1, 1024, 2048, 2048, 2048, 1024);

    // 5: zero whole predictions region (inactive rows stay 0)
    zero_pred_kernel<<<84000, 256>>>(out + O_PRED);

    // 6-9: bias sums + weight concatenations
    bias_kernel<<<16, 256>>>(l1bih, l1bhh, l2bih, l2bhh, dab, fbb);
    w1copy_kernel<<<8192, 256>>>(l1Wih, l1Whh);
    w2copy_kernel<<<16384, 256>>>(l2Wih, l2Whh);
    w3copy_kernel<<<3072, 256>>>(daW, fbW);

    // 10: token embedding gather
    embg_kernel<<<TTS * BBS, 256>>>(emb);

    // 11: base1 = mean_enc @ Wih[:,2048:].T + (bih+bhh)  (128 x 4096, K=2048)
    gemm32sk<true><<<dim3(4096 / 128, 4, 1), 128>>>(
        p_mean, l1Wih + 2048, p_b1, p_base1, 4096, 2048, 2048, 4096, -1);

    // 12: econ = embg @ Wih[:,0:1024].T  (2688 x 4096, K=1024)
    gemm128<0><<<dim3(4096 / 128, (TTS * BBS) / 128), 256>>>(
        p_embg, l1Wih, nullptr, p_econ, 4096, 1024, 1024, 4096, 4096);

    // 13: zero states
    zero_states_kernel<<<(BBS * 4096) / 256, 256>>>();

    // 14: sequential decode. Split-K partials give ~512 blocks/launch so the
    //     skinny GEMMs finally occupy the chip (was 128 blocks = 1 warp/SMSP).
    for (int t = 0; t < TTS; ++t) {
        // gates1 partials: [h2|h1](K=2048, split 4x512) @ W1cat.T
        gemm32sk<false><<<dim3(4096 / 128, 4, 4), 128>>>(
            p_x1, p_W1, nullptr, p_gp, 4096, 512, 2048, 2048, t);

        lstm1_kernel<<<(BBS * DHID) / 256, 256>>>(
            t, p_econ + (size_t)t * BBS * 4096);

        // att2/gate partials: h1n(K=1024, split 2x512) @ [dec_att;f_beta].T
        gemm32sk<false><<<dim3(3072 / 128, 4, 2), 128>>>(
            p_x2 + 2048, p_W3, nullptr, p_ap, 3072, 512, 4096, 1024, t);

        attn_kernel<<<BBS, 256>>>(faW, fab, t);

        // gates2 partials: [att|h1n|h2](K=4096, split 4x1024) @ W2cat.T
        gemm32sk<false><<<dim3(4096 / 128, 4, 4), 128>>>(
            p_x2, p_W2, nullptr, p_gp, 4096, 1024, 4096, 4096, t);

        lstm2_kernel<<<(BBS * DHID) / 256, 256>>>(t);
    }

    // 15: predictions = h2all[active] @ ram_W.T + ram_b (compact, scattered)
    gemm128<2><<<dim3(VOC / 128, (TTS * BBS + 127) / 128), 256>>>(
        p_h2, ramW, ramb, out + O_PRED, VOC, 1024, 1024, 1024, VOC);

    // 16: predicted_pos
    rpm_kernel<<<(TTS * BBS + 7) / 8, 256>>>(rpmW, out);
}

// round 13
// speedup vs baseline: 1.3305x; 1.0643x over previous
#include <cuda_runtime.h>
#include <cuda_bf16.h>
#include <mma.h>
#include <math.h>
using namespace nvcuda;

// ---------------------------------------------------------------------------
// Problem constants
// ---------------------------------------------------------------------------
#define TTS   21
#define CAPL  22
#define BBS   128
#define PPS   196
#define ENCD  2048
#define DHID  1024
#define VOC   32000

static constexpr long long O_PRED = 0;
static constexpr long long O_CAPS = (long long)BBS * TTS * VOC;
static constexpr long long O_DECL = O_CAPS + (long long)BBS * CAPL;
static constexpr long long O_SORT = O_DECL + BBS;
static constexpr long long O_RPOS = O_SORT + BBS;
static constexpr long long O_PPOS = O_RPOS + (long long)BBS * TTS;

// ---------------------------------------------------------------------------
// Static device scratch
// ---------------------------------------------------------------------------
__device__ float d_encs [(size_t)BBS * PPS * ENCD];
__device__ float d_att1 [(size_t)BBS * PPS * DHID];
__device__ float d_econ [(size_t)TTS * BBS * 4 * DHID];
__device__ float d_W1cat[4096 * 2048];
__device__ float d_W2cat[(size_t)4096 * 4096];
__device__ float d_W3cat[3072 * 1024];
__device__ float d_b1sum[4096];
__device__ float d_b2sum[4096];
__device__ float d_b3cat[3072];
__device__ float d_base1[BBS * 4096];
__device__ float d_gp   [4 * BBS * 4096];
__device__ float d_ap   [2 * BBS * 3072];
__device__ float d_x1   [BBS * 2048];
__device__ float d_x2   [BBS * 4096];
__device__ float d_c1   [BBS * DHID];
__device__ float d_c2   [BBS * DHID];
__device__ float d_mean [BBS * ENCD];
__device__ float d_h2all[(size_t)TTS * BBS * DHID];
__device__ int   d_sort  [BBS];
__device__ int   d_declen[BBS];
__device__ int   d_tokens[TTS * BBS];
__device__ int   d_nact  [TTS];
__device__ int   d_rowidx[TTS * BBS];
__device__ int   d_outrow[TTS * BBS];
__device__ int   d_cnt;

// bf16 hi/lo operand buffers (packed bf16x2 in uint32, row-major)
__device__ unsigned int d_ench [(size_t)BBS * PPS * (ENCD / 2)];
__device__ unsigned int d_encl [(size_t)BBS * PPS * (ENCD / 2)];
__device__ unsigned int d_eaWh [1024 * (ENCD / 2)];
__device__ unsigned int d_eaWl [1024 * (ENCD / 2)];
__device__ unsigned int d_W1eh [4096 * (DHID / 2)];
__device__ unsigned int d_W1el [4096 * (DHID / 2)];
__device__ unsigned int d_embgh[TTS * BBS * (DHID / 2)];
__device__ unsigned int d_embgl[TTS * BBS * (DHID / 2)];
__device__ unsigned int d_ramWh[(size_t)VOC * (DHID / 2)];
__device__ unsigned int d_ramWl[(size_t)VOC * (DHID / 2)];
__device__ unsigned int d_h2h  [TTS * BBS * (DHID / 2)];
__device__ unsigned int d_h2l  [TTS * BBS * (DHID / 2)];

// ---------------------------------------------------------------------------
// Helpers
// ---------------------------------------------------------------------------
__device__ __forceinline__ float sigf(float x) {
    return 1.0f / (1.0f + __expf(-x));
}
__device__ __forceinline__ float tanh_fast(float x) {
    return 1.0f - 2.0f / (__expf(2.0f * x) + 1.0f);
}
__device__ __forceinline__ unsigned int pack_hi(float a, float b) {
    __nv_bfloat162 p = __floats2bfloat162_rn(a, b);
    return *reinterpret_cast<unsigned int*>(&p);
}
__device__ __forceinline__ unsigned int pack_lo(float a, float b) {
    float ah = __bfloat162float(__float2bfloat16_rn(a));
    float bh = __bfloat162float(__float2bfloat16_rn(b));
    __nv_bfloat162 p = __floats2bfloat162_rn(a - ah, b - bh);
    return *reinterpret_cast<unsigned int*>(&p);
}
__device__ __forceinline__ unsigned int smem_u32(const void* p) {
    unsigned int a;
    asm("{ .reg .u64 t; cvta.to.shared.u64 t, %1; cvt.u32.u64 %0, t; }"
        : "=r"(a) : "l"(p));
    return a;
}
__device__ __forceinline__ void cp16(unsigned int dst, const void* src) {
    asm volatile("cp.async.cg.shared.global [%0], [%1], 16;"
                 :: "r"(dst), "l"(__cvta_generic_to_global(src)) : "memory");
}

// ---------------------------------------------------------------------------
// bf16x3 wmma GEMM (base-ISA HMMA): C[m,n] = sum_k A[m,k]*B[n,k], fp32 out.
// A,B given as hi/lo bf16 (packed bf16x2 uint32), row-major, ld in uint32.
// Tile 128x128, K-chunk 32, 256 threads (8 warps, warp tile 32x64).
// cp.async double-buffered smem. Skips the Al*Bl term (~2^-18 relative).
// MODE 0: plain  MODE 1: +bias  MODE 2: +bias, gather A rows via d_rowidx,
//         scatter C rows via d_outrow, skip rows >= d_cnt.
// smem: 2 bufs x 4 operands x (128 rows x 40 bf16) = 81920 B (dynamic).
// ---------------------------------------------------------------------------
static constexpr int WB_SMEM = 81920;

template<int MODE>
__global__ void __launch_bounds__(256)
gemm_wb(const unsigned int* __restrict__ Ah, const unsigned int* __restrict__ Al,
        const unsigned int* __restrict__ Bh, const unsigned int* __restrict__ Bl,
        const float* __restrict__ bias, float* __restrict__ C,
        int K, int lda32, int ldb32, int ldc) {
    extern __shared__ char smem[];
    const int tid = threadIdx.x;
    const int warp = tid >> 5;
    const int m0 = blockIdx.y * 128, n0 = blockIdx.x * 128;
    int count = 0;
    if (MODE == 2) {
        count = d_cnt;
        if (m0 >= count) return;
    }

    // loaders: 2 threads per row, each 2x16B per operand per chunk
    const int lr = tid >> 1;                 // row 0..127
    const int lc = (tid & 1) * 8;            // uint offset 0 or 8 (of 16/row)
    int arow = m0 + lr;
    if (MODE == 2) arow = (arow < count) ? d_rowidx[arow] : d_rowidx[0];
    const unsigned int* gA0 = Ah + (size_t)arow * lda32 + lc;
    const unsigned int* gA1 = Al + (size_t)arow * lda32 + lc;
    const unsigned int* gB0 = Bh + (size_t)(n0 + lr) * ldb32 + lc;
    const unsigned int* gB1 = Bl + (size_t)(n0 + lr) * ldb32 + lc;

    const unsigned int sbase = smem_u32(smem);
    const unsigned int drow = (unsigned)(lr * 80 + lc * 4);  // bytes in operand

    const int wm = (warp >> 1) * 32;
    const int wn = (warp & 1) * 64;

    wmma::fragment<wmma::accumulator, 16, 16, 16, float> acc[2][4];
    #pragma unroll
    for (int i = 0; i < 2; ++i)
        #pragma unroll
        for (int j = 0; j < 4; ++j)
            wmma::fill_fragment(acc[i][j], 0.0f);

    const int nch = K >> 5;

    // stage chunk 0 into buf 0
    {
        unsigned int d0 = sbase + drow;
        cp16(d0,                 gA0);     cp16(d0 + 16,             gA0 + 4);
        cp16(d0 + 10240,         gA1);     cp16(d0 + 10240 + 16,     gA1 + 4);
        cp16(d0 + 20480,         gB0);     cp16(d0 + 20480 + 16,     gB0 + 4);
        cp16(d0 + 30720,         gB1);     cp16(d0 + 30720 + 16,     gB1 + 4);
        asm volatile("cp.async.commit_group;" ::: "memory");
    }

    for (int ch = 0; ch < nch; ++ch) {
        const int buf = ch & 1;
        if (ch + 1 < nch) {
            const int kw = (ch + 1) * 16;
            unsigned int d0 = sbase + (buf ^ 1) * 40960 + drow;
            cp16(d0,             gA0 + kw); cp16(d0 + 16,         gA0 + kw + 4);
            cp16(d0 + 10240,     gA1 + kw); cp16(d0 + 10240 + 16, gA1 + kw + 4);
            cp16(d0 + 20480,     gB0 + kw); cp16(d0 + 20480 + 16, gB0 + kw + 4);
            cp16(d0 + 30720,     gB1 + kw); cp16(d0 + 30720 + 16, gB1 + kw + 4);
            asm volatile("cp.async.commit_group;" ::: "memory");
            asm volatile("cp.async.wait_group 1;" ::: "memory");
        } else {
            asm volatile("cp.async.wait_group 0;" ::: "memory");
        }
        __syncthreads();

        const __nv_bfloat16* pAh = (const __nv_bfloat16*)(smem + buf * 40960);
        const __nv_bfloat16* pAl = pAh + 5120;
        const __nv_bfloat16* pBh = pAh + 10240;
        const __nv_bfloat16* pBl = pAh + 15360;

        #pragma unroll
        for (int kk = 0; kk < 32; kk += 16) {
            wmma::fragment<wmma::matrix_a, 16, 16, 16, __nv_bfloat16,
                           wmma::row_major> ah[2], al[2];
            #pragma unroll
            for (int i = 0; i < 2; ++i) {
                wmma::load_matrix_sync(ah[i], pAh + (wm + i * 16) * 40 + kk, 40);
                wmma::load_matrix_sync(al[i], pAl + (wm + i * 16) * 40 + kk, 40);
            }
            #pragma unroll
            for (int j = 0; j < 4; ++j) {
                wmma::fragment<wmma::matrix_b, 16, 16, 16, __nv_bfloat16,
                               wmma::col_major> bh, bl;
                wmma::load_matrix_sync(bh, pBh + (wn + j * 16) * 40 + kk, 40);
                wmma::load_matrix_sync(bl, pBl + (wn + j * 16) * 40 + kk, 40);
                #pragma unroll
                for (int i = 0; i < 2; ++i) {
                    wmma::mma_sync(acc[i][j], ah[i], bh, acc[i][j]);
                    wmma::mma_sync(acc[i][j], al[i], bh, acc[i][j]);
                    wmma::mma_sync(acc[i][j], ah[i], bl, acc[i][j]);
                }
            }
        }
        __syncthreads();
    }

    // stage accumulators through smem, then masked/scattered scalar stores
    float* outs = (float*)smem;
    #pragma unroll
    for (int i = 0; i < 2; ++i)
        #pragma unroll
        for (int j = 0; j < 4; ++j)
            wmma::store_matrix_sync(outs + (wm + i * 16) * 128 + wn + j * 16,
                                    acc[i][j], 128, wmma::mem_row_major);
    __syncthreads();

    for (int i = tid; i < 128 * 128; i += 256) {
        int m = i >> 7, n = i & 127;
        float v = outs[i];
        int gm = m0 + m, gn = n0 + n;
        if (MODE >= 1) v += bias[gn];
        if (MODE == 2) {
            if (gm >= count) continue;
            C[(long long)d_outrow[gm] * ldc + gn] = v;
        } else {
            C[(size_t)gm * ldc + gn] = v;
        }
    }
}

// ---------------------------------------------------------------------------
// fp32 -> bf16 hi/lo conversion (2 elems per thread)
// ---------------------------------------------------------------------------
__global__ void conv_kernel(const float* __restrict__ src,
                            unsigned int* __restrict__ dh,
                            unsigned int* __restrict__ dl,
                            int cols2, int src_ld) {
    size_t idx = (size_t)blockIdx.x * 256 + threadIdx.x;
    size_t row = idx / cols2;
    int cp = (int)(idx - row * cols2);
    const float* s = src + row * (size_t)src_ld + (size_t)cp * 2;
    float a = s[0], b = s[1];
    dh[row * cols2 + cp] = pack_hi(a, b);
    dl[row * cols2 + cp] = pack_lo(a, b);
}

// ---------------------------------------------------------------------------
// Setup / gather / small kernels
// ---------------------------------------------------------------------------
__global__ void setup_kernel(const int* __restrict__ caplen,
                             const int* __restrict__ caps,
                             float* __restrict__ out) {
    __shared__ int lens_s[BBS];
    __shared__ int sort_s[BBS];
    __shared__ int dl_s[BBS];
    int i = threadIdx.x;
    int li = caplen[i];
    lens_s[i] = li;
    __syncthreads();
    int rank = 0;
    for (int j = 0; j < BBS; ++j) {
        int lj = lens_s[j];
        if (lj > li || (lj == li && j < i)) rank++;
    }
    sort_s[rank] = i;
    __syncthreads();
    int src = sort_s[i];
    d_sort[i] = src;
    int dl = lens_s[src] - 1;
    d_declen[i] = dl;
    dl_s[i] = dl;
    out[O_DECL + i] = (float)dl;
    out[O_SORT + i] = (float)src;
    for (int t = 0; t < CAPL; ++t) {
        int tok = caps[src * CAPL + t];
        out[O_CAPS + (long long)i * CAPL + t] = (float)tok;
        if (t < TTS) d_tokens[t * BBS + i] = tok;
    }
    float dlf = (float)dl;
    for (int s = 0; s < TTS; ++s)
        out[O_RPOS + (long long)i * TTS + s] =
            (s < dl) ? ((float)(s + 1) / dlf) : 0.0f;
    __syncthreads();
    if (i == 0) {
        int c = 0;
        for (int t = 0; t < TTS; ++t) {
            int n = 0;
            while (n < BBS && dl_s[n] > t) n++;
            d_nact[t] = n;
            for (int b = 0; b < n; ++b) {
                d_rowidx[c] = t * BBS + b;
                d_outrow[c] = b * TTS + t;
                c++;
            }
        }
        d_cnt = c;
    }
}

__global__ void gather_enc_kernel(const float* __restrict__ enc) {
    int g = blockIdx.x * 256 + threadIdx.x;
    int r = g >> 9, w = g & 511;
    int b = r / PPS, p = r % PPS;
    int srow = d_sort[b] * PPS + p;
    float4 v = ((const float4*)enc)[(size_t)srow * 512 + w];
    ((float4*)d_encs)[(size_t)r * 512 + w] = v;
    size_t o = (size_t)r * 1024 + (size_t)w * 2;
    d_ench[o]     = pack_hi(v.x, v.y);
    d_ench[o + 1] = pack_hi(v.z, v.w);
    d_encl[o]     = pack_lo(v.x, v.y);
    d_encl[o + 1] = pack_lo(v.z, v.w);
}

__global__ void mean_kernel() {
    int idx = blockIdx.x * 256 + threadIdx.x;
    int b = idx / ENCD, e = idx % ENCD;
    const float* base = d_encs + (size_t)b * PPS * ENCD + e;
    float s = 0.f;
    #pragma unroll 4
    for (int p = 0; p < PPS; ++p) s += base[(size_t)p * ENCD];
    d_mean[idx] = s * (1.0f / (float)PPS);
}

__global__ void w1copy_kernel(const float* __restrict__ l1Wih,
                              const float* __restrict__ l1Whh) {
    int g = blockIdx.x * 256 + threadIdx.x;
    int j = g / (2048 / 4);
    int c = (g % (2048 / 4)) * 4;
    float4 v;
    if (c < 1024) v = *(const float4*)(l1Wih + (size_t)j * 4096 + 1024 + c);
    else          v = *(const float4*)(l1Whh + (size_t)j * 1024 + (c - 1024));
    *(float4*)(d_W1cat + (size_t)j * 2048 + c) = v;
}

__global__ void w2copy_kernel(const float* __restrict__ l2Wih,
                              const float* __restrict__ l2Whh) {
    int g = blockIdx.x * 256 + threadIdx.x;
    int j = g / (4096 / 4);
    int c = (g % (4096 / 4)) * 4;
    float4 v;
    if (c < 3072) v = *(const float4*)(l2Wih + (size_t)j * 3072 + c);
    else          v = *(const float4*)(l2Whh + (size_t)j * 1024 + (c - 3072));
    *(float4*)(d_W2cat + (size_t)j * 4096 + c) = v;
}

__global__ void w3copy_kernel(const float* __restrict__ daW,
                              const float* __restrict__ fbW) {
    int g = blockIdx.x * 256 + threadIdx.x;
    int j = g / (1024 / 4);
    int c = (g % (1024 / 4)) * 4;
    float4 v;
    if (j < 1024) v = *(const float4*)(daW + (size_t)j * 1024 + c);
    else          v = *(const float4*)(fbW + (size_t)(j - 1024) * 1024 + c);
    *(float4*)(d_W3cat + (size_t)j * 1024 + c) = v;
}

__global__ void bias_kernel(const float* __restrict__ l1bih,
                            const float* __restrict__ l1bhh,
                            const float* __restrict__ l2bih,
                            const float* __restrict__ l2bhh,
                            const float* __restrict__ dab,
                            const float* __restrict__ fbb) {
    int j = blockIdx.x * 256 + threadIdx.x;
    d_b1sum[j] = l1bih[j] + l1bhh[j];
    d_b2sum[j] = l2bih[j] + l2bhh[j];
    if (j < 3072) d_b3cat[j] = (j < 1024) ? dab[j] : fbb[j - 1024];
}

__global__ void embg_kernel(const float* __restrict__ emb) {
    int m = blockIdx.x;
    int tok = d_tokens[m];
    const float2* src = (const float2*)(emb + (size_t)tok * DHID);
    #pragma unroll
    for (int q = 0; q < 2; ++q) {
        int i = threadIdx.x + 256 * q;
        float2 v = src[i];
        d_embgh[(size_t)m * 512 + i] = pack_hi(v.x, v.y);
        d_embgl[(size_t)m * 512 + i] = pack_lo(v.x, v.y);
    }
}

__global__ void zero_states_kernel() {
    int idx = blockIdx.x * 256 + threadIdx.x;
    d_x2[idx] = 0.f;
    if (idx < BBS * 2048) d_x1[idx] = 0.f;
    if (idx < BBS * DHID) { d_c1[idx] = 0.f; d_c2[idx] = 0.f; }
}

__global__ void zero_pred_kernel(float* __restrict__ out) {
    size_t g = (size_t)blockIdx.x * 256 + threadIdx.x;
    ((float4*)out)[g] = make_float4(0.f, 0.f, 0.f, 0.f);
}

// ---------------------------------------------------------------------------
// Skinny split-K GEMM (R11, unchanged)
// ---------------------------------------------------------------------------
template<bool BIAS>
__global__ void __launch_bounds__(128)
gemm32sk(const float* __restrict__ A,
         const float* __restrict__ Bm,
         const float* __restrict__ bias,
         float* __restrict__ C,
         int N, int Kc, int lda, int ldb, int t) {
    const int m0 = blockIdx.y * 32;
    if (t >= 0 && m0 >= d_nact[t]) return;
    __shared__ float As[16][36];
    __shared__ float Bs[16][132];
    const int tid = threadIdx.x;
    const int n0 = blockIdx.x * 128;
    const int ko = blockIdx.z * Kc;

    const int ar = tid >> 2;
    const int ac = (tid & 3) * 4;
    const float* Aptr = A + (size_t)(m0 + ar) * lda + ko + ac;
    const float* Bptr = Bm + (size_t)(n0 + tid) * ldb + ko;
    float* Cs = C + (size_t)blockIdx.z * BBS * N;

    const int ty = tid >> 4;
    const int tx = tid & 15;

    float acc[4][8];
    #pragma unroll
    for (int i = 0; i < 4; ++i)
        #pragma unroll
        for (int j = 0; j < 8; ++j) acc[i][j] = 0.f;

    float4 pav = *(const float4*)(Aptr);
    float4 pb[4];
    #pragma unroll
    for (int j = 0; j < 4; ++j) pb[j] = *(const float4*)(Bptr + j * 4);

    for (int k0 = 0; k0 < Kc; k0 += 16) {
        As[ac + 0][ar] = pav.x; As[ac + 1][ar] = pav.y;
        As[ac + 2][ar] = pav.z; As[ac + 3][ar] = pav.w;
        #pragma unroll
        for (int j = 0; j < 4; ++j) {
            Bs[j * 4 + 0][tid] = pb[j].x; Bs[j * 4 + 1][tid] = pb[j].y;
            Bs[j * 4 + 2][tid] = pb[j].z; Bs[j * 4 + 3][tid] = pb[j].w;
        }
        __syncthreads();
        if (k0 + 16 < Kc) {
            pav = *(const float4*)(Aptr + k0 + 16);
            #pragma unroll
            for (int j = 0; j < 4; ++j)
                pb[j] = *(const float4*)(Bptr + k0 + 16 + j * 4);
        }
        #pragma unroll
        for (int kk = 0; kk < 16; ++kk) {
            float a[4], b[8];
            *(float4*)(a)     = *(const float4*)&As[kk][ty * 4];
            *(float4*)(b)     = *(const float4*)&Bs[kk][tx * 4];
            *(float4*)(b + 4) = *(const float4*)&Bs[kk][64 + tx * 4];
            #pragma unroll
            for (int i = 0; i < 4; ++i)
                #pragma unroll
                for (int j = 0; j < 8; ++j)
                    acc[i][j] = fmaf(a[i], b[j], acc[i][j]);
        }
        __syncthreads();
    }

    float bv[8];
    #pragma unroll
    for (int j = 0; j < 8; ++j) {
        int n = (j < 4) ? (n0 + tx * 4 + j) : (n0 + 64 + tx * 4 + j - 4);
        bv[j] = BIAS ? bias[n] : 0.f;
    }

    #pragma unroll
    for (int i = 0; i < 4; ++i) {
        int m = m0 + ty * 4 + i;
        float* dst = Cs + (size_t)m * N + n0;
        float4 v0, v1;
        v0.x = acc[i][0] + bv[0]; v0.y = acc[i][1] + bv[1];
        v0.z = acc[i][2] + bv[2]; v0.w = acc[i][3] + bv[3];
        v1.x = acc[i][4] + bv[4]; v1.y = acc[i][5] + bv[5];
        v1.z = acc[i][6] + bv[6]; v1.w = acc[i][7] + bv[7];
        *(float4*)(dst + tx * 4)      = v0;
        *(float4*)(dst + 64 + tx * 4) = v1;
    }
}

// ---------------------------------------------------------------------------
// LSTM pointwise (R11, unchanged)
// ---------------------------------------------------------------------------
__global__ void lstm1_kernel(int t, const float* __restrict__ econ_t) {
    int idx = blockIdx.x * 256 + threadIdx.x;
    int b = idx / DHID, k = idx % DHID;
    if (t >= d_declen[b]) return;
    size_t base = (size_t)b * 4096;
    float g4[4];
    #pragma unroll
    for (int q = 0; q < 4; ++q) {
        int j = q * 1024 + k;
        float v = d_base1[base + j] + econ_t[base + j];
        v += d_gp[0 * BBS * 4096 + base + j];
        v += d_gp[1 * BBS * 4096 + base + j];
        v += d_gp[2 * BBS * 4096 + base + j];
        v += d_gp[3 * BBS * 4096 + base + j];
        g4[q] = v;
    }
    float c = d_c1[idx];
    float cn = sigf(g4[1]) * c + sigf(g4[0]) * tanhf(g4[2]);
    float hn = sigf(g4[3]) * tanhf(cn);
    d_c1[idx] = cn;
    d_x1[(size_t)b * 2048 + 1024 + k] = hn;
    d_x2[(size_t)b * 4096 + 2048 + k] = hn;
}

__global__ void lstm2_kernel(int t) {
    int idx = blockIdx.x * 256 + threadIdx.x;
    int b = idx / DHID, k = idx % DHID;
    if (t >= d_declen[b]) return;
    size_t base = (size_t)b * 4096;
    float g4[4];
    #pragma unroll
    for (int q = 0; q < 4; ++q) {
        int j = q * 1024 + k;
        float v = d_b2sum[j];
        v += d_gp[0 * BBS * 4096 + base + j];
        v += d_gp[1 * BBS * 4096 + base + j];
        v += d_gp[2 * BBS * 4096 + base + j];
        v += d_gp[3 * BBS * 4096 + base + j];
        g4[q] = v;
    }
    float c = d_c2[idx];
    float cn = sigf(g4[1]) * c + sigf(g4[0]) * tanhf(g4[2]);
    float hn = sigf(g4[3]) * tanhf(cn);
    d_c2[idx] = cn;
    d_h2all[(size_t)(t * BBS + b) * DHID + k] = hn;
    d_x1[(size_t)b * 2048 + k] = hn;
    d_x2[(size_t)b * 4096 + 3072 + k] = hn;
}

// ---------------------------------------------------------------------------
// Fused attention (R11, unchanged)
// ---------------------------------------------------------------------------
__global__ void attn_kernel(const float* __restrict__ fullW,
                            const float* __restrict__ fullb, int t) {
    const int b = blockIdx.x;
    if (t >= d_declen[b]) return;
    __shared__ float s_a2[DHID];
    __shared__ float s_w [DHID];
    __shared__ float s_sc[PPS];
    __shared__ float s_red[256];
    const int tid = threadIdx.x;
    const int lane = tid & 31, warp = tid >> 5;
    const size_t abase = (size_t)b * 3072;

    for (int i = tid; i < DHID; i += 256) {
        s_a2[i] = d_b3cat[i] + d_ap[abase + i]
                + d_ap[(size_t)BBS * 3072 + abase + i];
        s_w[i]  = fullW[i];
    }
    __syncthreads();

    const float b0 = fullb[0];
    for (int p = warp; p < PPS; p += 8) {
        const float* row = d_att1 + ((size_t)b * PPS + p) * DHID;
        float s = 0.f;
        #pragma unroll 8
        for (int a = lane; a < DHID; a += 32)
            s += tanh_fast(row[a] + s_a2[a]) * s_w[a];
        #pragma unroll
        for (int o = 16; o > 0; o >>= 1)
            s += __shfl_down_sync(0xffffffffu, s, o);
        if (lane == 0) s_sc[p] = s + b0;
    }
    __syncthreads();

    s_red[tid] = (tid < PPS) ? s_sc[tid] : -INFINITY;
    __syncthreads();
    for (int s = 128; s > 0; s >>= 1) {
        if (tid < s) s_red[tid] = fmaxf(s_red[tid], s_red[tid + s]);
        __syncthreads();
    }
    float mx = s_red[0];
    __syncthreads();
    float e = 0.f;
    if (tid < PPS) e = __expf(s_sc[tid] - mx);
    s_red[tid] = e;
    __syncthreads();
    for (int s = 128; s > 0; s >>= 1) {
        if (tid < s) s_red[tid] += s_red[tid + s];
        __syncthreads();
    }
    float inv = 1.0f / s_red[0];
    __syncthreads();
    if (tid < PPS) s_sc[tid] = e * inv;
    __syncthreads();

    const float* encb = d_encs + (size_t)b * PPS * ENCD;
    for (int ei = tid; ei < ENCD; ei += 256) {
        float acc = 0.f;
        const float* col = encb + ei;
        #pragma unroll 4
        for (int p = 0; p < PPS; ++p)
            acc = fmaf(s_sc[p], col[(size_t)p * ENCD], acc);
        float gl = d_b3cat[1024 + ei] + d_ap[abase + 1024 + ei]
                 + d_ap[(size_t)BBS * 3072 + abase + 1024 + ei];
        d_x2[(size_t)b * 4096 + ei] = sigf(gl) * acc;
    }
}

__global__ void rpm_kernel(const float* __restrict__ rpmW,
                           float* __restrict__ out) {
    int m = blockIdx.x * 8 + (threadIdx.x >> 5);
    if (m >= TTS * BBS) return;
    int lane = threadIdx.x & 31;
    int t = m / BBS, b = m % BBS;
    const float* h = d_h2all + (size_t)m * DHID;
    float s = 0.f;
    #pragma unroll 8
    for (int k = lane; k < DHID; k += 32) s += h[k] * rpmW[k];
    #pragma unroll
    for (int o = 16; o > 0; o >>= 1)
        s += __shfl_down_sync(0xffffffffu, s, o);
    if (lane == 0)
        out[O_PPOS + (long long)b * TTS + t] =
            (t < d_declen[b]) ? sigf(s) : 0.f;
}

// ---------------------------------------------------------------------------
// Launch
// ---------------------------------------------------------------------------
extern "C" void kernel_launch(void* const* d_in, const int* in_sizes, int n_in,
                              void* d_out, int out_size) {
    const float* enc_out = (const float*)d_in[0];
    const int*   caps    = (const int*)  d_in[1];
    const int*   caplen  = (const int*)  d_in[2];
    const float* emb     = (const float*)d_in[3];
    const float* eaW     = (const float*)d_in[4];
    const float* eab     = (const float*)d_in[5];
    const float* daW     = (const float*)d_in[6];
    const float* dab     = (const float*)d_in[7];
    const float* faW     = (const float*)d_in[8];
    const float* fab     = (const float*)d_in[9];
    const float* fbW     = (const float*)d_in[10];
    const float* fbb     = (const float*)d_in[11];
    const float* l1Wih   = (const float*)d_in[12];
    const float* l1Whh   = (const float*)d_in[13];
    const float* l1bih   = (const float*)d_in[14];
    const float* l1bhh   = (const float*)d_in[15];
    const float* l2Wih   = (const float*)d_in[16];
    const float* l2Whh   = (const float*)d_in[17];
    const float* l2bih   = (const float*)d_in[18];
    const float* l2bhh   = (const float*)d_in[19];
    const float* ramW    = (const float*)d_in[20];
    const float* ramb    = (const float*)d_in[21];
    const float* rpmW    = (const float*)d_in[22];
    float* out = (float*)d_out;

    float* p_att1;  cudaGetSymbolAddress((void**)&p_att1,  d_att1);
    float* p_econ;  cudaGetSymbolAddress((void**)&p_econ,  d_econ);
    float* p_W1;    cudaGetSymbolAddress((void**)&p_W1,    d_W1cat);
    float* p_W2;    cudaGetSymbolAddress((void**)&p_W2,    d_W2cat);
    float* p_W3;    cudaGetSymbolAddress((void**)&p_W3,    d_W3cat);
    float* p_b1;    cudaGetSymbolAddress((void**)&p_b1,    d_b1sum);
    float* p_base1; cudaGetSymbolAddress((void**)&p_base1, d_base1);
    float* p_gp;    cudaGetSymbolAddress((void**)&p_gp,    d_gp);
    float* p_ap;    cudaGetSymbolAddress((void**)&p_ap,    d_ap);
    float* p_x1;    cudaGetSymbolAddress((void**)&p_x1,    d_x1);
    float* p_x2;    cudaGetSymbolAddress((void**)&p_x2,    d_x2);
    float* p_mean;  cudaGetSymbolAddress((void**)&p_mean,  d_mean);
    float* p_h2;    cudaGetSymbolAddress((void**)&p_h2,    d_h2all);
    unsigned int *p_ench, *p_encl, *p_eaWh, *p_eaWl, *p_W1eh, *p_W1el;
    unsigned int *p_embgh, *p_embgl, *p_ramWh, *p_ramWl, *p_h2h, *p_h2l;
    cudaGetSymbolAddress((void**)&p_ench,  d_ench);
    cudaGetSymbolAddress((void**)&p_encl,  d_encl);
    cudaGetSymbolAddress((void**)&p_eaWh,  d_eaWh);
    cudaGetSymbolAddress((void**)&p_eaWl,  d_eaWl);
    cudaGetSymbolAddress((void**)&p_W1eh,  d_W1eh);
    cudaGetSymbolAddress((void**)&p_W1el,  d_W1el);
    cudaGetSymbolAddress((void**)&p_embgh, d_embgh);
    cudaGetSymbolAddress((void**)&p_embgl, d_embgl);
    cudaGetSymbolAddress((void**)&p_ramWh, d_ramWh);
    cudaGetSymbolAddress((void**)&p_ramWl, d_ramWl);
    cudaGetSymbolAddress((void**)&p_h2h,   d_h2h);
    cudaGetSymbolAddress((void**)&p_h2l,   d_h2l);

    cudaFuncSetAttribute(gemm_wb<0>, cudaFuncAttributeMaxDynamicSharedMemorySize,
                         WB_SMEM);
    cudaFuncSetAttribute(gemm_wb<1>, cudaFuncAttributeMaxDynamicSharedMemorySize,
                         WB_SMEM);
    cudaFuncSetAttribute(gemm_wb<2>, cudaFuncAttributeMaxDynamicSharedMemorySize,
                         WB_SMEM);

    // 1-3: sort, gather(+bf16 split), convert eaW
    setup_kernel<<<1, BBS>>>(caplen, caps, out);
    gather_enc_kernel<<<50176, 256>>>(enc_out);
    conv_kernel<<<(1024 * 1024) / 256, 256>>>(eaW, p_eaWh, p_eaWl, 1024, 2048);

    // 4: att1 (bf16x3 HMMA): 25088 x 1024, K=2048  <- profiled slot
    gemm_wb<1><<<dim3(1024 / 128, (BBS * PPS) / 128), 256, WB_SMEM>>>(
        p_ench, p_encl, p_eaWh, p_eaWl, eab, p_att1, 2048, 1024, 1024, 1024);

    // 5+: mean, zero pred, biases, weight concats, W1e conversion
    mean_kernel<<<(BBS * ENCD) / 256, 256>>>();
    zero_pred_kernel<<<84000, 256>>>(out + O_PRED);
    bias_kernel<<<16, 256>>>(l1bih, l1bhh, l2bih, l2bhh, dab, fbb);
    w1copy_kernel<<<8192, 256>>>(l1Wih, l1Whh);
    w2copy_kernel<<<16384, 256>>>(l2Wih, l2Whh);
    w3copy_kernel<<<3072, 256>>>(daW, fbW);
    conv_kernel<<<(4096 * 512) / 256, 256>>>(l1Wih, p_W1eh, p_W1el, 512, 4096);

    // embeddings (bf16 split)
    embg_kernel<<<TTS * BBS, 256>>>(emb);

    // econ (bf16x3 HMMA): 2688 x 4096, K=1024
    gemm_wb<0><<<dim3(4096 / 128, (TTS * BBS) / 128), 256, WB_SMEM>>>(
        p_embgh, p_embgl, p_W1eh, p_W1el, nullptr, p_econ, 1024, 512, 512, 4096);

    // ramW conversion (for preds later)
    conv_kernel<<<(VOC * 512) / 256, 256>>>(ramW, p_ramWh, p_ramWl, 512, 1024);

    // base1 = mean_enc @ Wih[:,2048:].T + (bih+bhh)
    gemm32sk<true><<<dim3(4096 / 128, 4, 1), 128>>>(
        p_mean, l1Wih + 2048, p_b1, p_base1, 4096, 2048, 2048, 4096, -1);

    zero_states_kernel<<<(BBS * 4096) / 256, 256>>>();

    // sequential decode (R11 split-K SIMT)
    for (int t = 0; t < TTS; ++t) {
        gemm32sk<false><<<dim3(4096 / 128, 4, 4), 128>>>(
            p_x1, p_W1, nullptr, p_gp, 4096, 512, 2048, 2048, t);

        lstm1_kernel<<<(BBS * DHID) / 256, 256>>>(
            t, p_econ + (size_t)t * BBS * 4096);

        gemm32sk<false><<<dim3(3072 / 128, 4, 2), 128>>>(
            p_x2 + 2048, p_W3, nullptr, p_ap, 3072, 512, 4096, 1024, t);

        attn_kernel<<<BBS, 256>>>(faW, fab, t);

        gemm32sk<false><<<dim3(4096 / 128, 4, 4), 128>>>(
            p_x2, p_W2, nullptr, p_gp, 4096, 1024, 4096, 4096, t);

        lstm2_kernel<<<(BBS * DHID) / 256, 256>>>(t);
    }

    // h2 -> bf16 split, then preds (bf16x3 HMMA, compact gather/scatter)
    conv_kernel<<<(TTS * BBS * 512) / 256, 256>>>(p_h2, p_h2h, p_h2l, 512, 1024);
    gemm_wb<2><<<dim3(VOC / 128, (TTS * BBS + 127) / 128), 256, WB_SMEM>>>(
        p_h2h, p_h2l, p_ramWh, p_ramWl, ramb, out + O_PRED, 1024, 512, 512, VOC);

    // predicted_pos
    rpm_kernel<<<(TTS * BBS + 7) / 8, 256>>>(rpmW, out);
}

// round 14
// speedup vs baseline: 1.7642x; 1.3260x over previous
#include <cuda_runtime.h>
#include <cuda_bf16.h>
#include <mma.h>
#include <math.h>
using namespace nvcuda;

// ---------------------------------------------------------------------------
// Problem constants
// ---------------------------------------------------------------------------
#define TTS   21
#define CAPL  22
#define BBS   128
#define PPS   196
#define ENCD  2048
#define DHID  1024
#define VOC   32000

static constexpr long long O_PRED = 0;
static constexpr long long O_CAPS = (long long)BBS * TTS * VOC;
static constexpr long long O_DECL = O_CAPS + (long long)BBS * CAPL;
static constexpr long long O_SORT = O_DECL + BBS;
static constexpr long long O_RPOS = O_SORT + BBS;
static constexpr long long O_PPOS = O_RPOS + (long long)BBS * TTS;

// ---------------------------------------------------------------------------
// Static device scratch
// ---------------------------------------------------------------------------
__device__ float d_encs [(size_t)BBS * PPS * ENCD];
__device__ float d_att1 [(size_t)BBS * PPS * DHID];
__device__ float d_econ [(size_t)TTS * BBS * 4 * DHID];
__device__ float d_W1cat[4096 * 2048];
__device__ float d_W2cat[(size_t)4096 * 4096];
__device__ float d_W3cat[3072 * 1024];
__device__ float d_b1sum[4096];
__device__ float d_b2sum[4096];
__device__ float d_b3cat[3072];
__device__ float d_base1[BBS * 4096];
__device__ float d_gp   [4 * BBS * 4096];
__device__ float d_ap   [2 * BBS * 3072];
__device__ float d_c1   [BBS * DHID];
__device__ float d_c2   [BBS * DHID];
__device__ float d_mean [BBS * ENCD];
__device__ float d_h2all[(size_t)TTS * BBS * DHID];
__device__ int   d_sort  [BBS];
__device__ int   d_declen[BBS];
__device__ int   d_tokens[TTS * BBS];
__device__ int   d_nact  [TTS];
__device__ int   d_rowidx[TTS * BBS];
__device__ int   d_outrow[TTS * BBS];
__device__ int   d_cnt;

// bf16 hi/lo buffers (packed bf16x2 in uint32, row-major)
__device__ unsigned int d_ench [(size_t)BBS * PPS * (ENCD / 2)];
__device__ unsigned int d_encl [(size_t)BBS * PPS * (ENCD / 2)];
__device__ unsigned int d_eaWh [1024 * (ENCD / 2)];
__device__ unsigned int d_eaWl [1024 * (ENCD / 2)];
__device__ unsigned int d_W1eh [4096 * (DHID / 2)];
__device__ unsigned int d_W1el [4096 * (DHID / 2)];
__device__ unsigned int d_embgh[TTS * BBS * (DHID / 2)];
__device__ unsigned int d_embgl[TTS * BBS * (DHID / 2)];
__device__ unsigned int d_ramWh[(size_t)VOC * (DHID / 2)];
__device__ unsigned int d_ramWl[(size_t)VOC * (DHID / 2)];
__device__ unsigned int d_h2h  [TTS * BBS * (DHID / 2)];
__device__ unsigned int d_h2l  [TTS * BBS * (DHID / 2)];
// loop-GEMM operands
__device__ unsigned int d_W1h  [4096 * 1024];   // W1cat bf16 hi (4096 x 2048)
__device__ unsigned int d_W1l  [4096 * 1024];
__device__ unsigned int d_W2h  [(size_t)4096 * 2048];
__device__ unsigned int d_W2l  [(size_t)4096 * 2048];
__device__ unsigned int d_W3h  [3072 * 512];
__device__ unsigned int d_W3l  [3072 * 512];
__device__ unsigned int d_x1h  [BBS * 1024];    // [h2 | h1] bf16 hi
__device__ unsigned int d_x1l  [BBS * 1024];
__device__ unsigned int d_x2h  [BBS * 2048];    // [att | h1n | h2]
__device__ unsigned int d_x2l  [BBS * 2048];

// ---------------------------------------------------------------------------
// Helpers
// ---------------------------------------------------------------------------
__device__ __forceinline__ float sigf(float x) {
    return 1.0f / (1.0f + __expf(-x));
}
__device__ __forceinline__ float tanh_fast(float x) {
    return 1.0f - 2.0f / (__expf(2.0f * x) + 1.0f);
}
__device__ __forceinline__ unsigned int pack_hi(float a, float b) {
    __nv_bfloat162 p = __floats2bfloat162_rn(a, b);
    return *reinterpret_cast<unsigned int*>(&p);
}
__device__ __forceinline__ unsigned int pack_lo(float a, float b) {
    float ah = __bfloat162float(__float2bfloat16_rn(a));
    float bh = __bfloat162float(__float2bfloat16_rn(b));
    __nv_bfloat162 p = __floats2bfloat162_rn(a - ah, b - bh);
    return *reinterpret_cast<unsigned int*>(&p);
}
__device__ __forceinline__ unsigned int smem_u32(const void* p) {
    unsigned int a;
    asm("{ .reg .u64 t; cvta.to.shared.u64 t, %1; cvt.u32.u64 %0, t; }"
        : "=r"(a) : "l"(p));
    return a;
}
__device__ __forceinline__ void cp16(unsigned int dst, const void* src) {
    asm volatile("cp.async.cg.shared.global [%0], [%1], 16;"
                 :: "r"(dst), "l"(__cvta_generic_to_global(src)) : "memory");
}
__device__ __forceinline__ void cp8(unsigned int dst, const void* src) {
    asm volatile("cp.async.ca.shared.global [%0], [%1], 8;"
                 :: "r"(dst), "l"(__cvta_generic_to_global(src)) : "memory");
}

// ---------------------------------------------------------------------------
// Big bf16x3 wmma GEMM (128x128 tile). 2 blocks/SM forced.
// MODE 0: plain  MODE 1: +bias  MODE 2: +bias + gather/scatter (preds)
// ---------------------------------------------------------------------------
static constexpr int WB_SMEM = 81920;

template<int MODE>
__global__ void __launch_bounds__(256, 2)
gemm_wb(const unsigned int* __restrict__ Ah, const unsigned int* __restrict__ Al,
        const unsigned int* __restrict__ Bh, const unsigned int* __restrict__ Bl,
        const float* __restrict__ bias, float* __restrict__ C,
        int K, int lda32, int ldb32, int ldc) {
    extern __shared__ char smem[];
    const int tid = threadIdx.x;
    const int warp = tid >> 5;
    const int m0 = blockIdx.y * 128, n0 = blockIdx.x * 128;
    int count = 0;
    if (MODE == 2) {
        count = d_cnt;
        if (m0 >= count) return;
    }

    const int lr = tid >> 1;
    const int lc = (tid & 1) * 8;
    int arow = m0 + lr;
    if (MODE == 2) arow = (arow < count) ? d_rowidx[arow] : d_rowidx[0];
    const unsigned int* gA0 = Ah + (size_t)arow * lda32 + lc;
    const unsigned int* gA1 = Al + (size_t)arow * lda32 + lc;
    const unsigned int* gB0 = Bh + (size_t)(n0 + lr) * ldb32 + lc;
    const unsigned int* gB1 = Bl + (size_t)(n0 + lr) * ldb32 + lc;

    const unsigned int sbase = smem_u32(smem);
    const unsigned int drow = (unsigned)(lr * 80 + lc * 4);

    const int wm = (warp >> 1) * 32;
    const int wn = (warp & 1) * 64;

    wmma::fragment<wmma::accumulator, 16, 16, 16, float> acc[2][4];
    #pragma unroll
    for (int i = 0; i < 2; ++i)
        #pragma unroll
        for (int j = 0; j < 4; ++j)
            wmma::fill_fragment(acc[i][j], 0.0f);

    const int nch = K >> 5;
    {
        unsigned int d0 = sbase + drow;
        cp16(d0,             gA0); cp16(d0 + 16,         gA0 + 4);
        cp16(d0 + 10240,     gA1); cp16(d0 + 10240 + 16, gA1 + 4);
        cp16(d0 + 20480,     gB0); cp16(d0 + 20480 + 16, gB0 + 4);
        cp16(d0 + 30720,     gB1); cp16(d0 + 30720 + 16, gB1 + 4);
        asm volatile("cp.async.commit_group;" ::: "memory");
    }

    for (int ch = 0; ch < nch; ++ch) {
        const int buf = ch & 1;
        if (ch + 1 < nch) {
            const int kw = (ch + 1) * 16;
            unsigned int d0 = sbase + (buf ^ 1) * 40960 + drow;
            cp16(d0,             gA0 + kw); cp16(d0 + 16,         gA0 + kw + 4);
            cp16(d0 + 10240,     gA1 + kw); cp16(d0 + 10240 + 16, gA1 + kw + 4);
            cp16(d0 + 20480,     gB0 + kw); cp16(d0 + 20480 + 16, gB0 + kw + 4);
            cp16(d0 + 30720,     gB1 + kw); cp16(d0 + 30720 + 16, gB1 + kw + 4);
            asm volatile("cp.async.commit_group;" ::: "memory");
            asm volatile("cp.async.wait_group 1;" ::: "memory");
        } else {
            asm volatile("cp.async.wait_group 0;" ::: "memory");
        }
        __syncthreads();

        const __nv_bfloat16* pAh = (const __nv_bfloat16*)(smem + buf * 40960);
        const __nv_bfloat16* pAl = pAh + 5120;
        const __nv_bfloat16* pBh = pAh + 10240;
        const __nv_bfloat16* pBl = pAh + 15360;

        #pragma unroll
        for (int kk = 0; kk < 32; kk += 16) {
            wmma::fragment<wmma::matrix_a, 16, 16, 16, __nv_bfloat16,
                           wmma::row_major> ah[2], al[2];
            #pragma unroll
            for (int i = 0; i < 2; ++i) {
                wmma::load_matrix_sync(ah[i], pAh + (wm + i * 16) * 40 + kk, 40);
                wmma::load_matrix_sync(al[i], pAl + (wm + i * 16) * 40 + kk, 40);
            }
            #pragma unroll
            for (int j = 0; j < 4; ++j) {
                wmma::fragment<wmma::matrix_b, 16, 16, 16, __nv_bfloat16,
                               wmma::col_major> bh, bl;
                wmma::load_matrix_sync(bh, pBh + (wn + j * 16) * 40 + kk, 40);
                wmma::load_matrix_sync(bl, pBl + (wn + j * 16) * 40 + kk, 40);
                #pragma unroll
                for (int i = 0; i < 2; ++i) {
                    wmma::mma_sync(acc[i][j], ah[i], bh, acc[i][j]);
                    wmma::mma_sync(acc[i][j], al[i], bh, acc[i][j]);
                    wmma::mma_sync(acc[i][j], ah[i], bl, acc[i][j]);
                }
            }
        }
        __syncthreads();
    }

    float* outs = (float*)smem;
    #pragma unroll
    for (int i = 0; i < 2; ++i)
        #pragma unroll
        for (int j = 0; j < 4; ++j)
            wmma::store_matrix_sync(outs + (wm + i * 16) * 128 + wn + j * 16,
                                    acc[i][j], 128, wmma::mem_row_major);
    __syncthreads();

    for (int i = tid; i < 128 * 128; i += 256) {
        int m = i >> 7, n = i & 127;
        float v = outs[i];
        int gm = m0 + m, gn = n0 + n;
        if (MODE >= 1) v += bias[gn];
        if (MODE == 2) {
            if (gm >= count) continue;
            C[(long long)d_outrow[gm] * ldc + gn] = v;
        } else {
            C[(size_t)gm * ldc + gn] = v;
        }
    }
}

// ---------------------------------------------------------------------------
// Skinny bf16x3 wmma split-K GEMM for the decode loop.
// 32x128 tile, K-chunk 32, 8 warps (warp tile 16x32), double-buffered.
// Writes fp32 partials to slab blockIdx.z of C. Early-exit via d_nact[t].
// smem: 2 bufs x (A:2x2560 + B:2x10240) = 51200 B.
// ---------------------------------------------------------------------------
static constexpr int WS_SMEM = 51200;

__global__ void __launch_bounds__(256)
gemm_ws(const unsigned int* __restrict__ Ah, const unsigned int* __restrict__ Al,
        const unsigned int* __restrict__ Bh, const unsigned int* __restrict__ Bl,
        float* __restrict__ C, int N, int Kc, int lda32, int ldb32, int t) {
    const int m0 = blockIdx.y * 32;
    if (m0 >= d_nact[t]) return;
    extern __shared__ char smem[];
    const int tid = threadIdx.x;
    const int warp = tid >> 5;
    const int n0 = blockIdx.x * 128;
    const int ko32 = blockIdx.z * (Kc >> 1);
    float* Cs = C + (size_t)blockIdx.z * BBS * N;

    // A loaders: 32 rows x 16 u32, 256 thr x 1 cp8
    const int ra = tid >> 3, ca = (tid & 7) * 2;
    const unsigned int* gAh = Ah + (size_t)(m0 + ra) * lda32 + ko32 + ca;
    const unsigned int* gAl = Al + (size_t)(m0 + ra) * lda32 + ko32 + ca;
    const unsigned int aoff = (unsigned)(ra * 80 + ca * 4);
    // B loaders: 128 rows x 16 u32, 256 thr x 2 cp16
    const int rb = tid >> 1, cb = (tid & 1) * 8;
    const unsigned int* gBh = Bh + (size_t)(n0 + rb) * ldb32 + ko32 + cb;
    const unsigned int* gBl = Bl + (size_t)(n0 + rb) * ldb32 + ko32 + cb;
    const unsigned int boff = (unsigned)(rb * 80 + cb * 4);

    const unsigned int sbase = smem_u32(smem);
    const int wm = (warp >> 2) * 16;
    const int wn = (warp & 3) * 32;

    wmma::fragment<wmma::accumulator, 16, 16, 16, float> acc[2];
    wmma::fill_fragment(acc[0], 0.0f);
    wmma::fill_fragment(acc[1], 0.0f);

    const int nch = Kc >> 5;
    {
        cp8(sbase + aoff,                 gAh);
        cp8(sbase + 2560 + aoff,          gAl);
        cp16(sbase + 5120 + boff,         gBh);
        cp16(sbase + 5120 + boff + 16,    gBh + 4);
        cp16(sbase + 15360 + boff,        gBl);
        cp16(sbase + 15360 + boff + 16,   gBl + 4);
        asm volatile("cp.async.commit_group;" ::: "memory");
    }

    for (int ch = 0; ch < nch; ++ch) {
        const int buf = ch & 1;
        if (ch + 1 < nch) {
            const int kw = (ch + 1) * 16;
            unsigned int s = sbase + (buf ^ 1) * 25600;
            cp8(s + aoff,                gAh + kw);
            cp8(s + 2560 + aoff,         gAl + kw);
            cp16(s + 5120 + boff,        gBh + kw);
            cp16(s + 5120 + boff + 16,   gBh + kw + 4);
            cp16(s + 15360 + boff,       gBl + kw);
            cp16(s + 15360 + boff + 16,  gBl + kw + 4);
            asm volatile("cp.async.commit_group;" ::: "memory");
            asm volatile("cp.async.wait_group 1;" ::: "memory");
        } else {
            asm volatile("cp.async.wait_group 0;" ::: "memory");
        }
        __syncthreads();

        const __nv_bfloat16* pAh = (const __nv_bfloat16*)(smem + buf * 25600);
        const __nv_bfloat16* pAl = pAh + 1280;
        const __nv_bfloat16* pBh = pAh + 2560;
        const __nv_bfloat16* pBl = pAh + 7680;

        #pragma unroll
        for (int kk = 0; kk < 32; kk += 16) {
            wmma::fragment<wmma::matrix_a, 16, 16, 16, __nv_bfloat16,
                           wmma::row_major> ah, al;
            wmma::load_matrix_sync(ah, pAh + wm * 40 + kk, 40);
            wmma::load_matrix_sync(al, pAl + wm * 40 + kk, 40);
            #pragma unroll
            for (int j = 0; j < 2; ++j) {
                wmma::fragment<wmma::matrix_b, 16, 16, 16, __nv_bfloat16,
                               wmma::col_major> bh, bl;
                wmma::load_matrix_sync(bh, pBh + (wn + j * 16) * 40 + kk, 40);
                wmma::load_matrix_sync(bl, pBl + (wn + j * 16) * 40 + kk, 40);
                wmma::mma_sync(acc[j], ah, bh, acc[j]);
                wmma::mma_sync(acc[j], al, bh, acc[j]);
                wmma::mma_sync(acc[j], ah, bl, acc[j]);
            }
        }
        __syncthreads();
    }

    float* outs = (float*)smem;
    #pragma unroll
    for (int j = 0; j < 2; ++j)
        wmma::store_matrix_sync(outs + wm * 128 + wn + j * 16, acc[j], 128,
                                wmma::mem_row_major);
    __syncthreads();

    for (int i = tid; i < 32 * 128; i += 256) {
        int m = i >> 7, n = i & 127;
        Cs[(size_t)(m0 + m) * N + n0 + n] = outs[i];
    }
}

// ---------------------------------------------------------------------------
// fp32 -> bf16 hi/lo conversion (2 elems per thread)
// ---------------------------------------------------------------------------
__global__ void conv_kernel(const float* __restrict__ src,
                            unsigned int* __restrict__ dh,
                            unsigned int* __restrict__ dl,
                            int cols2, int src_ld) {
    size_t idx = (size_t)blockIdx.x * 256 + threadIdx.x;
    size_t row = idx / cols2;
    int cp = (int)(idx - row * cols2);
    const float* s = src + row * (size_t)src_ld + (size_t)cp * 2;
    float a = s[0], b = s[1];
    dh[row * cols2 + cp] = pack_hi(a, b);
    dl[row * cols2 + cp] = pack_lo(a, b);
}

// ---------------------------------------------------------------------------
// Setup / gather / small kernels
// ---------------------------------------------------------------------------
__global__ void setup_kernel(const int* __restrict__ caplen,
                             const int* __restrict__ caps,
                             float* __restrict__ out) {
    __shared__ int lens_s[BBS];
    __shared__ int sort_s[BBS];
    __shared__ int dl_s[BBS];
    int i = threadIdx.x;
    int li = caplen[i];
    lens_s[i] = li;
    __syncthreads();
    int rank = 0;
    for (int j = 0; j < BBS; ++j) {
        int lj = lens_s[j];
        if (lj > li || (lj == li && j < i)) rank++;
    }
    sort_s[rank] = i;
    __syncthreads();
    int src = sort_s[i];
    d_sort[i] = src;
    int dl = lens_s[src] - 1;
    d_declen[i] = dl;
    dl_s[i] = dl;
    out[O_DECL + i] = (float)dl;
    out[O_SORT + i] = (float)src;
    for (int t = 0; t < CAPL; ++t) {
        int tok = caps[src * CAPL + t];
        out[O_CAPS + (long long)i * CAPL + t] = (float)tok;
        if (t < TTS) d_tokens[t * BBS + i] = tok;
    }
    float dlf = (float)dl;
    for (int s = 0; s < TTS; ++s)
        out[O_RPOS + (long long)i * TTS + s] =
            (s < dl) ? ((float)(s + 1) / dlf) : 0.0f;
    __syncthreads();
    if (i == 0) {
        int c = 0;
        for (int t = 0; t < TTS; ++t) {
            int n = 0;
            while (n < BBS && dl_s[n] > t) n++;
            d_nact[t] = n;
            for (int b = 0; b < n; ++b) {
                d_rowidx[c] = t * BBS + b;
                d_outrow[c] = b * TTS + t;
                c++;
            }
        }
        d_cnt = c;
    }
}

__global__ void gather_enc_kernel(const float* __restrict__ enc) {
    int g = blockIdx.x * 256 + threadIdx.x;
    int r = g >> 9, w = g & 511;
    int b = r / PPS, p = r % PPS;
    int srow = d_sort[b] * PPS + p;
    float4 v = ((const float4*)enc)[(size_t)srow * 512 + w];
    ((float4*)d_encs)[(size_t)r * 512 + w] = v;
    size_t o = (size_t)r * 1024 + (size_t)w * 2;
    d_ench[o]     = pack_hi(v.x, v.y);
    d_ench[o + 1] = pack_hi(v.z, v.w);
    d_encl[o]     = pack_lo(v.x, v.y);
    d_encl[o + 1] = pack_lo(v.z, v.w);
}

__global__ void mean_kernel() {
    int idx = blockIdx.x * 256 + threadIdx.x;
    int b = idx / ENCD, e = idx % ENCD;
    const float* base = d_encs + (size_t)b * PPS * ENCD + e;
    float s = 0.f;
    #pragma unroll 4
    for (int p = 0; p < PPS; ++p) s += base[(size_t)p * ENCD];
    d_mean[idx] = s * (1.0f / (float)PPS);
}

__global__ void w1copy_kernel(const float* __restrict__ l1Wih,
                              const float* __restrict__ l1Whh) {
    int g = blockIdx.x * 256 + threadIdx.x;
    int j = g / (2048 / 4);
    int c = (g % (2048 / 4)) * 4;
    float4 v;
    if (c < 1024) v = *(const float4*)(l1Wih + (size_t)j * 4096 + 1024 + c);
    else          v = *(const float4*)(l1Whh + (size_t)j * 1024 + (c - 1024));
    *(float4*)(d_W1cat + (size_t)j * 2048 + c) = v;
}

__global__ void w2copy_kernel(const float* __restrict__ l2Wih,
                              const float* __restrict__ l2Whh) {
    int g = blockIdx.x * 256 + threadIdx.x;
    int j = g / (4096 / 4);
    int c = (g % (4096 / 4)) * 4;
    float4 v;
    if (c < 3072) v = *(const float4*)(l2Wih + (size_t)j * 3072 + c);
    else          v = *(const float4*)(l2Whh + (size_t)j * 1024 + (c - 3072));
    *(float4*)(d_W2cat + (size_t)j * 4096 + c) = v;
}

__global__ void w3copy_kernel(const float* __restrict__ daW,
                              const float* __restrict__ fbW) {
    int g = blockIdx.x * 256 + threadIdx.x;
    int j = g / (1024 / 4);
    int c = (g % (1024 / 4)) * 4;
    float4 v;
    if (j < 1024) v = *(const float4*)(daW + (size_t)j * 1024 + c);
    else          v = *(const float4*)(fbW + (size_t)(j - 1024) * 1024 + c);
    *(float4*)(d_W3cat + (size_t)j * 1024 + c) = v;
}

__global__ void bias_kernel(const float* __restrict__ l1bih,
                            const float* __restrict__ l1bhh,
                            const float* __restrict__ l2bih,
                            const float* __restrict__ l2bhh,
                            const float* __restrict__ dab,
                            const float* __restrict__ fbb) {
    int j = blockIdx.x * 256 + threadIdx.x;
    d_b1sum[j] = l1bih[j] + l1bhh[j];
    d_b2sum[j] = l2bih[j] + l2bhh[j];
    if (j < 3072) d_b3cat[j] = (j < 1024) ? dab[j] : fbb[j - 1024];
}

__global__ void embg_kernel(const float* __restrict__ emb) {
    int m = blockIdx.x;
    int tok = d_tokens[m];
    const float2* src = (const float2*)(emb + (size_t)tok * DHID);
    #pragma unroll
    for (int q = 0; q < 2; ++q) {
        int i = threadIdx.x + 256 * q;
        float2 v = src[i];
        d_embgh[(size_t)m * 512 + i] = pack_hi(v.x, v.y);
        d_embgl[(size_t)m * 512 + i] = pack_lo(v.x, v.y);
    }
}

__global__ void zero_states_kernel() {
    int idx = blockIdx.x * 256 + threadIdx.x;        // 0 .. 262143
    d_x2h[idx] = 0u; d_x2l[idx] = 0u;
    if (idx < BBS * 1024) { d_x1h[idx] = 0u; d_x1l[idx] = 0u; }
    if (idx < BBS * DHID) { d_c1[idx] = 0.f; d_c2[idx] = 0.f; }
}

__global__ void zero_pred_kernel(float* __restrict__ out) {
    size_t g = (size_t)blockIdx.x * 256 + threadIdx.x;
    ((float4*)out)[g] = make_float4(0.f, 0.f, 0.f, 0.f);
}

// ---------------------------------------------------------------------------
// Plain SIMT split-K GEMM (kept only for base1; runs once)
// ---------------------------------------------------------------------------
__global__ void __launch_bounds__(128)
gemm32sk(const float* __restrict__ A,
         const float* __restrict__ Bm,
         const float* __restrict__ bias,
         float* __restrict__ C,
         int N, int Kc, int lda, int ldb) {
    const int m0 = blockIdx.y * 32;
    __shared__ float As[16][36];
    __shared__ float Bs[16][132];
    const int tid = threadIdx.x;
    const int n0 = blockIdx.x * 128;

    const int ar = tid >> 2;
    const int ac = (tid & 3) * 4;
    const float* Aptr = A + (size_t)(m0 + ar) * lda + ac;
    const float* Bptr = Bm + (size_t)(n0 + tid) * ldb;

    const int ty = tid >> 4;
    const int tx = tid & 15;

    float acc[4][8];
    #pragma unroll
    for (int i = 0; i < 4; ++i)
        #pragma unroll
        for (int j = 0; j < 8; ++j) acc[i][j] = 0.f;

    float4 pav = *(const float4*)(Aptr);
    float4 pb[4];
    #pragma unroll
    for (int j = 0; j < 4; ++j) pb[j] = *(const float4*)(Bptr + j * 4);

    for (int k0 = 0; k0 < Kc; k0 += 16) {
        As[ac + 0][ar] = pav.x; As[ac + 1][ar] = pav.y;
        As[ac + 2][ar] = pav.z; As[ac + 3][ar] = pav.w;
        #pragma unroll
        for (int j = 0; j < 4; ++j) {
            Bs[j * 4 + 0][tid] = pb[j].x; Bs[j * 4 + 1][tid] = pb[j].y;
            Bs[j * 4 + 2][tid] = pb[j].z; Bs[j * 4 + 3][tid] = pb[j].w;
        }
        __syncthreads();
        if (k0 + 16 < Kc) {
            pav = *(const float4*)(Aptr + k0 + 16);
            #pragma unroll
            for (int j = 0; j < 4; ++j)
                pb[j] = *(const float4*)(Bptr + k0 + 16 + j * 4);
        }
        #pragma unroll
        for (int kk = 0; kk < 16; ++kk) {
            float a[4], b[8];
            *(float4*)(a)     = *(const float4*)&As[kk][ty * 4];
            *(float4*)(b)     = *(const float4*)&Bs[kk][tx * 4];
            *(float4*)(b + 4) = *(const float4*)&Bs[kk][64 + tx * 4];
            #pragma unroll
            for (int i = 0; i < 4; ++i)
                #pragma unroll
                for (int j = 0; j < 8; ++j)
                    acc[i][j] = fmaf(a[i], b[j], acc[i][j]);
        }
        __syncthreads();
    }

    float bv[8];
    #pragma unroll
    for (int j = 0; j < 8; ++j) {
        int n = (j < 4) ? (n0 + tx * 4 + j) : (n0 + 64 + tx * 4 + j - 4);
        bv[j] = bias[n];
    }

    #pragma unroll
    for (int i = 0; i < 4; ++i) {
        int m = m0 + ty * 4 + i;
        float* dst = C + (size_t)m * N + n0;
        float4 v0, v1;
        v0.x = acc[i][0] + bv[0]; v0.y = acc[i][1] + bv[1];
        v0.z = acc[i][2] + bv[2]; v0.w = acc[i][3] + bv[3];
        v1.x = acc[i][4] + bv[4]; v1.y = acc[i][5] + bv[5];
        v1.z = acc[i][6] + bv[6]; v1.w = acc[i][7] + bv[7];
        *(float4*)(dst + tx * 4)      = v0;
        *(float4*)(dst + 64 + tx * 4) = v1;
    }
}

// ---------------------------------------------------------------------------
// LSTM pointwise: 2 elems/thread, sums split-K partials, writes bf16 states.
// ---------------------------------------------------------------------------
__global__ void lstm1_kernel(int t, const float* __restrict__ econ_t) {
    int idx = blockIdx.x * 256 + threadIdx.x;        // (b,q) q over pairs
    int b = idx >> 9, q = idx & 511;
    if (t >= d_declen[b]) return;
    size_t base = (size_t)b * 4096;
    float2 g[4];
    #pragma unroll
    for (int qt = 0; qt < 4; ++qt) {
        int j = qt * 1024 + q * 2;
        float2 v = *(const float2*)(d_base1 + base + j);
        float2 e = *(const float2*)(econ_t + base + j);
        v.x += e.x; v.y += e.y;
        #pragma unroll
        for (int s = 0; s < 4; ++s) {
            float2 p = *(const float2*)(d_gp + (size_t)s * BBS * 4096 + base + j);
            v.x += p.x; v.y += p.y;
        }
        g[qt] = v;
    }
    float2 c = *(const float2*)(d_c1 + (size_t)b * 1024 + q * 2);
    float cn0 = sigf(g[1].x) * c.x + sigf(g[0].x) * tanhf(g[2].x);
    float cn1 = sigf(g[1].y) * c.y + sigf(g[0].y) * tanhf(g[2].y);
    float hn0 = sigf(g[3].x) * tanhf(cn0);
    float hn1 = sigf(g[3].y) * tanhf(cn1);
    *(float2*)(d_c1 + (size_t)b * 1024 + q * 2) = make_float2(cn0, cn1);
    unsigned int hi = pack_hi(hn0, hn1), lo = pack_lo(hn0, hn1);
    d_x1h[b * 1024 + 512 + q] = hi;  d_x1l[b * 1024 + 512 + q] = lo;
    d_x2h[b * 2048 + 1024 + q] = hi; d_x2l[b * 2048 + 1024 + q] = lo;
}

__global__ void lstm2_kernel(int t) {
    int idx = blockIdx.x * 256 + threadIdx.x;
    int b = idx >> 9, q = idx & 511;
    if (t >= d_declen[b]) return;
    size_t base = (size_t)b * 4096;
    float2 g[4];
    #pragma unroll
    for (int qt = 0; qt < 4; ++qt) {
        int j = qt * 1024 + q * 2;
        float2 v = *(const float2*)(d_b2sum + j);
        #pragma unroll
        for (int s = 0; s < 4; ++s) {
            float2 p = *(const float2*)(d_gp + (size_t)s * BBS * 4096 + base + j);
            v.x += p.x; v.y += p.y;
        }
        g[qt] = v;
    }
    float2 c = *(const float2*)(d_c2 + (size_t)b * 1024 + q * 2);
    float cn0 = sigf(g[1].x) * c.x + sigf(g[0].x) * tanhf(g[2].x);
    float cn1 = sigf(g[1].y) * c.y + sigf(g[0].y) * tanhf(g[2].y);
    float hn0 = sigf(g[3].x) * tanhf(cn0);
    float hn1 = sigf(g[3].y) * tanhf(cn1);
    *(float2*)(d_c2 + (size_t)b * 1024 + q * 2) = make_float2(cn0, cn1);
    size_t hrow = (size_t)(t * BBS + b);
    *(float2*)(d_h2all + hrow * 1024 + q * 2) = make_float2(hn0, hn1);
    unsigned int hi = pack_hi(hn0, hn1), lo = pack_lo(hn0, hn1);
    d_h2h[hrow * 512 + q] = hi;      d_h2l[hrow * 512 + q] = lo;
    d_x1h[b * 1024 + q] = hi;        d_x1l[b * 1024 + q] = lo;
    d_x2h[b * 2048 + 1536 + q] = hi; d_x2l[b * 2048 + 1536 + q] = lo;
}

// ---------------------------------------------------------------------------
// Fused attention; att2/gate = b3 + 2 split-K partial slabs; writes bf16 att.
// ---------------------------------------------------------------------------
__global__ void attn_kernel(const float* __restrict__ fullW,
                            const float* __restrict__ fullb, int t) {
    const int b = blockIdx.x;
    if (t >= d_declen[b]) return;
    __shared__ float s_a2[DHID];
    __shared__ float s_w [DHID];
    __shared__ float s_sc[PPS];
    __shared__ float s_red[256];
    const int tid = threadIdx.x;
    const int lane = tid & 31, warp = tid >> 5;
    const size_t abase = (size_t)b * 3072;

    for (int i = tid; i < DHID; i += 256) {
        s_a2[i] = d_b3cat[i] + d_ap[abase + i]
                + d_ap[(size_t)BBS * 3072 + abase + i];
        s_w[i]  = fullW[i];
    }
    __syncthreads();

    const float b0 = fullb[0];
    for (int p = warp; p < PPS; p += 8) {
        const float* row = d_att1 + ((size_t)b * PPS + p) * DHID;
        float s = 0.f;
        #pragma unroll 8
        for (int a = lane; a < DHID; a += 32)
            s += tanh_fast(row[a] + s_a2[a]) * s_w[a];
        #pragma unroll
        for (int o = 16; o > 0; o >>= 1)
            s += __shfl_down_sync(0xffffffffu, s, o);
        if (lane == 0) s_sc[p] = s + b0;
    }
    __syncthreads();

    s_red[tid] = (tid < PPS) ? s_sc[tid] : -INFINITY;
    __syncthreads();
    for (int s = 128; s > 0; s >>= 1) {
        if (tid < s) s_red[tid] = fmaxf(s_red[tid], s_red[tid + s]);
        __syncthreads();
    }
    float mx = s_red[0];
    __syncthreads();
    float e = 0.f;
    if (tid < PPS) e = __expf(s_sc[tid] - mx);
    s_red[tid] = e;
    __syncthreads();
    for (int s = 128; s > 0; s >>= 1) {
        if (tid < s) s_red[tid] += s_red[tid + s];
        __syncthreads();
    }
    float inv = 1.0f / s_red[0];
    __syncthreads();
    if (tid < PPS) s_sc[tid] = e * inv;
    __syncthreads();

    const float* encb = d_encs + (size_t)b * PPS * ENCD;
    for (int e2 = tid; e2 < ENCD / 2; e2 += 256) {
        int ei = e2 * 2;
        float a0 = 0.f, a1 = 0.f;
        const float* col = encb + ei;
        #pragma unroll 4
        for (int p = 0; p < PPS; ++p) {
            float al = s_sc[p];
            a0 = fmaf(al, col[(size_t)p * ENCD], a0);
            a1 = fmaf(al, col[(size_t)p * ENCD + 1], a1);
        }
        float gl0 = d_b3cat[1024 + ei] + d_ap[abase + 1024 + ei]
                  + d_ap[(size_t)BBS * 3072 + abase + 1024 + ei];
        float gl1 = d_b3cat[1024 + ei + 1] + d_ap[abase + 1024 + ei + 1]
                  + d_ap[(size_t)BBS * 3072 + abase + 1024 + ei + 1];
        float v0 = sigf(gl0) * a0, v1 = sigf(gl1) * a1;
        d_x2h[b * 2048 + e2] = pack_hi(v0, v1);
        d_x2l[b * 2048 + e2] = pack_lo(v0, v1);
    }
}

__global__ void rpm_kernel(const float* __restrict__ rpmW,
                           float* __restrict__ out) {
    int m = blockIdx.x * 8 + (threadIdx.x >> 5);
    if (m >= TTS * BBS) return;
    int lane = threadIdx.x & 31;
    int t = m / BBS, b = m % BBS;
    const float* h = d_h2all + (size_t)m * DHID;
    float s = 0.f;
    #pragma unroll 8
    for (int k = lane; k < DHID; k += 32) s += h[k] * rpmW[k];
    #pragma unroll
    for (int o = 16; o > 0; o >>= 1)
        s += __shfl_down_sync(0xffffffffu, s, o);
    if (lane == 0)
        out[O_PPOS + (long long)b * TTS + t] =
            (t < d_declen[b]) ? sigf(s) : 0.f;
}

// ---------------------------------------------------------------------------
// Launch
// ---------------------------------------------------------------------------
extern "C" void kernel_launch(void* const* d_in, const int* in_sizes, int n_in,
                              void* d_out, int out_size) {
    const float* enc_out = (const float*)d_in[0];
    const int*   caps    = (const int*)  d_in[1];
    const int*   caplen  = (const int*)  d_in[2];
    const float* emb     = (const float*)d_in[3];
    const float* eaW     = (const float*)d_in[4];
    const float* eab     = (const float*)d_in[5];
    const float* daW     = (const float*)d_in[6];
    const float* dab     = (const float*)d_in[7];
    const float* faW     = (const float*)d_in[8];
    const float* fab     = (const float*)d_in[9];
    const float* fbW     = (const float*)d_in[10];
    const float* fbb     = (const float*)d_in[11];
    const float* l1Wih   = (const float*)d_in[12];
    const float* l1Whh   = (const float*)d_in[13];
    const float* l1bih   = (const float*)d_in[14];
    const float* l1bhh   = (const float*)d_in[15];
    const float* l2Wih   = (const float*)d_in[16];
    const float* l2Whh   = (const float*)d_in[17];
    const float* l2bih   = (const float*)d_in[18];
    const float* l2bhh   = (const float*)d_in[19];
    const float* ramW    = (const float*)d_in[20];
    const float* ramb    = (const float*)d_in[21];
    const float* rpmW    = (const float*)d_in[22];
    float* out = (float*)d_out;

    float* p_att1;  cudaGetSymbolAddress((void**)&p_att1,  d_att1);
    float* p_econ;  cudaGetSymbolAddress((void**)&p_econ,  d_econ);
    float* p_W1c;   cudaGetSymbolAddress((void**)&p_W1c,   d_W1cat);
    float* p_W2c;   cudaGetSymbolAddress((void**)&p_W2c,   d_W2cat);
    float* p_W3c;   cudaGetSymbolAddress((void**)&p_W3c,   d_W3cat);
    float* p_b1;    cudaGetSymbolAddress((void**)&p_b1,    d_b1sum);
    float* p_base1; cudaGetSymbolAddress((void**)&p_base1, d_base1);
    float* p_gp;    cudaGetSymbolAddress((void**)&p_gp,    d_gp);
    float* p_ap;    cudaGetSymbolAddress((void**)&p_ap,    d_ap);
    float* p_mean;  cudaGetSymbolAddress((void**)&p_mean,  d_mean);
    unsigned int *p_ench, *p_encl, *p_eaWh, *p_eaWl, *p_W1eh, *p_W1el;
    unsigned int *p_embgh, *p_embgl, *p_ramWh, *p_ramWl, *p_h2h, *p_h2l;
    unsigned int *p_W1h, *p_W1l, *p_W2h, *p_W2l, *p_W3h, *p_W3l;
    unsigned int *p_x1h, *p_x1l, *p_x2h, *p_x2l;
    cudaGetSymbolAddress((void**)&p_ench,  d_ench);
    cudaGetSymbolAddress((void**)&p_encl,  d_encl);
    cudaGetSymbolAddress((void**)&p_eaWh,  d_eaWh);
    cudaGetSymbolAddress((void**)&p_eaWl,  d_eaWl);
    cudaGetSymbolAddress((void**)&p_W1eh,  d_W1eh);
    cudaGetSymbolAddress((void**)&p_W1el,  d_W1el);
    cudaGetSymbolAddress((void**)&p_embgh, d_embgh);
    cudaGetSymbolAddress((void**)&p_embgl, d_embgl);
    cudaGetSymbolAddress((void**)&p_ramWh, d_ramWh);
    cudaGetSymbolAddress((void**)&p_ramWl, d_ramWl);
    cudaGetSymbolAddress((void**)&p_h2h,   d_h2h);
    cudaGetSymbolAddress((void**)&p_h2l,   d_h2l);
    cudaGetSymbolAddress((void**)&p_W1h,   d_W1h);
    cudaGetSymbolAddress((void**)&p_W1l,   d_W1l);
    cudaGetSymbolAddress((void**)&p_W2h,   d_W2h);
    cudaGetSymbolAddress((void**)&p_W2l,   d_W2l);
    cudaGetSymbolAddress((void**)&p_W3h,   d_W3h);
    cudaGetSymbolAddress((void**)&p_W3l,   d_W3l);
    cudaGetSymbolAddress((void**)&p_x1h,   d_x1h);
    cudaGetSymbolAddress((void**)&p_x1l,   d_x1l);
    cudaGetSymbolAddress((void**)&p_x2h,   d_x2h);
    cudaGetSymbolAddress((void**)&p_x2l,   d_x2l);

    cudaFuncSetAttribute(gemm_wb<0>, cudaFuncAttributeMaxDynamicSharedMemorySize,
                         WB_SMEM);
    cudaFuncSetAttribute(gemm_wb<1>, cudaFuncAttributeMaxDynamicSharedMemorySize,
                         WB_SMEM);
    cudaFuncSetAttribute(gemm_wb<2>, cudaFuncAttributeMaxDynamicSharedMemorySize,
                         WB_SMEM);
    cudaFuncSetAttribute(gemm_ws, cudaFuncAttributeMaxDynamicSharedMemorySize,
                         WS_SMEM);

    // 1-3: sort, gather(+bf16 split), convert eaW
    setup_kernel<<<1, BBS>>>(caplen, caps, out);
    gather_enc_kernel<<<50176, 256>>>(enc_out);
    conv_kernel<<<(1024 * 1024) / 256, 256>>>(eaW, p_eaWh, p_eaWl, 1024, 2048);

    // 4: att1 (bf16x3 HMMA, 2 blk/SM): 25088 x 1024, K=2048  <- profiled slot
    gemm_wb<1><<<dim3(1024 / 128, (BBS * PPS) / 128), 256, WB_SMEM>>>(
        p_ench, p_encl, p_eaWh, p_eaWl, eab, p_att1, 2048, 1024, 1024, 1024);

    // 5+: mean, zero pred, biases, weight concats + conversions
    mean_kernel<<<(BBS * ENCD) / 256, 256>>>();
    zero_pred_kernel<<<84000, 256>>>(out + O_PRED);
    bias_kernel<<<16, 256>>>(l1bih, l1bhh, l2bih, l2bhh, dab, fbb);
    w1copy_kernel<<<8192, 256>>>(l1Wih, l1Whh);
    w2copy_kernel<<<16384, 256>>>(l2Wih, l2Whh);
    w3copy_kernel<<<3072, 256>>>(daW, fbW);
    conv_kernel<<<(4096 * 512) / 256, 256>>>(l1Wih, p_W1eh, p_W1el, 512, 4096);
    conv_kernel<<<(4096 * 1024) / 256, 256>>>(p_W1c, p_W1h, p_W1l, 1024, 2048);
    conv_kernel<<<(4096 * 2048) / 256, 256>>>(p_W2c, p_W2h, p_W2l, 2048, 4096);
    conv_kernel<<<(3072 * 512) / 256, 256>>>(p_W3c, p_W3h, p_W3l, 512, 1024);

    // embeddings (bf16 split)
    embg_kernel<<<TTS * BBS, 256>>>(emb);

    // econ (bf16x3 HMMA): 2688 x 4096, K=1024
    gemm_wb<0><<<dim3(4096 / 128, (TTS * BBS) / 128), 256, WB_SMEM>>>(
        p_embgh, p_embgl, p_W1eh, p_W1el, nullptr, p_econ, 1024, 512, 512, 4096);

    // ramW conversion (for preds later)
    conv_kernel<<<(VOC * 512) / 256, 256>>>(ramW, p_ramWh, p_ramWl, 512, 1024);

    // base1 = mean_enc @ Wih[:,2048:].T + (bih+bhh)
    gemm32sk<<<dim3(4096 / 128, 4), 128>>>(
        p_mean, l1Wih + 2048, p_b1, p_base1, 4096, 2048, 2048, 4096);

    zero_states_kernel<<<(BBS * 2048) / 256, 256>>>();

    // sequential decode: HMMA split-K partials -> pointwise epilogues
    for (int t = 0; t < TTS; ++t) {
        // gates1: x1[128x2048] @ W1cat.T -> 4 slabs (Kc=512)
        gemm_ws<<<dim3(32, 4, 4), 256, WS_SMEM>>>(
            p_x1h, p_x1l, p_W1h, p_W1l, p_gp, 4096, 512, 1024, 1024, t);

        lstm1_kernel<<<(BBS * DHID / 2) / 256, 256>>>(
            t, p_econ + (size_t)t * BBS * 4096);

        // att2/gate: h1n[128x1024] @ [dec_att;f_beta].T -> 2 slabs (Kc=512)
        gemm_ws<<<dim3(24, 4, 2), 256, WS_SMEM>>>(
            p_x2h + 1024, p_x2l + 1024, p_W3h, p_W3l, p_ap,
            3072, 512, 2048, 512, t);

        attn_kernel<<<BBS, 256>>>(faW, fab, t);

        // gates2: x2[128x4096] @ W2cat.T -> 4 slabs (Kc=1024)
        gemm_ws<<<dim3(32, 4, 4), 256, WS_SMEM>>>(
            p_x2h, p_x2l, p_W2h, p_W2l, p_gp, 4096, 1024, 2048, 2048, t);

        lstm2_kernel<<<(BBS * DHID / 2) / 256, 256>>>(t);
    }

    // preds (bf16x3 HMMA, compact gather/scatter); h2 hi/lo written by lstm2
    gemm_wb<2><<<dim3(VOC / 128, (TTS * BBS + 127) / 128), 256, WB_SMEM>>>(
        p_h2h, p_h2l, p_ramWh, p_ramWl, ramb, out + O_PRED, 1024, 512, 512, VOC);

    // predicted_pos
    rpm_kernel<<<(TTS * BBS + 7) / 8, 256>>>(rpmW, out);
}

// round 15
// speedup vs baseline: 1.8003x; 1.0205x over previous
#include <cuda_runtime.h>
#include <cuda_bf16.h>
#include <mma.h>
#include <math.h>
using namespace nvcuda;

// ---------------------------------------------------------------------------
// Problem constants
// ---------------------------------------------------------------------------
#define TTS   21
#define CAPL  22
#define BBS   128
#define PPS   196
#define ENCD  2048
#define DHID  1024
#define VOC   32000

static constexpr long long O_PRED = 0;
static constexpr long long O_CAPS = (long long)BBS * TTS * VOC;
static constexpr long long O_DECL = O_CAPS + (long long)BBS * CAPL;
static constexpr long long O_SORT = O_DECL + BBS;
static constexpr long long O_RPOS = O_SORT + BBS;
static constexpr long long O_PPOS = O_RPOS + (long long)BBS * TTS;

// ---------------------------------------------------------------------------
// Static device scratch
// ---------------------------------------------------------------------------
__device__ float d_encs [(size_t)BBS * PPS * ENCD];
__device__ float d_att1 [(size_t)BBS * PPS * DHID];
__device__ float d_econ [(size_t)TTS * BBS * 4 * DHID];
__device__ float d_W1cat[4096 * 2048];
__device__ float d_W2cat[(size_t)4096 * 4096];
__device__ float d_W3cat[3072 * 1024];
__device__ float d_b1sum[4096];
__device__ float d_b2sum[4096];
__device__ float d_b3cat[3072];
__device__ float d_base1[BBS * 4096];
__device__ float d_gp   [(size_t)8 * BBS * 4096];   // 8 split-K slabs
__device__ float d_ap   [(size_t)4 * BBS * 3072];   // 4 split-K slabs
__device__ float d_c1   [BBS * DHID];
__device__ float d_c2   [BBS * DHID];
__device__ float d_mean [BBS * ENCD];
__device__ float d_h2all[(size_t)TTS * BBS * DHID];
__device__ int   d_sort  [BBS];
__device__ int   d_declen[BBS];
__device__ int   d_tokens[TTS * BBS];
__device__ int   d_nact  [TTS];
__device__ int   d_rowidx[TTS * BBS];
__device__ int   d_outrow[TTS * BBS];
__device__ int   d_cnt;

// bf16 hi/lo buffers (packed bf16x2 in uint32, row-major)
__device__ unsigned int d_ench [(size_t)BBS * PPS * (ENCD / 2)];
__device__ unsigned int d_encl [(size_t)BBS * PPS * (ENCD / 2)];
__device__ unsigned int d_eaWh [1024 * (ENCD / 2)];
__device__ unsigned int d_eaWl [1024 * (ENCD / 2)];
__device__ unsigned int d_W1eh [4096 * (DHID / 2)];
__device__ unsigned int d_W1el [4096 * (DHID / 2)];
__device__ unsigned int d_embgh[TTS * BBS * (DHID / 2)];
__device__ unsigned int d_embgl[TTS * BBS * (DHID / 2)];
__device__ unsigned int d_ramWh[(size_t)VOC * (DHID / 2)];
__device__ unsigned int d_ramWl[(size_t)VOC * (DHID / 2)];
__device__ unsigned int d_h2h  [TTS * BBS * (DHID / 2)];
__device__ unsigned int d_h2l  [TTS * BBS * (DHID / 2)];
// loop-GEMM operands
__device__ unsigned int d_W1h  [4096 * 1024];
__device__ unsigned int d_W1l  [4096 * 1024];
__device__ unsigned int d_W2h  [(size_t)4096 * 2048];
__device__ unsigned int d_W2l  [(size_t)4096 * 2048];
__device__ unsigned int d_W3h  [3072 * 512];
__device__ unsigned int d_W3l  [3072 * 512];
__device__ unsigned int d_x1h  [BBS * 1024];
__device__ unsigned int d_x1l  [BBS * 1024];
__device__ unsigned int d_x2h  [BBS * 2048];
__device__ unsigned int d_x2l  [BBS * 2048];

// ---------------------------------------------------------------------------
// Helpers
// ---------------------------------------------------------------------------
__device__ __forceinline__ float sigf(float x) {
    return 1.0f / (1.0f + __expf(-x));
}
__device__ __forceinline__ float tanh_fast(float x) {
    return 1.0f - 2.0f / (__expf(2.0f * x) + 1.0f);
}
__device__ __forceinline__ unsigned int pack_hi(float a, float b) {
    __nv_bfloat162 p = __floats2bfloat162_rn(a, b);
    return *reinterpret_cast<unsigned int*>(&p);
}
__device__ __forceinline__ unsigned int pack_lo(float a, float b) {
    float ah = __bfloat162float(__float2bfloat16_rn(a));
    float bh = __bfloat162float(__float2bfloat16_rn(b));
    __nv_bfloat162 p = __floats2bfloat162_rn(a - ah, b - bh);
    return *reinterpret_cast<unsigned int*>(&p);
}
__device__ __forceinline__ unsigned int smem_u32(const void* p) {
    unsigned int a;
    asm("{ .reg .u64 t; cvta.to.shared.u64 t, %1; cvt.u32.u64 %0, t; }"
        : "=r"(a) : "l"(p));
    return a;
}
__device__ __forceinline__ void cp16(unsigned int dst, const void* src) {
    asm volatile("cp.async.cg.shared.global [%0], [%1], 16;"
                 :: "r"(dst), "l"(__cvta_generic_to_global(src)) : "memory");
}

// ---------------------------------------------------------------------------
// Big bf16x3 wmma GEMM (128x128 tile, 2 blocks/SM). Unchanged from R14.
// MODE 0: plain  MODE 1: +bias  MODE 2: +bias + gather/scatter (preds)
// ---------------------------------------------------------------------------
static constexpr int WB_SMEM = 81920;

template<int MODE>
__global__ void __launch_bounds__(256, 2)
gemm_wb(const unsigned int* __restrict__ Ah, const unsigned int* __restrict__ Al,
        const unsigned int* __restrict__ Bh, const unsigned int* __restrict__ Bl,
        const float* __restrict__ bias, float* __restrict__ C,
        int K, int lda32, int ldb32, int ldc) {
    extern __shared__ char smem[];
    const int tid = threadIdx.x;
    const int warp = tid >> 5;
    const int m0 = blockIdx.y * 128, n0 = blockIdx.x * 128;
    int count = 0;
    if (MODE == 2) {
        count = d_cnt;
        if (m0 >= count) return;
    }

    const int lr = tid >> 1;
    const int lc = (tid & 1) * 8;
    int arow = m0 + lr;
    if (MODE == 2) arow = (arow < count) ? d_rowidx[arow] : d_rowidx[0];
    const unsigned int* gA0 = Ah + (size_t)arow * lda32 + lc;
    const unsigned int* gA1 = Al + (size_t)arow * lda32 + lc;
    const unsigned int* gB0 = Bh + (size_t)(n0 + lr) * ldb32 + lc;
    const unsigned int* gB1 = Bl + (size_t)(n0 + lr) * ldb32 + lc;

    const unsigned int sbase = smem_u32(smem);
    const unsigned int drow = (unsigned)(lr * 80 + lc * 4);

    const int wm = (warp >> 1) * 32;
    const int wn = (warp & 1) * 64;

    wmma::fragment<wmma::accumulator, 16, 16, 16, float> acc[2][4];
    #pragma unroll
    for (int i = 0; i < 2; ++i)
        #pragma unroll
        for (int j = 0; j < 4; ++j)
            wmma::fill_fragment(acc[i][j], 0.0f);

    const int nch = K >> 5;
    {
        unsigned int d0 = sbase + drow;
        cp16(d0,             gA0); cp16(d0 + 16,         gA0 + 4);
        cp16(d0 + 10240,     gA1); cp16(d0 + 10240 + 16, gA1 + 4);
        cp16(d0 + 20480,     gB0); cp16(d0 + 20480 + 16, gB0 + 4);
        cp16(d0 + 30720,     gB1); cp16(d0 + 30720 + 16, gB1 + 4);
        asm volatile("cp.async.commit_group;" ::: "memory");
    }

    for (int ch = 0; ch < nch; ++ch) {
        const int buf = ch & 1;
        if (ch + 1 < nch) {
            const int kw = (ch + 1) * 16;
            unsigned int d0 = sbase + (buf ^ 1) * 40960 + drow;
            cp16(d0,             gA0 + kw); cp16(d0 + 16,         gA0 + kw + 4);
            cp16(d0 + 10240,     gA1 + kw); cp16(d0 + 10240 + 16, gA1 + kw + 4);
            cp16(d0 + 20480,     gB0 + kw); cp16(d0 + 20480 + 16, gB0 + kw + 4);
            cp16(d0 + 30720,     gB1 + kw); cp16(d0 + 30720 + 16, gB1 + kw + 4);
            asm volatile("cp.async.commit_group;" ::: "memory");
            asm volatile("cp.async.wait_group 1;" ::: "memory");
        } else {
            asm volatile("cp.async.wait_group 0;" ::: "memory");
        }
        __syncthreads();

        const __nv_bfloat16* pAh = (const __nv_bfloat16*)(smem + buf * 40960);
        const __nv_bfloat16* pAl = pAh + 5120;
        const __nv_bfloat16* pBh = pAh + 10240;
        const __nv_bfloat16* pBl = pAh + 15360;

        #pragma unroll
        for (int kk = 0; kk < 32; kk += 16) {
            wmma::fragment<wmma::matrix_a, 16, 16, 16, __nv_bfloat16,
                           wmma::row_major> ah[2], al[2];
            #pragma unroll
            for (int i = 0; i < 2; ++i) {
                wmma::load_matrix_sync(ah[i], pAh + (wm + i * 16) * 40 + kk, 40);
                wmma::load_matrix_sync(al[i], pAl + (wm + i * 16) * 40 + kk, 40);
            }
            #pragma unroll
            for (int j = 0; j < 4; ++j) {
                wmma::fragment<wmma::matrix_b, 16, 16, 16, __nv_bfloat16,
                               wmma::col_major> bh, bl;
                wmma::load_matrix_sync(bh, pBh + (wn + j * 16) * 40 + kk, 40);
                wmma::load_matrix_sync(bl, pBl + (wn + j * 16) * 40 + kk, 40);
                #pragma unroll
                for (int i = 0; i < 2; ++i) {
                    wmma::mma_sync(acc[i][j], ah[i], bh, acc[i][j]);
                    wmma::mma_sync(acc[i][j], al[i], bh, acc[i][j]);
                    wmma::mma_sync(acc[i][j], ah[i], bl, acc[i][j]);
                }
            }
        }
        __syncthreads();
    }

    float* outs = (float*)smem;
    #pragma unroll
    for (int i = 0; i < 2; ++i)
        #pragma unroll
        for (int j = 0; j < 4; ++j)
            wmma::store_matrix_sync(outs + (wm + i * 16) * 128 + wn + j * 16,
                                    acc[i][j], 128, wmma::mem_row_major);
    __syncthreads();

    for (int i = tid; i < 128 * 128; i += 256) {
        int m = i >> 7, n = i & 127;
        float v = outs[i];
        int gm = m0 + m, gn = n0 + n;
        if (MODE >= 1) v += bias[gn];
        if (MODE == 2) {
            if (gm >= count) continue;
            C[(long long)d_outrow[gm] * ldc + gn] = v;
        } else {
            C[(size_t)gm * ldc + gn] = v;
        }
    }
}

// ---------------------------------------------------------------------------
// Skinny bf16x3 wmma split-K GEMM v2: 32x128 tile, K-chunk 64 (half the
// syncs of R14), double-buffered cp.async, DIRECT fragment stores to the
// global partial slab (no smem epilogue). 8 warps, warp tile 16x32.
// smem: 2 stages x (A 2x4608 + B 2x18432) = 92160 B.
// ---------------------------------------------------------------------------
static constexpr int WS_SMEM = 92160;

__global__ void __launch_bounds__(256, 2)
gemm_ws(const unsigned int* __restrict__ Ah, const unsigned int* __restrict__ Al,
        const unsigned int* __restrict__ Bh, const unsigned int* __restrict__ Bl,
        float* __restrict__ C, int N, int Kc, int lda32, int ldb32, int t) {
    const int m0 = blockIdx.y * 32;
    if (m0 >= d_nact[t]) return;
    extern __shared__ char smem[];
    const int tid = threadIdx.x;
    const int warp = tid >> 5;
    const int n0 = blockIdx.x * 128;
    const int ko32 = blockIdx.z * (Kc >> 1);          // u32 offset of slab
    float* Cs = C + (size_t)blockIdx.z * BBS * N;

    // A loaders: 32 rows x 32 u32; 1 cp16 per thread per operand
    const int ra = tid >> 3, ca = (tid & 7) * 16;      // byte col 0..112
    const unsigned int* gAh = Ah + (size_t)(m0 + ra) * lda32 + ko32 + (ca >> 2);
    const unsigned int* gAl = Al + (size_t)(m0 + ra) * lda32 + ko32 + (ca >> 2);
    const unsigned int aoff = (unsigned)(ra * 144 + ca);
    // B loaders: 128 rows x 32 u32; 2 threads/row, 2 cp16 each
    const int rb = tid >> 1, cb = (tid & 1) * 64;      // byte col 0 or 64
    const unsigned int* gBh = Bh + (size_t)(n0 + rb) * ldb32 + ko32 + (cb >> 2);
    const unsigned int* gBl = Bl + (size_t)(n0 + rb) * ldb32 + ko32 + (cb >> 2);
    const unsigned int boff = (unsigned)(rb * 144 + cb);

    const unsigned int sbase = smem_u32(smem);
    const int wm = (warp >> 2) * 16;
    const int wn = (warp & 3) * 32;

    wmma::fragment<wmma::accumulator, 16, 16, 16, float> acc[2];
    wmma::fill_fragment(acc[0], 0.0f);
    wmma::fill_fragment(acc[1], 0.0f);

    const int nch = Kc >> 6;                           // chunks of 64 bf16
    {
        unsigned int s = sbase;
        cp16(s + aoff,                  gAh);
        cp16(s + 4608 + aoff,           gAl);
        cp16(s + 9216 + boff,           gBh);
        cp16(s + 9216 + boff + 16,      gBh + 4);
        cp16(s + 9216 + boff + 32,      gBh + 8);
        cp16(s + 9216 + boff + 48,      gBh + 12);
        cp16(s + 27648 + boff,          gBl);
        cp16(s + 27648 + boff + 16,     gBl + 4);
        cp16(s + 27648 + boff + 32,     gBl + 8);
        cp16(s + 27648 + boff + 48,     gBl + 12);
        asm volatile("cp.async.commit_group;" ::: "memory");
    }

    for (int ch = 0; ch < nch; ++ch) {
        const int buf = ch & 1;
        if (ch + 1 < nch) {
            const int kw = (ch + 1) * 32;              // u32 per chunk
            unsigned int s = sbase + (buf ^ 1) * 46080;
            cp16(s + aoff,              gAh + kw);
            cp16(s + 4608 + aoff,       gAl + kw);
            cp16(s + 9216 + boff,       gBh + kw);
            cp16(s + 9216 + boff + 16,  gBh + kw + 4);
            cp16(s + 9216 + boff + 32,  gBh + kw + 8);
            cp16(s + 9216 + boff + 48,  gBh + kw + 12);
            cp16(s + 27648 + boff,      gBl + kw);
            cp16(s + 27648 + boff + 16, gBl + kw + 4);
            cp16(s + 27648 + boff + 32, gBl + kw + 8);
            cp16(s + 27648 + boff + 48, gBl + kw + 12);
            asm volatile("cp.async.commit_group;" ::: "memory");
            asm volatile("cp.async.wait_group 1;" ::: "memory");
        } else {
            asm volatile("cp.async.wait_group 0;" ::: "memory");
        }
        __syncthreads();

        const __nv_bfloat16* pAh = (const __nv_bfloat16*)(smem + buf * 46080);
        const __nv_bfloat16* pAl = pAh + 2304;
        const __nv_bfloat16* pBh = pAh + 4608;
        const __nv_bfloat16* pBl = pAh + 13824;

        #pragma unroll
        for (int kk = 0; kk < 64; kk += 16) {
            wmma::fragment<wmma::matrix_a, 16, 16, 16, __nv_bfloat16,
                           wmma::row_major> ah, al;
            wmma::load_matrix_sync(ah, pAh + wm * 72 + kk, 72);
            wmma::load_matrix_sync(al, pAl + wm * 72 + kk, 72);
            #pragma unroll
            for (int j = 0; j < 2; ++j) {
                wmma::fragment<wmma::matrix_b, 16, 16, 16, __nv_bfloat16,
                               wmma::col_major> bh, bl;
                wmma::load_matrix_sync(bh, pBh + (wn + j * 16) * 72 + kk, 72);
                wmma::load_matrix_sync(bl, pBl + (wn + j * 16) * 72 + kk, 72);
                wmma::mma_sync(acc[j], ah, bh, acc[j]);
                wmma::mma_sync(acc[j], al, bh, acc[j]);
                wmma::mma_sync(acc[j], ah, bl, acc[j]);
            }
        }
        __syncthreads();
    }

    // direct fragment stores to the fp32 partial slab
    #pragma unroll
    for (int j = 0; j < 2; ++j)
        wmma::store_matrix_sync(Cs + (size_t)(m0 + wm) * N + n0 + wn + j * 16,
                                acc[j], N, wmma::mem_row_major);
}

// ---------------------------------------------------------------------------
// fp32 -> bf16 hi/lo conversion (2 elems per thread)
// ---------------------------------------------------------------------------
__global__ void conv_kernel(const float* __restrict__ src,
                            unsigned int* __restrict__ dh,
                            unsigned int* __restrict__ dl,
                            int cols2, int src_ld) {
    size_t idx = (size_t)blockIdx.x * 256 + threadIdx.x;
    size_t row = idx / cols2;
    int cp = (int)(idx - row * cols2);
    const float* s = src + row * (size_t)src_ld + (size_t)cp * 2;
    float a = s[0], b = s[1];
    dh[row * cols2 + cp] = pack_hi(a, b);
    dl[row * cols2 + cp] = pack_lo(a, b);
}

// ---------------------------------------------------------------------------
// Setup / gather / small kernels (unchanged)
// ---------------------------------------------------------------------------
__global__ void setup_kernel(const int* __restrict__ caplen,
                             const int* __restrict__ caps,
                             float* __restrict__ out) {
    __shared__ int lens_s[BBS];
    __shared__ int sort_s[BBS];
    __shared__ int dl_s[BBS];
    int i = threadIdx.x;
    int li = caplen[i];
    lens_s[i] = li;
    __syncthreads();
    int rank = 0;
    for (int j = 0; j < BBS; ++j) {
        int lj = lens_s[j];
        if (lj > li || (lj == li && j < i)) rank++;
    }
    sort_s[rank] = i;
    __syncthreads();
    int src = sort_s[i];
    d_sort[i] = src;
    int dl = lens_s[src] - 1;
    d_declen[i] = dl;
    dl_s[i] = dl;
    out[O_DECL + i] = (float)dl;
    out[O_SORT + i] = (float)src;
    for (int t = 0; t < CAPL; ++t) {
        int tok = caps[src * CAPL + t];
        out[O_CAPS + (long long)i * CAPL + t] = (float)tok;
        if (t < TTS) d_tokens[t * BBS + i] = tok;
    }
    float dlf = (float)dl;
    for (int s = 0; s < TTS; ++s)
        out[O_RPOS + (long long)i * TTS + s] =
            (s < dl) ? ((float)(s + 1) / dlf) : 0.0f;
    __syncthreads();
    if (i == 0) {
        int c = 0;
        for (int t = 0; t < TTS; ++t) {
            int n = 0;
            while (n < BBS && dl_s[n] > t) n++;
            d_nact[t] = n;
            for (int b = 0; b < n; ++b) {
                d_rowidx[c] = t * BBS + b;
                d_outrow[c] = b * TTS + t;
                c++;
            }
        }
        d_cnt = c;
    }
}

__global__ void gather_enc_kernel(const float* __restrict__ enc) {
    int g = blockIdx.x * 256 + threadIdx.x;
    int r = g >> 9, w = g & 511;
    int b = r / PPS, p = r % PPS;
    int srow = d_sort[b] * PPS + p;
    float4 v = ((const float4*)enc)[(size_t)srow * 512 + w];
    ((float4*)d_encs)[(size_t)r * 512 + w] = v;
    size_t o = (size_t)r * 1024 + (size_t)w * 2;
    d_ench[o]     = pack_hi(v.x, v.y);
    d_ench[o + 1] = pack_hi(v.z, v.w);
    d_encl[o]     = pack_lo(v.x, v.y);
    d_encl[o + 1] = pack_lo(v.z, v.w);
}

__global__ void mean_kernel() {
    int idx = blockIdx.x * 256 + threadIdx.x;
    int b = idx / ENCD, e = idx % ENCD;
    const float* base = d_encs + (size_t)b * PPS * ENCD + e;
    float s = 0.f;
    #pragma unroll 4
    for (int p = 0; p < PPS; ++p) s += base[(size_t)p * ENCD];
    d_mean[idx] = s * (1.0f / (float)PPS);
}

__global__ void w1copy_kernel(const float* __restrict__ l1Wih,
                              const float* __restrict__ l1Whh) {
    int g = blockIdx.x * 256 + threadIdx.x;
    int j = g / (2048 / 4);
    int c = (g % (2048 / 4)) * 4;
    float4 v;
    if (c < 1024) v = *(const float4*)(l1Wih + (size_t)j * 4096 + 1024 + c);
    else          v = *(const float4*)(l1Whh + (size_t)j * 1024 + (c - 1024));
    *(float4*)(d_W1cat + (size_t)j * 2048 + c) = v;
}

__global__ void w2copy_kernel(const float* __restrict__ l2Wih,
                              const float* __restrict__ l2Whh) {
    int g = blockIdx.x * 256 + threadIdx.x;
    int j = g / (4096 / 4);
    int c = (g % (4096 / 4)) * 4;
    float4 v;
    if (c < 3072) v = *(const float4*)(l2Wih + (size_t)j * 3072 + c);
    else          v = *(const float4*)(l2Whh + (size_t)j * 1024 + (c - 3072));
    *(float4*)(d_W2cat + (size_t)j * 4096 + c) = v;
}

__global__ void w3copy_kernel(const float* __restrict__ daW,
                              const float* __restrict__ fbW) {
    int g = blockIdx.x * 256 + threadIdx.x;
    int j = g / (1024 / 4);
    int c = (g % (1024 / 4)) * 4;
    float4 v;
    if (j < 1024) v = *(const float4*)(daW + (size_t)j * 1024 + c);
    else          v = *(const float4*)(fbW + (size_t)(j - 1024) * 1024 + c);
    *(float4*)(d_W3cat + (size_t)j * 1024 + c) = v;
}

__global__ void bias_kernel(const float* __restrict__ l1bih,
                            const float* __restrict__ l1bhh,
                            const float* __restrict__ l2bih,
                            const float* __restrict__ l2bhh,
                            const float* __restrict__ dab,
                            const float* __restrict__ fbb) {
    int j = blockIdx.x * 256 + threadIdx.x;
    d_b1sum[j] = l1bih[j] + l1bhh[j];
    d_b2sum[j] = l2bih[j] + l2bhh[j];
    if (j < 3072) d_b3cat[j] = (j < 1024) ? dab[j] : fbb[j - 1024];
}

__global__ void embg_kernel(const float* __restrict__ emb) {
    int m = blockIdx.x;
    int tok = d_tokens[m];
    const float2* src = (const float2*)(emb + (size_t)tok * DHID);
    #pragma unroll
    for (int q = 0; q < 2; ++q) {
        int i = threadIdx.x + 256 * q;
        float2 v = src[i];
        d_embgh[(size_t)m * 512 + i] = pack_hi(v.x, v.y);
        d_embgl[(size_t)m * 512 + i] = pack_lo(v.x, v.y);
    }
}

__global__ void zero_states_kernel() {
    int idx = blockIdx.x * 256 + threadIdx.x;
    d_x2h[idx] = 0u; d_x2l[idx] = 0u;
    if (idx < BBS * 1024) { d_x1h[idx] = 0u; d_x1l[idx] = 0u; }
    if (idx < BBS * DHID) { d_c1[idx] = 0.f; d_c2[idx] = 0.f; }
}

__global__ void zero_pred_kernel(float* __restrict__ out) {
    size_t g = (size_t)blockIdx.x * 256 + threadIdx.x;
    ((float4*)out)[g] = make_float4(0.f, 0.f, 0.f, 0.f);
}

// ---------------------------------------------------------------------------
// Plain SIMT split-K GEMM (base1 only; runs once)
// ---------------------------------------------------------------------------
__global__ void __launch_bounds__(128)
gemm32sk(const float* __restrict__ A,
         const float* __restrict__ Bm,
         const float* __restrict__ bias,
         float* __restrict__ C,
         int N, int Kc, int lda, int ldb) {
    const int m0 = blockIdx.y * 32;
    __shared__ float As[16][36];
    __shared__ float Bs[16][132];
    const int tid = threadIdx.x;
    const int n0 = blockIdx.x * 128;

    const int ar = tid >> 2;
    const int ac = (tid & 3) * 4;
    const float* Aptr = A + (size_t)(m0 + ar) * lda + ac;
    const float* Bptr = Bm + (size_t)(n0 + tid) * ldb;

    const int ty = tid >> 4;
    const int tx = tid & 15;

    float acc[4][8];
    #pragma unroll
    for (int i = 0; i < 4; ++i)
        #pragma unroll
        for (int j = 0; j < 8; ++j) acc[i][j] = 0.f;

    float4 pav = *(const float4*)(Aptr);
    float4 pb[4];
    #pragma unroll
    for (int j = 0; j < 4; ++j) pb[j] = *(const float4*)(Bptr + j * 4);

    for (int k0 = 0; k0 < Kc; k0 += 16) {
        As[ac + 0][ar] = pav.x; As[ac + 1][ar] = pav.y;
        As[ac + 2][ar] = pav.z; As[ac + 3][ar] = pav.w;
        #pragma unroll
        for (int j = 0; j < 4; ++j) {
            Bs[j * 4 + 0][tid] = pb[j].x; Bs[j * 4 + 1][tid] = pb[j].y;
            Bs[j * 4 + 2][tid] = pb[j].z; Bs[j * 4 + 3][tid] = pb[j].w;
        }
        __syncthreads();
        if (k0 + 16 < Kc) {
            pav = *(const float4*)(Aptr + k0 + 16);
            #pragma unroll
            for (int j = 0; j < 4; ++j)
                pb[j] = *(const float4*)(Bptr + k0 + 16 + j * 4);
        }
        #pragma unroll
        for (int kk = 0; kk < 16; ++kk) {
            float a[4], b[8];
            *(float4*)(a)     = *(const float4*)&As[kk][ty * 4];
            *(float4*)(b)     = *(const float4*)&Bs[kk][tx * 4];
            *(float4*)(b + 4) = *(const float4*)&Bs[kk][64 + tx * 4];
            #pragma unroll
            for (int i = 0; i < 4; ++i)
                #pragma unroll
                for (int j = 0; j < 8; ++j)
                    acc[i][j] = fmaf(a[i], b[j], acc[i][j]);
        }
        __syncthreads();
    }

    float bv[8];
    #pragma unroll
    for (int j = 0; j < 8; ++j) {
        int n = (j < 4) ? (n0 + tx * 4 + j) : (n0 + 64 + tx * 4 + j - 4);
        bv[j] = bias[n];
    }

    #pragma unroll
    for (int i = 0; i < 4; ++i) {
        int m = m0 + ty * 4 + i;
        float* dst = C + (size_t)m * N + n0;
        float4 v0, v1;
        v0.x = acc[i][0] + bv[0]; v0.y = acc[i][1] + bv[1];
        v0.z = acc[i][2] + bv[2]; v0.w = acc[i][3] + bv[3];
        v1.x = acc[i][4] + bv[4]; v1.y = acc[i][5] + bv[5];
        v1.z = acc[i][6] + bv[6]; v1.w = acc[i][7] + bv[7];
        *(float4*)(dst + tx * 4)      = v0;
        *(float4*)(dst + 64 + tx * 4) = v1;
    }
}

// ---------------------------------------------------------------------------
// LSTM pointwise: sums 8 split-K slabs, writes bf16 states.
// ---------------------------------------------------------------------------
__global__ void lstm1_kernel(int t, const float* __restrict__ econ_t) {
    int idx = blockIdx.x * 256 + threadIdx.x;
    int b = idx >> 9, q = idx & 511;
    if (t >= d_declen[b]) return;
    size_t base = (size_t)b * 4096;
    float2 g[4];
    #pragma unroll
    for (int qt = 0; qt < 4; ++qt) {
        int j = qt * 1024 + q * 2;
        float2 v = *(const float2*)(d_base1 + base + j);
        float2 e = *(const float2*)(econ_t + base + j);
        v.x += e.x; v.y += e.y;
        #pragma unroll
        for (int s = 0; s < 8; ++s) {
            float2 p = *(const float2*)(d_gp + (size_t)s * BBS * 4096 + base + j);
            v.x += p.x; v.y += p.y;
        }
        g[qt] = v;
    }
    float2 c = *(const float2*)(d_c1 + (size_t)b * 1024 + q * 2);
    float cn0 = sigf(g[1].x) * c.x + sigf(g[0].x) * tanhf(g[2].x);
    float cn1 = sigf(g[1].y) * c.y + sigf(g[0].y) * tanhf(g[2].y);
    float hn0 = sigf(g[3].x) * tanhf(cn0);
    float hn1 = sigf(g[3].y) * tanhf(cn1);
    *(float2*)(d_c1 + (size_t)b * 1024 + q * 2) = make_float2(cn0, cn1);
    unsigned int hi = pack_hi(hn0, hn1), lo = pack_lo(hn0, hn1);
    d_x1h[b * 1024 + 512 + q] = hi;  d_x1l[b * 1024 + 512 + q] = lo;
    d_x2h[b * 2048 + 1024 + q] = hi; d_x2l[b * 2048 + 1024 + q] = lo;
}

__global__ void lstm2_kernel(int t) {
    int idx = blockIdx.x * 256 + threadIdx.x;
    int b = idx >> 9, q = idx & 511;
    if (t >= d_declen[b]) return;
    size_t base = (size_t)b * 4096;
    float2 g[4];
    #pragma unroll
    for (int qt = 0; qt < 4; ++qt) {
        int j = qt * 1024 + q * 2;
        float2 v = *(const float2*)(d_b2sum + j);
        #pragma unroll
        for (int s = 0; s < 8; ++s) {
            float2 p = *(const float2*)(d_gp + (size_t)s * BBS * 4096 + base + j);
            v.x += p.x; v.y += p.y;
        }
        g[qt] = v;
    }
    float2 c = *(const float2*)(d_c2 + (size_t)b * 1024 + q * 2);
    float cn0 = sigf(g[1].x) * c.x + sigf(g[0].x) * tanhf(g[2].x);
    float cn1 = sigf(g[1].y) * c.y + sigf(g[0].y) * tanhf(g[2].y);
    float hn0 = sigf(g[3].x) * tanhf(cn0);
    float hn1 = sigf(g[3].y) * tanhf(cn1);
    *(float2*)(d_c2 + (size_t)b * 1024 + q * 2) = make_float2(cn0, cn1);
    size_t hrow = (size_t)(t * BBS + b);
    *(float2*)(d_h2all + hrow * 1024 + q * 2) = make_float2(hn0, hn1);
    unsigned int hi = pack_hi(hn0, hn1), lo = pack_lo(hn0, hn1);
    d_h2h[hrow * 512 + q] = hi;      d_h2l[hrow * 512 + q] = lo;
    d_x1h[b * 1024 + q] = hi;        d_x1l[b * 1024 + q] = lo;
    d_x2h[b * 2048 + 1536 + q] = hi; d_x2l[b * 2048 + 1536 + q] = lo;
}

// ---------------------------------------------------------------------------
// Fused attention; att2/gate = b3 + 4 split-K partial slabs; writes bf16 att.
// ---------------------------------------------------------------------------
__global__ void attn_kernel(const float* __restrict__ fullW,
                            const float* __restrict__ fullb, int t) {
    const int b = blockIdx.x;
    if (t >= d_declen[b]) return;
    __shared__ float s_a2[DHID];
    __shared__ float s_w [DHID];
    __shared__ float s_sc[PPS];
    __shared__ float s_red[256];
    const int tid = threadIdx.x;
    const int lane = tid & 31, warp = tid >> 5;
    const size_t abase = (size_t)b * 3072;

    for (int i = tid; i < DHID; i += 256) {
        float v = d_b3cat[i];
        #pragma unroll
        for (int s = 0; s < 4; ++s)
            v += d_ap[(size_t)s * BBS * 3072 + abase + i];
        s_a2[i] = v;
        s_w[i]  = fullW[i];
    }
    __syncthreads();

    const float b0 = fullb[0];
    for (int p = warp; p < PPS; p += 8) {
        const float* row = d_att1 + ((size_t)b * PPS + p) * DHID;
        float s = 0.f;
        #pragma unroll 8
        for (int a = lane; a < DHID; a += 32)
            s += tanh_fast(row[a] + s_a2[a]) * s_w[a];
        #pragma unroll
        for (int o = 16; o > 0; o >>= 1)
            s += __shfl_down_sync(0xffffffffu, s, o);
        if (lane == 0) s_sc[p] = s + b0;
    }
    __syncthreads();

    s_red[tid] = (tid < PPS) ? s_sc[tid] : -INFINITY;
    __syncthreads();
    for (int s = 128; s > 0; s >>= 1) {
        if (tid < s) s_red[tid] = fmaxf(s_red[tid], s_red[tid + s]);
        __syncthreads();
    }
    float mx = s_red[0];
    __syncthreads();
    float e = 0.f;
    if (tid < PPS) e = __expf(s_sc[tid] - mx);
    s_red[tid] = e;
    __syncthreads();
    for (int s = 128; s > 0; s >>= 1) {
        if (tid < s) s_red[tid] += s_red[tid + s];
        __syncthreads();
    }
    float inv = 1.0f / s_red[0];
    __syncthreads();
    if (tid < PPS) s_sc[tid] = e * inv;
    __syncthreads();

    const float* encb = d_encs + (size_t)b * PPS * ENCD;
    for (int e2 = tid; e2 < ENCD / 2; e2 += 256) {
        int ei = e2 * 2;
        float a0 = 0.f, a1 = 0.f;
        const float* col = encb + ei;
        #pragma unroll 4
        for (int p = 0; p < PPS; ++p) {
            float al = s_sc[p];
            a0 = fmaf(al, col[(size_t)p * ENCD], a0);
            a1 = fmaf(al, col[(size_t)p * ENCD + 1], a1);
        }
        float gl0 = d_b3cat[1024 + ei];
        float gl1 = d_b3cat[1024 + ei + 1];
        #pragma unroll
        for (int s = 0; s < 4; ++s) {
            gl0 += d_ap[(size_t)s * BBS * 3072 + abase + 1024 + ei];
            gl1 += d_ap[(size_t)s * BBS * 3072 + abase + 1024 + ei + 1];
        }
        float v0 = sigf(gl0) * a0, v1 = sigf(gl1) * a1;
        d_x2h[b * 2048 + e2] = pack_hi(v0, v1);
        d_x2l[b * 2048 + e2] = pack_lo(v0, v1);
    }
}

__global__ void rpm_kernel(const float* __restrict__ rpmW,
                           float* __restrict__ out) {
    int m = blockIdx.x * 8 + (threadIdx.x >> 5);
    if (m >= TTS * BBS) return;
    int lane = threadIdx.x & 31;
    int t = m / BBS, b = m % BBS;
    const float* h = d_h2all + (size_t)m * DHID;
    float s = 0.f;
    #pragma unroll 8
    for (int k = lane; k < DHID; k += 32) s += h[k] * rpmW[k];
    #pragma unroll
    for (int o = 16; o > 0; o >>= 1)
        s += __shfl_down_sync(0xffffffffu, s, o);
    if (lane == 0)
        out[O_PPOS + (long long)b * TTS + t] =
            (t < d_declen[b]) ? sigf(s) : 0.f;
}

// ---------------------------------------------------------------------------
// Launch
// ---------------------------------------------------------------------------
extern "C" void kernel_launch(void* const* d_in, const int* in_sizes, int n_in,
                              void* d_out, int out_size) {
    const float* enc_out = (const float*)d_in[0];
    const int*   caps    = (const int*)  d_in[1];
    const int*   caplen  = (const int*)  d_in[2];
    const float* emb     = (const float*)d_in[3];
    const float* eaW     = (const float*)d_in[4];
    const float* eab     = (const float*)d_in[5];
    const float* daW     = (const float*)d_in[6];
    const float* dab     = (const float*)d_in[7];
    const float* faW     = (const float*)d_in[8];
    const float* fab     = (const float*)d_in[9];
    const float* fbW     = (const float*)d_in[10];
    const float* fbb     = (const float*)d_in[11];
    const float* l1Wih   = (const float*)d_in[12];
    const float* l1Whh   = (const float*)d_in[13];
    const float* l1bih   = (const float*)d_in[14];
    const float* l1bhh   = (const float*)d_in[15];
    const float* l2Wih   = (const float*)d_in[16];
    const float* l2Whh   = (const float*)d_in[17];
    const float* l2bih   = (const float*)d_in[18];
    const float* l2bhh   = (const float*)d_in[19];
    const float* ramW    = (const float*)d_in[20];
    const float* ramb    = (const float*)d_in[21];
    const float* rpmW    = (const float*)d_in[22];
    float* out = (float*)d_out;

    float* p_att1;  cudaGetSymbolAddress((void**)&p_att1,  d_att1);
    float* p_econ;  cudaGetSymbolAddress((void**)&p_econ,  d_econ);
    float* p_W1c;   cudaGetSymbolAddress((void**)&p_W1c,   d_W1cat);
    float* p_W2c;   cudaGetSymbolAddress((void**)&p_W2c,   d_W2cat);
    float* p_W3c;   cudaGetSymbolAddress((void**)&p_W3c,   d_W3cat);
    float* p_b1;    cudaGetSymbolAddress((void**)&p_b1,    d_b1sum);
    float* p_base1; cudaGetSymbolAddress((void**)&p_base1, d_base1);
    float* p_gp;    cudaGetSymbolAddress((void**)&p_gp,    d_gp);
    float* p_ap;    cudaGetSymbolAddress((void**)&p_ap,    d_ap);
    float* p_mean;  cudaGetSymbolAddress((void**)&p_mean,  d_mean);
    unsigned int *p_ench, *p_encl, *p_eaWh, *p_eaWl, *p_W1eh, *p_W1el;
    unsigned int *p_embgh, *p_embgl, *p_ramWh, *p_ramWl, *p_h2h, *p_h2l;
    unsigned int *p_W1h, *p_W1l, *p_W2h, *p_W2l, *p_W3h, *p_W3l;
    unsigned int *p_x1h, *p_x1l, *p_x2h, *p_x2l;
    cudaGetSymbolAddress((void**)&p_ench,  d_ench);
    cudaGetSymbolAddress((void**)&p_encl,  d_encl);
    cudaGetSymbolAddress((void**)&p_eaWh,  d_eaWh);
    cudaGetSymbolAddress((void**)&p_eaWl,  d_eaWl);
    cudaGetSymbolAddress((void**)&p_W1eh,  d_W1eh);
    cudaGetSymbolAddress((void**)&p_W1el,  d_W1el);
    cudaGetSymbolAddress((void**)&p_embgh, d_embgh);
    cudaGetSymbolAddress((void**)&p_embgl, d_embgl);
    cudaGetSymbolAddress((void**)&p_ramWh, d_ramWh);
    cudaGetSymbolAddress((void**)&p_ramWl, d_ramWl);
    cudaGetSymbolAddress((void**)&p_h2h,   d_h2h);
    cudaGetSymbolAddress((void**)&p_h2l,   d_h2l);
    cudaGetSymbolAddress((void**)&p_W1h,   d_W1h);
    cudaGetSymbolAddress((void**)&p_W1l,   d_W1l);
    cudaGetSymbolAddress((void**)&p_W2h,   d_W2h);
    cudaGetSymbolAddress((void**)&p_W2l,   d_W2l);
    cudaGetSymbolAddress((void**)&p_W3h,   d_W3h);
    cudaGetSymbolAddress((void**)&p_W3l,   d_W3l);
    cudaGetSymbolAddress((void**)&p_x1h,   d_x1h);
    cudaGetSymbolAddress((void**)&p_x1l,   d_x1l);
    cudaGetSymbolAddress((void**)&p_x2h,   d_x2h);
    cudaGetSymbolAddress((void**)&p_x2l,   d_x2l);

    cudaFuncSetAttribute(gemm_wb<0>, cudaFuncAttributeMaxDynamicSharedMemorySize,
                         WB_SMEM);
    cudaFuncSetAttribute(gemm_wb<1>, cudaFuncAttributeMaxDynamicSharedMemorySize,
                         WB_SMEM);
    cudaFuncSetAttribute(gemm_wb<2>, cudaFuncAttributeMaxDynamicSharedMemorySize,
                         WB_SMEM);
    cudaFuncSetAttribute(gemm_ws, cudaFuncAttributeMaxDynamicSharedMemorySize,
                         WS_SMEM);

    // 1-3: sort, gather(+bf16 split), convert eaW
    setup_kernel<<<1, BBS>>>(caplen, caps, out);
    gather_enc_kernel<<<50176, 256>>>(enc_out);
    conv_kernel<<<(1024 * 1024) / 256, 256>>>(eaW, p_eaWh, p_eaWl, 1024, 2048);

    // 4: att1 (bf16x3 HMMA): 25088 x 1024, K=2048  <- profiled slot
    gemm_wb<1><<<dim3(1024 / 128, (BBS * PPS) / 128), 256, WB_SMEM>>>(
        p_ench, p_encl, p_eaWh, p_eaWl, eab, p_att1, 2048, 1024, 1024, 1024);

    // 5+: mean, zero pred, biases, weight concats + conversions
    mean_kernel<<<(BBS * ENCD) / 256, 256>>>();
    zero_pred_kernel<<<84000, 256>>>(out + O_PRED);
    bias_kernel<<<16, 256>>>(l1bih, l1bhh, l2bih, l2bhh, dab, fbb);
    w1copy_kernel<<<8192, 256>>>(l1Wih, l1Whh);
    w2copy_kernel<<<16384, 256>>>(l2Wih, l2Whh);
    w3copy_kernel<<<3072, 256>>>(daW, fbW);
    conv_kernel<<<(4096 * 512) / 256, 256>>>(l1Wih, p_W1eh, p_W1el, 512, 4096);
    conv_kernel<<<(4096 * 1024) / 256, 256>>>(p_W1c, p_W1h, p_W1l, 1024, 2048);
    conv_kernel<<<(4096 * 2048) / 256, 256>>>(p_W2c, p_W2h, p_W2l, 2048, 4096);
    conv_kernel<<<(3072 * 512) / 256, 256>>>(p_W3c, p_W3h, p_W3l, 512, 1024);

    // embeddings (bf16 split)
    embg_kernel<<<TTS * BBS, 256>>>(emb);

    // econ (bf16x3 HMMA): 2688 x 4096, K=1024
    gemm_wb<0><<<dim3(4096 / 128, (TTS * BBS) / 128), 256, WB_SMEM>>>(
        p_embgh, p_embgl, p_W1eh, p_W1el, nullptr, p_econ, 1024, 512, 512, 4096);

    // ramW conversion (for preds later)
    conv_kernel<<<(VOC * 512) / 256, 256>>>(ramW, p_ramWh, p_ramWl, 512, 1024);

    // base1 = mean_enc @ Wih[:,2048:].T + (bih+bhh)
    gemm32sk<<<dim3(4096 / 128, 4), 128>>>(
        p_mean, l1Wih + 2048, p_b1, p_base1, 4096, 2048, 2048, 4096);

    zero_states_kernel<<<(BBS * 2048) / 256, 256>>>();

    // sequential decode: HMMA split-K partials -> pointwise epilogues
    for (int t = 0; t < TTS; ++t) {
        // gates1: x1[128x2048] @ W1cat.T -> 8 slabs (Kc=256, 4 chunks)
        gemm_ws<<<dim3(32, 4, 8), 256, WS_SMEM>>>(
            p_x1h, p_x1l, p_W1h, p_W1l, p_gp, 4096, 256, 1024, 1024, t);

        lstm1_kernel<<<(BBS * DHID / 2) / 256, 256>>>(
            t, p_econ + (size_t)t * BBS * 4096);

        // att2/gate: h1n[128x1024] @ [dec_att;f_beta].T -> 4 slabs (Kc=256)
        gemm_ws<<<dim3(24, 4, 4), 256, WS_SMEM>>>(
            p_x2h + 1024, p_x2l + 1024, p_W3h, p_W3l, p_ap,
            3072, 256, 2048, 512, t);

        attn_kernel<<<BBS, 256>>>(faW, fab, t);

        // gates2: x2[128x4096] @ W2cat.T -> 8 slabs (Kc=512, 8 chunks)
        gemm_ws<<<dim3(32, 4, 8), 256, WS_SMEM>>>(
            p_x2h, p_x2l, p_W2h, p_W2l, p_gp, 4096, 512, 2048, 2048, t);

        lstm2_kernel<<<(BBS * DHID / 2) / 256, 256>>>(t);
    }

    // preds (bf16x3 HMMA, compact gather/scatter)
    gemm_wb<2><<<dim3(VOC / 128, (TTS * BBS + 127) / 128), 256, WB_SMEM>>>(
        p_h2h, p_h2l, p_ramWh, p_ramWl, ramb, out + O_PRED, 1024, 512, 512, VOC);

    // predicted_pos
    rpm_kernel<<<(TTS * BBS + 7) / 8, 256>>>(rpmW, out);
}

// round 16
// speedup vs baseline: 1.8486x; 1.0269x over previous
#include <cuda_runtime.h>
#include <cuda_bf16.h>
#include <mma.h>
#include <math.h>
using namespace nvcuda;

// ---------------------------------------------------------------------------
// Problem constants
// ---------------------------------------------------------------------------
#define TTS   21
#define CAPL  22
#define BBS   128
#define PPS   196
#define ENCD  2048
#define DHID  1024
#define VOC   32000

static constexpr long long O_PRED = 0;
static constexpr long long O_CAPS = (long long)BBS * TTS * VOC;
static constexpr long long O_DECL = O_CAPS + (long long)BBS * CAPL;
static constexpr long long O_SORT = O_DECL + BBS;
static constexpr long long O_RPOS = O_SORT + BBS;
static constexpr long long O_PPOS = O_RPOS + (long long)BBS * TTS;

// ---------------------------------------------------------------------------
// Static device scratch
// ---------------------------------------------------------------------------
__device__ float d_encs [(size_t)BBS * PPS * ENCD];
__device__ float d_att1 [(size_t)BBS * PPS * DHID];
__device__ float d_econ [(size_t)TTS * BBS * 4 * DHID];
__device__ float d_W1cat[4096 * 2048];
__device__ float d_W2cat[(size_t)4096 * 4096];
__device__ float d_W3cat[3072 * 1024];
__device__ float d_b1sum[4096];
__device__ float d_b2sum[4096];
__device__ float d_b3cat[3072];
__device__ float d_base1[BBS * 4096];
__device__ float d_gp   [(size_t)8 * BBS * 4096];   // 8 split-K slabs
__device__ float d_ap   [(size_t)4 * BBS * 3072];   // 4 split-K slabs
__device__ float d_c1   [BBS * DHID];
__device__ float d_c2   [BBS * DHID];
__device__ float d_mean [BBS * ENCD];
__device__ float d_h2all[(size_t)TTS * BBS * DHID];
__device__ int   d_sort  [BBS];
__device__ int   d_declen[BBS];
__device__ int   d_tokens[TTS * BBS];
__device__ int   d_nact  [TTS];
__device__ int   d_rowidx[TTS * BBS];
__device__ int   d_outrow[TTS * BBS];
__device__ int   d_cnt;

// bf16 hi/lo buffers (packed bf16x2 in uint32, row-major)
__device__ unsigned int d_ench [(size_t)BBS * PPS * (ENCD / 2)];
__device__ unsigned int d_encl [(size_t)BBS * PPS * (ENCD / 2)];
__device__ unsigned int d_eaWh [1024 * (ENCD / 2)];
__device__ unsigned int d_eaWl [1024 * (ENCD / 2)];
__device__ unsigned int d_W1eh [4096 * (DHID / 2)];
__device__ unsigned int d_W1el [4096 * (DHID / 2)];
__device__ unsigned int d_embgh[TTS * BBS * (DHID / 2)];
__device__ unsigned int d_embgl[TTS * BBS * (DHID / 2)];
__device__ unsigned int d_ramWh[(size_t)VOC * (DHID / 2)];
__device__ unsigned int d_ramWl[(size_t)VOC * (DHID / 2)];
__device__ unsigned int d_h2h  [TTS * BBS * (DHID / 2)];
__device__ unsigned int d_h2l  [TTS * BBS * (DHID / 2)];
// loop-GEMM operands
__device__ unsigned int d_W1h  [4096 * 1024];
__device__ unsigned int d_W1l  [4096 * 1024];
__device__ unsigned int d_W2h  [(size_t)4096 * 2048];
__device__ unsigned int d_W2l  [(size_t)4096 * 2048];
__device__ unsigned int d_W3h  [3072 * 512];
__device__ unsigned int d_W3l  [3072 * 512];
__device__ unsigned int d_x1h  [BBS * 1024];
__device__ unsigned int d_x1l  [BBS * 1024];
__device__ unsigned int d_x2h  [BBS * 2048];
__device__ unsigned int d_x2l  [BBS * 2048];

// ---------------------------------------------------------------------------
// Helpers
// ---------------------------------------------------------------------------
__device__ __forceinline__ float sigf(float x) {
    return 1.0f / (1.0f + __expf(-x));
}
__device__ __forceinline__ float tanh_fast(float x) {
    return 1.0f - 2.0f / (__expf(2.0f * x) + 1.0f);
}
__device__ __forceinline__ unsigned int pack_hi(float a, float b) {
    __nv_bfloat162 p = __floats2bfloat162_rn(a, b);
    return *reinterpret_cast<unsigned int*>(&p);
}
__device__ __forceinline__ unsigned int pack_lo(float a, float b) {
    float ah = __bfloat162float(__float2bfloat16_rn(a));
    float bh = __bfloat162float(__float2bfloat16_rn(b));
    __nv_bfloat162 p = __floats2bfloat162_rn(a - ah, b - bh);
    return *reinterpret_cast<unsigned int*>(&p);
}
__device__ __forceinline__ unsigned int smem_u32(const void* p) {
    unsigned int a;
    asm("{ .reg .u64 t; cvta.to.shared.u64 t, %1; cvt.u32.u64 %0, t; }"
        : "=r"(a) : "l"(p));
    return a;
}
__device__ __forceinline__ void cp16(unsigned int dst, const void* src) {
    asm volatile("cp.async.cg.shared.global [%0], [%1], 16;"
                 :: "r"(dst), "l"(__cvta_generic_to_global(src)) : "memory");
}
__device__ __forceinline__ void ldsm4(unsigned int* r, unsigned int addr) {
    asm volatile("ldmatrix.sync.aligned.m8n8.x4.shared.b16 {%0,%1,%2,%3}, [%4];"
                 : "=r"(r[0]), "=r"(r[1]), "=r"(r[2]), "=r"(r[3]) : "r"(addr));
}
__device__ __forceinline__ void ldsm2(unsigned int* r, unsigned int addr) {
    asm volatile("ldmatrix.sync.aligned.m8n8.x2.shared.b16 {%0,%1}, [%2];"
                 : "=r"(r[0]), "=r"(r[1]) : "r"(addr));
}
__device__ __forceinline__ void mma16816(float* d, const unsigned int* a,
                                         const unsigned int* b) {
    asm volatile(
        "mma.sync.aligned.m16n8k16.row.col.f32.bf16.bf16.f32 "
        "{%0,%1,%2,%3}, {%4,%5,%6,%7}, {%8,%9}, {%0,%1,%2,%3};"
        : "+f"(d[0]), "+f"(d[1]), "+f"(d[2]), "+f"(d[3])
        : "r"(a[0]), "r"(a[1]), "r"(a[2]), "r"(a[3]), "r"(b[0]), "r"(b[1]));
}

// ---------------------------------------------------------------------------
// Big bf16x3 GEMM, hand-rolled mma.sync.m16n8k16 (128x128 tile, 2 blk/SM).
// Same loaders/layout/epilogue as the R15 wmma version; inner machinery is
// raw ldmatrix + mma with B-fragment double buffering for LDSM/HMMA overlap.
// MODE 0: plain  MODE 1: +bias  MODE 2: +bias + gather/scatter (preds)
// ---------------------------------------------------------------------------
static constexpr int WB_SMEM = 81920;

template<int MODE>
__global__ void __launch_bounds__(256, 2)
gemm_wb(const unsigned int* __restrict__ Ah, const unsigned int* __restrict__ Al,
        const unsigned int* __restrict__ Bh, const unsigned int* __restrict__ Bl,
        const float* __restrict__ bias, float* __restrict__ C,
        int K, int lda32, int ldb32, int ldc) {
    extern __shared__ char smem[];
    const int tid = threadIdx.x;
    const int warp = tid >> 5;
    const int lane = tid & 31;
    const int m0 = blockIdx.y * 128, n0 = blockIdx.x * 128;
    int count = 0;
    if (MODE == 2) {
        count = d_cnt;
        if (m0 >= count) return;
    }

    const int lr = tid >> 1;
    const int lc = (tid & 1) * 8;
    int arow = m0 + lr;
    if (MODE == 2) arow = (arow < count) ? d_rowidx[arow] : d_rowidx[0];
    const unsigned int* gA0 = Ah + (size_t)arow * lda32 + lc;
    const unsigned int* gA1 = Al + (size_t)arow * lda32 + lc;
    const unsigned int* gB0 = Bh + (size_t)(n0 + lr) * ldb32 + lc;
    const unsigned int* gB1 = Bl + (size_t)(n0 + lr) * ldb32 + lc;

    const unsigned int sbase = smem_u32(smem);
    const unsigned int drow = (unsigned)(lr * 80 + lc * 4);

    const int wm = (warp >> 1) * 32;
    const int wn = (warp & 1) * 64;

    // per-lane ldmatrix address components (elements stride 40 -> 80 bytes)
    const int li = lane & 7;
    const int lt = lane >> 3;
    const unsigned int aRow0 =
        (unsigned)((wm + li + ((lt & 1) << 3)) * 80 + ((lt >> 1) << 4));
    const unsigned int aRow1 = aRow0 + 16 * 80;
    const unsigned int bRow0 =
        (unsigned)((wn + li) * 80 + ((lt & 1) << 4));

    float acc[2][8][4];
    #pragma unroll
    for (int i = 0; i < 2; ++i)
        #pragma unroll
        for (int j = 0; j < 8; ++j)
            #pragma unroll
            for (int q = 0; q < 4; ++q) acc[i][j][q] = 0.f;

    const int nch = K >> 5;
    {
        unsigned int d0 = sbase + drow;
        cp16(d0,             gA0); cp16(d0 + 16,         gA0 + 4);
        cp16(d0 + 10240,     gA1); cp16(d0 + 10240 + 16, gA1 + 4);
        cp16(d0 + 20480,     gB0); cp16(d0 + 20480 + 16, gB0 + 4);
        cp16(d0 + 30720,     gB1); cp16(d0 + 30720 + 16, gB1 + 4);
        asm volatile("cp.async.commit_group;" ::: "memory");
    }

    for (int ch = 0; ch < nch; ++ch) {
        const int buf = ch & 1;
        if (ch + 1 < nch) {
            const int kw = (ch + 1) * 16;
            unsigned int d0 = sbase + (buf ^ 1) * 40960 + drow;
            cp16(d0,             gA0 + kw); cp16(d0 + 16,         gA0 + kw + 4);
            cp16(d0 + 10240,     gA1 + kw); cp16(d0 + 10240 + 16, gA1 + kw + 4);
            cp16(d0 + 20480,     gB0 + kw); cp16(d0 + 20480 + 16, gB0 + kw + 4);
            cp16(d0 + 30720,     gB1 + kw); cp16(d0 + 30720 + 16, gB1 + kw + 4);
            asm volatile("cp.async.commit_group;" ::: "memory");
            asm volatile("cp.async.wait_group 1;" ::: "memory");
        } else {
            asm volatile("cp.async.wait_group 0;" ::: "memory");
        }
        __syncthreads();

        const unsigned int base = sbase + buf * 40960;

        #pragma unroll
        for (int kk = 0; kk < 32; kk += 16) {
            const unsigned int kb = (unsigned)(kk * 2);
            unsigned int ah0[4], ah1[4], al0[4], al1[4];
            ldsm4(ah0, base + aRow0 + kb);
            ldsm4(ah1, base + aRow1 + kb);
            ldsm4(al0, base + 10240 + aRow0 + kb);
            ldsm4(al1, base + 10240 + aRow1 + kb);

            unsigned int bh0[2], bl0[2], bh1[2], bl1[2];
            ldsm2(bh0, base + 20480 + bRow0 + kb);
            ldsm2(bl0, base + 30720 + bRow0 + kb);

            #pragma unroll
            for (int j = 0; j < 8; ++j) {
                unsigned int* bhc = (j & 1) ? bh1 : bh0;
                unsigned int* blc = (j & 1) ? bl1 : bl0;
                if (j < 7) {
                    unsigned int* bhn = (j & 1) ? bh0 : bh1;
                    unsigned int* bln = (j & 1) ? bl0 : bl1;
                    unsigned int off = (unsigned)((j + 1) * 640);
                    ldsm2(bhn, base + 20480 + bRow0 + off + kb);
                    ldsm2(bln, base + 30720 + bRow0 + off + kb);
                }
                mma16816(acc[0][j], ah0, bhc);
                mma16816(acc[1][j], ah1, bhc);
                mma16816(acc[0][j], al0, bhc);
                mma16816(acc[1][j], al1, bhc);
                mma16816(acc[0][j], ah0, blc);
                mma16816(acc[1][j], ah1, blc);
            }
        }
        __syncthreads();
    }

    // stage accumulators through smem (same layout as wmma store), then the
    // proven masked/scattered scalar store loop.
    float* outs = (float*)smem;
    {
        const int r = lane >> 2;
        const int c = (lane & 3) * 2;
        #pragma unroll
        for (int mi = 0; mi < 2; ++mi)
            #pragma unroll
            for (int j = 0; j < 8; ++j) {
                float* o = outs + (size_t)(wm + mi * 16 + r) * 128
                         + wn + j * 8 + c;
                o[0] = acc[mi][j][0];
                o[1] = acc[mi][j][1];
                o[8 * 128] = acc[mi][j][2];
                o[8 * 128 + 1] = acc[mi][j][3];
            }
    }
    __syncthreads();

    for (int i = tid; i < 128 * 128; i += 256) {
        int m = i >> 7, n = i & 127;
        float v = outs[i];
        int gm = m0 + m, gn = n0 + n;
        if (MODE >= 1) v += bias[gn];
        if (MODE == 2) {
            if (gm >= count) continue;
            C[(long long)d_outrow[gm] * ldc + gn] = v;
        } else {
            C[(size_t)gm * ldc + gn] = v;
        }
    }
}

// ---------------------------------------------------------------------------
// Skinny bf16x3 wmma split-K GEMM (R15, unchanged): 32x128 tile, K-chunk 64,
// direct fragment stores to global partial slab.
// ---------------------------------------------------------------------------
static constexpr int WS_SMEM = 92160;

__global__ void __launch_bounds__(256, 2)
gemm_ws(const unsigned int* __restrict__ Ah, const unsigned int* __restrict__ Al,
        const unsigned int* __restrict__ Bh, const unsigned int* __restrict__ Bl,
        float* __restrict__ C, int N, int Kc, int lda32, int ldb32, int t) {
    const int m0 = blockIdx.y * 32;
    if (m0 >= d_nact[t]) return;
    extern __shared__ char smem[];
    const int tid = threadIdx.x;
    const int warp = tid >> 5;
    const int n0 = blockIdx.x * 128;
    const int ko32 = blockIdx.z * (Kc >> 1);
    float* Cs = C + (size_t)blockIdx.z * BBS * N;

    const int ra = tid >> 3, ca = (tid & 7) * 16;
    const unsigned int* gAh = Ah + (size_t)(m0 + ra) * lda32 + ko32 + (ca >> 2);
    const unsigned int* gAl = Al + (size_t)(m0 + ra) * lda32 + ko32 + (ca >> 2);
    const unsigned int aoff = (unsigned)(ra * 144 + ca);
    const int rb = tid >> 1, cb = (tid & 1) * 64;
    const unsigned int* gBh = Bh + (size_t)(n0 + rb) * ldb32 + ko32 + (cb >> 2);
    const unsigned int* gBl = Bl + (size_t)(n0 + rb) * ldb32 + ko32 + (cb >> 2);
    const unsigned int boff = (unsigned)(rb * 144 + cb);

    const unsigned int sbase = smem_u32(smem);
    const int wm = (warp >> 2) * 16;
    const int wn = (warp & 3) * 32;

    wmma::fragment<wmma::accumulator, 16, 16, 16, float> acc[2];
    wmma::fill_fragment(acc[0], 0.0f);
    wmma::fill_fragment(acc[1], 0.0f);

    const int nch = Kc >> 6;
    {
        unsigned int s = sbase;
        cp16(s + aoff,                  gAh);
        cp16(s + 4608 + aoff,           gAl);
        cp16(s + 9216 + boff,           gBh);
        cp16(s + 9216 + boff + 16,      gBh + 4);
        cp16(s + 9216 + boff + 32,     gBh + 8);
        cp16(s + 9216 + boff + 48,     gBh + 12);
        cp16(s + 27648 + boff,          gBl);
        cp16(s + 27648 + boff + 16,     gBl + 4);
        cp16(s + 27648 + boff + 32,    gBl + 8);
        cp16(s + 27648 + boff + 48,    gBl + 12);
        asm volatile("cp.async.commit_group;" ::: "memory");
    }

    for (int ch = 0; ch < nch; ++ch) {
        const int buf = ch & 1;
        if (ch + 1 < nch) {
            const int kw = (ch + 1) * 32;
            unsigned int s = sbase + (buf ^ 1) * 46080;
            cp16(s + aoff,              gAh + kw);
            cp16(s + 4608 + aoff,       gAl + kw);
            cp16(s + 9216 + boff,       gBh + kw);
            cp16(s + 9216 + boff + 16,  gBh + kw + 4);
            cp16(s + 9216 + boff + 32,  gBh + kw + 8);
            cp16(s + 9216 + boff + 48,  gBh + kw + 12);
            cp16(s + 27648 + boff,      gBl + kw);
            cp16(s + 27648 + boff + 16, gBl + kw + 4);
            cp16(s + 27648 + boff + 32, gBl + kw + 8);
            cp16(s + 27648 + boff + 48, gBl + kw + 12);
            asm volatile("cp.async.commit_group;" ::: "memory");
            asm volatile("cp.async.wait_group 1;" ::: "memory");
        } else {
            asm volatile("cp.async.wait_group 0;" ::: "memory");
        }
        __syncthreads();

        const __nv_bfloat16* pAh = (const __nv_bfloat16*)(smem + buf * 46080);
        const __nv_bfloat16* pAl = pAh + 2304;
        const __nv_bfloat16* pBh = pAh + 4608;
        const __nv_bfloat16* pBl = pAh + 13824;

        #pragma unroll
        for (int kk = 0; kk < 64; kk += 16) {
            wmma::fragment<wmma::matrix_a, 16, 16, 16, __nv_bfloat16,
                           wmma::row_major> ah, al;
            wmma::load_matrix_sync(ah, pAh + wm * 72 + kk, 72);
            wmma::load_matrix_sync(al, pAl + wm * 72 + kk, 72);
            #pragma unroll
            for (int j = 0; j < 2; ++j) {
                wmma::fragment<wmma::matrix_b, 16, 16, 16, __nv_bfloat16,
                               wmma::col_major> bh, bl;
                wmma::load_matrix_sync(bh, pBh + (wn + j * 16) * 72 + kk, 72);
                wmma::load_matrix_sync(bl, pBl + (wn + j * 16) * 72 + kk, 72);
                wmma::mma_sync(acc[j], ah, bh, acc[j]);
                wmma::mma_sync(acc[j], al, bh, acc[j]);
                wmma::mma_sync(acc[j], ah, bl, acc[j]);
            }
        }
        __syncthreads();
    }

    #pragma unroll
    for (int j = 0; j < 2; ++j)
        wmma::store_matrix_sync(Cs + (size_t)(m0 + wm) * N + n0 + wn + j * 16,
                                acc[j], N, wmma::mem_row_major);
}

// ---------------------------------------------------------------------------
// fp32 -> bf16 hi/lo conversion (2 elems per thread)
// ---------------------------------------------------------------------------
__global__ void conv_kernel(const float* __restrict__ src,
                            unsigned int* __restrict__ dh,
                            unsigned int* __restrict__ dl,
                            int cols2, int src_ld) {
    size_t idx = (size_t)blockIdx.x * 256 + threadIdx.x;
    size_t row = idx / cols2;
    int cp = (int)(idx - row * cols2);
    const float* s = src + row * (size_t)src_ld + (size_t)cp * 2;
    float a = s[0], b = s[1];
    dh[row * cols2 + cp] = pack_hi(a, b);
    dl[row * cols2 + cp] = pack_lo(a, b);
}

// ---------------------------------------------------------------------------
// Setup / gather / small kernels (unchanged)
// ---------------------------------------------------------------------------
__global__ void setup_kernel(const int* __restrict__ caplen,
                             const int* __restrict__ caps,
                             float* __restrict__ out) {
    __shared__ int lens_s[BBS];
    __shared__ int sort_s[BBS];
    __shared__ int dl_s[BBS];
    int i = threadIdx.x;
    int li = caplen[i];
    lens_s[i] = li;
    __syncthreads();
    int rank = 0;
    for (int j = 0; j < BBS; ++j) {
        int lj = lens_s[j];
        if (lj > li || (lj == li && j < i)) rank++;
    }
    sort_s[rank] = i;
    __syncthreads();
    int src = sort_s[i];
    d_sort[i] = src;
    int dl = lens_s[src] - 1;
    d_declen[i] = dl;
    dl_s[i] = dl;
    out[O_DECL + i] = (float)dl;
    out[O_SORT + i] = (float)src;
    for (int t = 0; t < CAPL; ++t) {
        int tok = caps[src * CAPL + t];
        out[O_CAPS + (long long)i * CAPL + t] = (float)tok;
        if (t < TTS) d_tokens[t * BBS + i] = tok;
    }
    float dlf = (float)dl;
    for (int s = 0; s < TTS; ++s)
        out[O_RPOS + (long long)i * TTS + s] =
            (s < dl) ? ((float)(s + 1) / dlf) : 0.0f;
    __syncthreads();
    if (i == 0) {
        int c = 0;
        for (int t = 0; t < TTS; ++t) {
            int n = 0;
            while (n < BBS && dl_s[n] > t) n++;
            d_nact[t] = n;
            for (int b = 0; b < n; ++b) {
                d_rowidx[c] = t * BBS + b;
                d_outrow[c] = b * TTS + t;
                c++;
            }
        }
        d_cnt = c;
    }
}

__global__ void gather_enc_kernel(const float* __restrict__ enc) {
    int g = blockIdx.x * 256 + threadIdx.x;
    int r = g >> 9, w = g & 511;
    int b = r / PPS, p = r % PPS;
    int srow = d_sort[b] * PPS + p;
    float4 v = ((const float4*)enc)[(size_t)srow * 512 + w];
    ((float4*)d_encs)[(size_t)r * 512 + w] = v;
    size_t o = (size_t)r * 1024 + (size_t)w * 2;
    d_ench[o]     = pack_hi(v.x, v.y);
    d_ench[o + 1] = pack_hi(v.z, v.w);
    d_encl[o]     = pack_lo(v.x, v.y);
    d_encl[o + 1] = pack_lo(v.z, v.w);
}

__global__ void mean_kernel() {
    int idx = blockIdx.x * 256 + threadIdx.x;
    int b = idx / ENCD, e = idx % ENCD;
    const float* base = d_encs + (size_t)b * PPS * ENCD + e;
    float s = 0.f;
    #pragma unroll 4
    for (int p = 0; p < PPS; ++p) s += base[(size_t)p * ENCD];
    d_mean[idx] = s * (1.0f / (float)PPS);
}

__global__ void w1copy_kernel(const float* __restrict__ l1Wih,
                              const float* __restrict__ l1Whh) {
    int g = blockIdx.x * 256 + threadIdx.x;
    int j = g / (2048 / 4);
    int c = (g % (2048 / 4)) * 4;
    float4 v;
    if (c < 1024) v = *(const float4*)(l1Wih + (size_t)j * 4096 + 1024 + c);
    else          v = *(const float4*)(l1Whh + (size_t)j * 1024 + (c - 1024));
    *(float4*)(d_W1cat + (size_t)j * 2048 + c) = v;
}

__global__ void w2copy_kernel(const float* __restrict__ l2Wih,
                              const float* __restrict__ l2Whh) {
    int g = blockIdx.x * 256 + threadIdx.x;
    int j = g / (4096 / 4);
    int c = (g % (4096 / 4)) * 4;
    float4 v;
    if (c < 3072) v = *(const float4*)(l2Wih + (size_t)j * 3072 + c);
    else          v = *(const float4*)(l2Whh + (size_t)j * 1024 + (c - 3072));
    *(float4*)(d_W2cat + (size_t)j * 4096 + c) = v;
}

__global__ void w3copy_kernel(const float* __restrict__ daW,
                              const float* __restrict__ fbW) {
    int g = blockIdx.x * 256 + threadIdx.x;
    int j = g / (1024 / 4);
    int c = (g % (1024 / 4)) * 4;
    float4 v;
    if (j < 1024) v = *(const float4*)(daW + (size_t)j * 1024 + c);
    else          v = *(const float4*)(fbW + (size_t)(j - 1024) * 1024 + c);
    *(float4*)(d_W3cat + (size_t)j * 1024 + c) = v;
}

__global__ void bias_kernel(const float* __restrict__ l1bih,
                            const float* __restrict__ l1bhh,
                            const float* __restrict__ l2bih,
                            const float* __restrict__ l2bhh,
                            const float* __restrict__ dab,
                            const float* __restrict__ fbb) {
    int j = blockIdx.x * 256 + threadIdx.x;
    d_b1sum[j] = l1bih[j] + l1bhh[j];
    d_b2sum[j] = l2bih[j] + l2bhh[j];
    if (j < 3072) d_b3cat[j] = (j < 1024) ? dab[j] : fbb[j - 1024];
}

__global__ void embg_kernel(const float* __restrict__ emb) {
    int m = blockIdx.x;
    int tok = d_tokens[m];
    const float2* src = (const float2*)(emb + (size_t)tok * DHID);
    #pragma unroll
    for (int q = 0; q < 2; ++q) {
        int i = threadIdx.x + 256 * q;
        float2 v = src[i];
        d_embgh[(size_t)m * 512 + i] = pack_hi(v.x, v.y);
        d_embgl[(size_t)m * 512 + i] = pack_lo(v.x, v.y);
    }
}

__global__ void zero_states_kernel() {
    int idx = blockIdx.x * 256 + threadIdx.x;
    d_x2h[idx] = 0u; d_x2l[idx] = 0u;
    if (idx < BBS * 1024) { d_x1h[idx] = 0u; d_x1l[idx] = 0u; }
    if (idx < BBS * DHID) { d_c1[idx] = 0.f; d_c2[idx] = 0.f; }
}

__global__ void zero_pred_kernel(float* __restrict__ out) {
    size_t g = (size_t)blockIdx.x * 256 + threadIdx.x;
    ((float4*)out)[g] = make_float4(0.f, 0.f, 0.f, 0.f);
}

// ---------------------------------------------------------------------------
// Plain SIMT split-K GEMM (base1 only; runs once)
// ---------------------------------------------------------------------------
__global__ void __launch_bounds__(128)
gemm32sk(const float* __restrict__ A,
         const float* __restrict__ Bm,
         const float* __restrict__ bias,
         float* __restrict__ C,
         int N, int Kc, int lda, int ldb) {
    const int m0 = blockIdx.y * 32;
    __shared__ float As[16][36];
    __shared__ float Bs[16][132];
    const int tid = threadIdx.x;
    const int n0 = blockIdx.x * 128;

    const int ar = tid >> 2;
    const int ac = (tid & 3) * 4;
    const float* Aptr = A + (size_t)(m0 + ar) * lda + ac;
    const float* Bptr = Bm + (size_t)(n0 + tid) * ldb;

    const int ty = tid >> 4;
    const int tx = tid & 15;

    float acc[4][8];
    #pragma unroll
    for (int i = 0; i < 4; ++i)
        #pragma unroll
        for (int j = 0; j < 8; ++j) acc[i][j] = 0.f;

    float4 pav = *(const float4*)(Aptr);
    float4 pb[4];
    #pragma unroll
    for (int j = 0; j < 4; ++j) pb[j] = *(const float4*)(Bptr + j * 4);

    for (int k0 = 0; k0 < Kc; k0 += 16) {
        As[ac + 0][ar] = pav.x; As[ac + 1][ar] = pav.y;
        As[ac + 2][ar] = pav.z; As[ac + 3][ar] = pav.w;
        #pragma unroll
        for (int j = 0; j < 4; ++j) {
            Bs[j * 4 + 0][tid] = pb[j].x; Bs[j * 4 + 1][tid] = pb[j].y;
            Bs[j * 4 + 2][tid] = pb[j].z; Bs[j * 4 + 3][tid] = pb[j].w;
        }
        __syncthreads();
        if (k0 + 16 < Kc) {
            pav = *(const float4*)(Aptr + k0 + 16);
            #pragma unroll
            for (int j = 0; j < 4; ++j)
                pb[j] = *(const float4*)(Bptr + k0 + 16 + j * 4);
        }
        #pragma unroll
        for (int kk = 0; kk < 16; ++kk) {
            float a[4], b[8];
            *(float4*)(a)     = *(const float4*)&As[kk][ty * 4];
            *(float4*)(b)     = *(const float4*)&Bs[kk][tx * 4];
            *(float4*)(b + 4) = *(const float4*)&Bs[kk][64 + tx * 4];
            #pragma unroll
            for (int i = 0; i < 4; ++i)
                #pragma unroll
                for (int j = 0; j < 8; ++j)
                    acc[i][j] = fmaf(a[i], b[j], acc[i][j]);
        }
        __syncthreads();
    }

    float bv[8];
    #pragma unroll
    for (int j = 0; j < 8; ++j) {
        int n = (j < 4) ? (n0 + tx * 4 + j) : (n0 + 64 + tx * 4 + j - 4);
        bv[j] = bias[n];
    }

    #pragma unroll
    for (int i = 0; i < 4; ++i) {
        int m = m0 + ty * 4 + i;
        float* dst = C + (size_t)m * N + n0;
        float4 v0, v1;
        v0.x = acc[i][0] + bv[0]; v0.y = acc[i][1] + bv[1];
        v0.z = acc[i][2] + bv[2]; v0.w = acc[i][3] + bv[3];
        v1.x = acc[i][4] + bv[4]; v1.y = acc[i][5] + bv[5];
        v1.z = acc[i][6] + bv[6]; v1.w = acc[i][7] + bv[7];
        *(float4*)(dst + tx * 4)      = v0;
        *(float4*)(dst + 64 + tx * 4) = v1;
    }
}

// ---------------------------------------------------------------------------
// LSTM pointwise: sums 8 split-K slabs, writes bf16 states.
// ---------------------------------------------------------------------------
__global__ void lstm1_kernel(int t, const float* __restrict__ econ_t) {
    int idx = blockIdx.x * 256 + threadIdx.x;
    int b = idx >> 9, q = idx & 511;
    if (t >= d_declen[b]) return;
    size_t base = (size_t)b * 4096;
    float2 g[4];
    #pragma unroll
    for (int qt = 0; qt < 4; ++qt) {
        int j = qt * 1024 + q * 2;
        float2 v = *(const float2*)(d_base1 + base + j);
        float2 e = *(const float2*)(econ_t + base + j);
        v.x += e.x; v.y += e.y;
        #pragma unroll
        for (int s = 0; s < 8; ++s) {
            float2 p = *(const float2*)(d_gp + (size_t)s * BBS * 4096 + base + j);
            v.x += p.x; v.y += p.y;
        }
        g[qt] = v;
    }
    float2 c = *(const float2*)(d_c1 + (size_t)b * 1024 + q * 2);
    float cn0 = sigf(g[1].x) * c.x + sigf(g[0].x) * tanhf(g[2].x);
    float cn1 = sigf(g[1].y) * c.y + sigf(g[0].y) * tanhf(g[2].y);
    float hn0 = sigf(g[3].x) * tanhf(cn0);
    float hn1 = sigf(g[3].y) * tanhf(cn1);
    *(float2*)(d_c1 + (size_t)b * 1024 + q * 2) = make_float2(cn0, cn1);
    unsigned int hi = pack_hi(hn0, hn1), lo = pack_lo(hn0, hn1);
    d_x1h[b * 1024 + 512 + q] = hi;  d_x1l[b * 1024 + 512 + q] = lo;
    d_x2h[b * 2048 + 1024 + q] = hi; d_x2l[b * 2048 + 1024 + q] = lo;
}

__global__ void lstm2_kernel(int t) {
    int idx = blockIdx.x * 256 + threadIdx.x;
    int b = idx >> 9, q = idx & 511;
    if (t >= d_declen[b]) return;
    size_t base = (size_t)b * 4096;
    float2 g[4];
    #pragma unroll
    for (int qt = 0; qt < 4; ++qt) {
        int j = qt * 1024 + q * 2;
        float2 v = *(const float2*)(d_b2sum + j);
        #pragma unroll
        for (int s = 0; s < 8; ++s) {
            float2 p = *(const float2*)(d_gp + (size_t)s * BBS * 4096 + base + j);
            v.x += p.x; v.y += p.y;
        }
        g[qt] = v;
    }
    float2 c = *(const float2*)(d_c2 + (size_t)b * 1024 + q * 2);
    float cn0 = sigf(g[1].x) * c.x + sigf(g[0].x) * tanhf(g[2].x);
    float cn1 = sigf(g[1].y) * c.y + sigf(g[0].y) * tanhf(g[2].y);
    float hn0 = sigf(g[3].x) * tanhf(cn0);
    float hn1 = sigf(g[3].y) * tanhf(cn1);
    *(float2*)(d_c2 + (size_t)b * 1024 + q * 2) = make_float2(cn0, cn1);
    size_t hrow = (size_t)(t * BBS + b);
    *(float2*)(d_h2all + hrow * 1024 + q * 2) = make_float2(hn0, hn1);
    unsigned int hi = pack_hi(hn0, hn1), lo = pack_lo(hn0, hn1);
    d_h2h[hrow * 512 + q] = hi;      d_h2l[hrow * 512 + q] = lo;
    d_x1h[b * 1024 + q] = hi;        d_x1l[b * 1024 + q] = lo;
    d_x2h[b * 2048 + 1536 + q] = hi; d_x2l[b * 2048 + 1536 + q] = lo;
}

// ---------------------------------------------------------------------------
// Fused attention; att2/gate = b3 + 4 split-K partial slabs; writes bf16 att.
// ---------------------------------------------------------------------------
__global__ void attn_kernel(const float* __restrict__ fullW,
                            const float* __restrict__ fullb, int t) {
    const int b = blockIdx.x;
    if (t >= d_declen[b]) return;
    __shared__ float s_a2[DHID];
    __shared__ float s_w [DHID];
    __shared__ float s_sc[PPS];
    __shared__ float s_red[256];
    const int tid = threadIdx.x;
    const int lane = tid & 31, warp = tid >> 5;
    const size_t abase = (size_t)b * 3072;

    for (int i = tid; i < DHID; i += 256) {
        float v = d_b3cat[i];
        #pragma unroll
        for (int s = 0; s < 4; ++s)
            v += d_ap[(size_t)s * BBS * 3072 + abase + i];
        s_a2[i] = v;
        s_w[i]  = fullW[i];
    }
    __syncthreads();

    const float b0 = fullb[0];
    for (int p = warp; p < PPS; p += 8) {
        const float* row = d_att1 + ((size_t)b * PPS + p) * DHID;
        float s = 0.f;
        #pragma unroll 8
        for (int a = lane; a < DHID; a += 32)
            s += tanh_fast(row[a] + s_a2[a]) * s_w[a];
        #pragma unroll
        for (int o = 16; o > 0; o >>= 1)
            s += __shfl_down_sync(0xffffffffu, s, o);
        if (lane == 0) s_sc[p] = s + b0;
    }
    __syncthreads();

    s_red[tid] = (tid < PPS) ? s_sc[tid] : -INFINITY;
    __syncthreads();
    for (int s = 128; s > 0; s >>= 1) {
        if (tid < s) s_red[tid] = fmaxf(s_red[tid], s_red[tid + s]);
        __syncthreads();
    }
    float mx = s_red[0];
    __syncthreads();
    float e = 0.f;
    if (tid < PPS) e = __expf(s_sc[tid] - mx);
    s_red[tid] = e;
    __syncthreads();
    for (int s = 128; s > 0; s >>= 1) {
        if (tid < s) s_red[tid] += s_red[tid + s];
        __syncthreads();
    }
    float inv = 1.0f / s_red[0];
    __syncthreads();
    if (tid < PPS) s_sc[tid] = e * inv;
    __syncthreads();

    const float* encb = d_encs + (size_t)b * PPS * ENCD;
    for (int e2 = tid; e2 < ENCD / 2; e2 += 256) {
        int ei = e2 * 2;
        float a0 = 0.f, a1 = 0.f;
        const float* col = encb + ei;
        #pragma unroll 4
        for (int p = 0; p < PPS; ++p) {
            float al = s_sc[p];
            a0 = fmaf(al, col[(size_t)p * ENCD], a0);
            a1 = fmaf(al, col[(size_t)p * ENCD + 1], a1);
        }
        float gl0 = d_b3cat[1024 + ei];
        float gl1 = d_b3cat[1024 + ei + 1];
        #pragma unroll
        for (int s = 0; s < 4; ++s) {
            gl0 += d_ap[(size_t)s * BBS * 3072 + abase + 1024 + ei];
            gl1 += d_ap[(size_t)s * BBS * 3072 + abase + 1024 + ei + 1];
        }
        float v0 = sigf(gl0) * a0, v1 = sigf(gl1) * a1;
        d_x2h[b * 2048 + e2] = pack_hi(v0, v1);
        d_x2l[b * 2048 + e2] = pack_lo(v0, v1);
    }
}

__global__ void rpm_kernel(const float* __restrict__ rpmW,
                           float* __restrict__ out) {
    int m = blockIdx.x * 8 + (threadIdx.x >> 5);
    if (m >= TTS * BBS) return;
    int lane = threadIdx.x & 31;
    int t = m / BBS, b = m % BBS;
    const float* h = d_h2all + (size_t)m * DHID;
    float s = 0.f;
    #pragma unroll 8
    for (int k = lane; k < DHID; k += 32) s += h[k] * rpmW[k];
    #pragma unroll
    for (int o = 16; o > 0; o >>= 1)
        s += __shfl_down_sync(0xffffffffu, s, o);
    if (lane == 0)
        out[O_PPOS + (long long)b * TTS + t] =
            (t < d_declen[b]) ? sigf(s) : 0.f;
}

// ---------------------------------------------------------------------------
// Launch
// ---------------------------------------------------------------------------
extern "C" void kernel_launch(void* const* d_in, const int* in_sizes, int n_in,
                              void* d_out, int out_size) {
    const float* enc_out = (const float*)d_in[0];
    const int*   caps    = (const int*)  d_in[1];
    const int*   caplen  = (const int*)  d_in[2];
    const float* emb     = (const float*)d_in[3];
    const float* eaW     = (const float*)d_in[4];
    const float* eab     = (const float*)d_in[5];
    const float* daW     = (const float*)d_in[6];
    const float* dab     = (const float*)d_in[7];
    const float* faW     = (const float*)d_in[8];
    const float* fab     = (const float*)d_in[9];
    const float* fbW     = (const float*)d_in[10];
    const float* fbb     = (const float*)d_in[11];
    const float* l1Wih   = (const float*)d_in[12];
    const float* l1Whh   = (const float*)d_in[13];
    const float* l1bih   = (const float*)d_in[14];
    const float* l1bhh   = (const float*)d_in[15];
    const float* l2Wih   = (const float*)d_in[16];
    const float* l2Whh   = (const float*)d_in[17];
    const float* l2bih   = (const float*)d_in[18];
    const float* l2bhh   = (const float*)d_in[19];
    const float* ramW    = (const float*)d_in[20];
    const float* ramb    = (const float*)d_in[21];
    const float* rpmW    = (const float*)d_in[22];
    float* out = (float*)d_out;

    float* p_att1;  cudaGetSymbolAddress((void**)&p_att1,  d_att1);
    float* p_econ;  cudaGetSymbolAddress((void**)&p_econ,  d_econ);
    float* p_W1c;   cudaGetSymbolAddress((void**)&p_W1c,   d_W1cat);
    float* p_W2c;   cudaGetSymbolAddress((void**)&p_W2c,   d_W2cat);
    float* p_W3c;   cudaGetSymbolAddress((void**)&p_W3c,   d_W3cat);
    float* p_b1;    cudaGetSymbolAddress((void**)&p_b1,    d_b1sum);
    float* p_base1; cudaGetSymbolAddress((void**)&p_base1, d_base1);
    float* p_gp;    cudaGetSymbolAddress((void**)&p_gp,    d_gp);
    float* p_ap;    cudaGetSymbolAddress((void**)&p_ap,    d_ap);
    float* p_mean;  cudaGetSymbolAddress((void**)&p_mean,  d_mean);
    unsigned int *p_ench, *p_encl, *p_eaWh, *p_eaWl, *p_W1eh, *p_W1el;
    unsigned int *p_embgh, *p_embgl, *p_ramWh, *p_ramWl, *p_h2h, *p_h2l;
    unsigned int *p_W1h, *p_W1l, *p_W2h, *p_W2l, *p_W3h, *p_W3l;
    unsigned int *p_x1h, *p_x1l, *p_x2h, *p_x2l;
    cudaGetSymbolAddress((void**)&p_ench,  d_ench);
    cudaGetSymbolAddress((void**)&p_encl,  d_encl);
    cudaGetSymbolAddress((void**)&p_eaWh,  d_eaWh);
    cudaGetSymbolAddress((void**)&p_eaWl,  d_eaWl);
    cudaGetSymbolAddress((void**)&p_W1eh,  d_W1eh);
    cudaGetSymbolAddress((void**)&p_W1el,  d_W1el);
    cudaGetSymbolAddress((void**)&p_embgh, d_embgh);
    cudaGetSymbolAddress((void**)&p_embgl, d_embgl);
    cudaGetSymbolAddress((void**)&p_ramWh, d_ramWh);
    cudaGetSymbolAddress((void**)&p_ramWl, d_ramWl);
    cudaGetSymbolAddress((void**)&p_h2h,   d_h2h);
    cudaGetSymbolAddress((void**)&p_h2l,   d_h2l);
    cudaGetSymbolAddress((void**)&p_W1h,   d_W1h);
    cudaGetSymbolAddress((void**)&p_W1l,   d_W1l);
    cudaGetSymbolAddress((void**)&p_W2h,   d_W2h);
    cudaGetSymbolAddress((void**)&p_W2l,   d_W2l);
    cudaGetSymbolAddress((void**)&p_W3h,   d_W3h);
    cudaGetSymbolAddress((void**)&p_W3l,   d_W3l);
    cudaGetSymbolAddress((void**)&p_x1h,   d_x1h);
    cudaGetSymbolAddress((void**)&p_x1l,   d_x1l);
    cudaGetSymbolAddress((void**)&p_x2h,   d_x2h);
    cudaGetSymbolAddress((void**)&p_x2l,   d_x2l);

    cudaFuncSetAttribute(gemm_wb<0>, cudaFuncAttributeMaxDynamicSharedMemorySize,
                         WB_SMEM);
    cudaFuncSetAttribute(gemm_wb<1>, cudaFuncAttributeMaxDynamicSharedMemorySize,
                         WB_SMEM);
    cudaFuncSetAttribute(gemm_wb<2>, cudaFuncAttributeMaxDynamicSharedMemorySize,
                         WB_SMEM);
    cudaFuncSetAttribute(gemm_ws, cudaFuncAttributeMaxDynamicSharedMemorySize,
                         WS_SMEM);

    // 1-3: sort, gather(+bf16 split), convert eaW
    setup_kernel<<<1, BBS>>>(caplen, caps, out);
    gather_enc_kernel<<<50176, 256>>>(enc_out);
    conv_kernel<<<(1024 * 1024) / 256, 256>>>(eaW, p_eaWh, p_eaWl, 1024, 2048);

    // 4: att1 (bf16x3 mma.sync): 25088 x 1024, K=2048  <- profiled slot
    gemm_wb<1><<<dim3(1024 / 128, (BBS * PPS) / 128), 256, WB_SMEM>>>(
        p_ench, p_encl, p_eaWh, p_eaWl, eab, p_att1, 2048, 1024, 1024, 1024);

    // 5+: mean, zero pred, biases, weight concats + conversions
    mean_kernel<<<(BBS * ENCD) / 256, 256>>>();
    zero_pred_kernel<<<84000, 256>>>(out + O_PRED);
    bias_kernel<<<16, 256>>>(l1bih, l1bhh, l2bih, l2bhh, dab, fbb);
    w1copy_kernel<<<8192, 256>>>(l1Wih, l1Whh);
    w2copy_kernel<<<16384, 256>>>(l2Wih, l2Whh);
    w3copy_kernel<<<3072, 256>>>(daW, fbW);
    conv_kernel<<<(4096 * 512) / 256, 256>>>(l1Wih, p_W1eh, p_W1el, 512, 4096);
    conv_kernel<<<(4096 * 1024) / 256, 256>>>(p_W1c, p_W1h, p_W1l, 1024, 2048);
    conv_kernel<<<(4096 * 2048) / 256, 256>>>(p_W2c, p_W2h, p_W2l, 2048, 4096);
    conv_kernel<<<(3072 * 512) / 256, 256>>>(p_W3c, p_W3h, p_W3l, 512, 1024);

    // embeddings (bf16 split)
    embg_kernel<<<TTS * BBS, 256>>>(emb);

    // econ (bf16x3): 2688 x 4096, K=1024
    gemm_wb<0><<<dim3(4096 / 128, (TTS * BBS) / 128), 256, WB_SMEM>>>(
        p_embgh, p_embgl, p_W1eh, p_W1el, nullptr, p_econ, 1024, 512, 512, 4096);

    // ramW conversion (for preds later)
    conv_kernel<<<(VOC * 512) / 256, 256>>>(ramW, p_ramWh, p_ramWl, 512, 1024);

    // base1 = mean_enc @ Wih[:,2048:].T + (bih+bhh)
    gemm32sk<<<dim3(4096 / 128, 4), 128>>>(
        p_mean, l1Wih + 2048, p_b1, p_base1, 4096, 2048, 2048, 4096);

    zero_states_kernel<<<(BBS * 2048) / 256, 256>>>();

    // sequential decode: HMMA split-K partials -> pointwise epilogues
    for (int t = 0; t < TTS; ++t) {
        gemm_ws<<<dim3(32, 4, 8), 256, WS_SMEM>>>(
            p_x1h, p_x1l, p_W1h, p_W1l, p_gp, 4096, 256, 1024, 1024, t);

        lstm1_kernel<<<(BBS * DHID / 2) / 256, 256>>>(
            t, p_econ + (size_t)t * BBS * 4096);

        gemm_ws<<<dim3(24, 4, 4), 256, WS_SMEM>>>(
            p_x2h + 1024, p_x2l + 1024, p_W3h, p_W3l, p_ap,
            3072, 256, 2048, 512, t);

        attn_kernel<<<BBS, 256>>>(faW, fab, t);

        gemm_ws<<<dim3(32, 4, 8), 256, WS_SMEM>>>(
            p_x2h, p_x2l, p_W2h, p_W2l, p_gp, 4096, 512, 2048, 2048, t);

        lstm2_kernel<<<(BBS * DHID / 2) / 256, 256>>>(t);
    }

    // preds (bf16x3, compact gather/scatter)
    gemm_wb<2><<<dim3(VOC / 128, (TTS * BBS + 127) / 128), 256, WB_SMEM>>>(
        p_h2h, p_h2l, p_ramWh, p_ramWl, ramb, out + O_PRED, 1024, 512, 512, VOC);

    // predicted_pos
    rpm_kernel<<<(TTS * BBS + 7) / 8, 256>>>(rpmW, out);
}

// round 17
// speedup vs baseline: 1.9231x; 1.0403x over previous
#include <cuda_runtime.h>
#include <cuda_bf16.h>
#include <mma.h>
#include <math.h>
using namespace nvcuda;

// ---------------------------------------------------------------------------
// Problem constants
// ---------------------------------------------------------------------------
#define TTS   21
#define CAPL  22
#define BBS   128
#define PPS   196
#define ENCD  2048
#define DHID  1024
#define VOC   32000

static constexpr long long O_PRED = 0;
static constexpr long long O_CAPS = (long long)BBS * TTS * VOC;
static constexpr long long O_DECL = O_CAPS + (long long)BBS * CAPL;
static constexpr long long O_SORT = O_DECL + BBS;
static constexpr long long O_RPOS = O_SORT + BBS;
static constexpr long long O_PPOS = O_RPOS + (long long)BBS * TTS;

// ---------------------------------------------------------------------------
// Static device scratch
// ---------------------------------------------------------------------------
__device__ float d_encs [(size_t)BBS * PPS * ENCD];
__device__ float d_att1 [(size_t)BBS * PPS * DHID];
__device__ float d_econ [(size_t)TTS * BBS * 4 * DHID];
__device__ float d_W1cat[4096 * 2048];
__device__ float d_W2cat[(size_t)4096 * 4096];
__device__ float d_W3cat[3072 * 1024];
__device__ float d_b1sum[4096];
__device__ float d_b2sum[4096];
__device__ float d_b3cat[3072];
__device__ float d_base1[BBS * 4096];
__device__ float d_gp   [(size_t)8 * BBS * 4096];   // 8 split-K slabs
__device__ float d_ap   [(size_t)4 * BBS * 3072];   // 4 split-K slabs
__device__ float d_c1   [BBS * DHID];
__device__ float d_c2   [BBS * DHID];
__device__ float d_mean [BBS * ENCD];
__device__ float d_h2all[(size_t)TTS * BBS * DHID];
__device__ int   d_sort  [BBS];
__device__ int   d_declen[BBS];
__device__ int   d_tokens[TTS * BBS];
__device__ int   d_nact  [TTS];
__device__ int   d_rowidx[TTS * BBS];
__device__ int   d_outrow[TTS * BBS];
__device__ int   d_cnt;

// bf16 hi/lo buffers (packed bf16x2 in uint32, row-major)
__device__ unsigned int d_ench [(size_t)BBS * PPS * (ENCD / 2)];
__device__ unsigned int d_encl [(size_t)BBS * PPS * (ENCD / 2)];
__device__ unsigned int d_eaWh [1024 * (ENCD / 2)];
__device__ unsigned int d_eaWl [1024 * (ENCD / 2)];
__device__ unsigned int d_W1eh [4096 * (DHID / 2)];
__device__ unsigned int d_W1el [4096 * (DHID / 2)];
__device__ unsigned int d_embgh[TTS * BBS * (DHID / 2)];
__device__ unsigned int d_embgl[TTS * BBS * (DHID / 2)];
__device__ unsigned int d_ramWh[(size_t)VOC * (DHID / 2)];
__device__ unsigned int d_ramWl[(size_t)VOC * (DHID / 2)];
__device__ unsigned int d_h2h  [TTS * BBS * (DHID / 2)];
__device__ unsigned int d_h2l  [TTS * BBS * (DHID / 2)];
// loop-GEMM operands
__device__ unsigned int d_W1h  [4096 * 1024];
__device__ unsigned int d_W1l  [4096 * 1024];
__device__ unsigned int d_W2h  [(size_t)4096 * 2048];
__device__ unsigned int d_W2l  [(size_t)4096 * 2048];
__device__ unsigned int d_W3h  [3072 * 512];
__device__ unsigned int d_W3l  [3072 * 512];
__device__ unsigned int d_x1h  [BBS * 1024];
__device__ unsigned int d_x1l  [BBS * 1024];
__device__ unsigned int d_x2h  [BBS * 2048];
__device__ unsigned int d_x2l  [BBS * 2048];

// ---------------------------------------------------------------------------
// Helpers
// ---------------------------------------------------------------------------
__device__ __forceinline__ float sigf(float x) {
    return 1.0f / (1.0f + __expf(-x));
}
__device__ __forceinline__ float tanh_fast(float x) {
    return 1.0f - 2.0f / (__expf(2.0f * x) + 1.0f);
}
__device__ __forceinline__ unsigned int pack_hi(float a, float b) {
    __nv_bfloat162 p = __floats2bfloat162_rn(a, b);
    return *reinterpret_cast<unsigned int*>(&p);
}
__device__ __forceinline__ unsigned int pack_lo(float a, float b) {
    float ah = __bfloat162float(__float2bfloat16_rn(a));
    float bh = __bfloat162float(__float2bfloat16_rn(b));
    __nv_bfloat162 p = __floats2bfloat162_rn(a - ah, b - bh);
    return *reinterpret_cast<unsigned int*>(&p);
}
__device__ __forceinline__ unsigned int smem_u32(const void* p) {
    unsigned int a;
    asm("{ .reg .u64 t; cvta.to.shared.u64 t, %1; cvt.u32.u64 %0, t; }"
        : "=r"(a) : "l"(p));
    return a;
}
__device__ __forceinline__ void cp16(unsigned int dst, const void* src) {
    asm volatile("cp.async.cg.shared.global [%0], [%1], 16;"
                 :: "r"(dst), "l"(__cvta_generic_to_global(src)) : "memory");
}
__device__ __forceinline__ void ldsm4(unsigned int* r, unsigned int addr) {
    asm volatile("ldmatrix.sync.aligned.m8n8.x4.shared.b16 {%0,%1,%2,%3}, [%4];"
                 : "=r"(r[0]), "=r"(r[1]), "=r"(r[2]), "=r"(r[3]) : "r"(addr));
}
__device__ __forceinline__ void ldsm2(unsigned int* r, unsigned int addr) {
    asm volatile("ldmatrix.sync.aligned.m8n8.x2.shared.b16 {%0,%1}, [%2];"
                 : "=r"(r[0]), "=r"(r[1]) : "r"(addr));
}
__device__ __forceinline__ void mma16816(float* d, const unsigned int* a,
                                         const unsigned int* b) {
    asm volatile(
        "mma.sync.aligned.m16n8k16.row.col.f32.bf16.bf16.f32 "
        "{%0,%1,%2,%3}, {%4,%5,%6,%7}, {%8,%9}, {%0,%1,%2,%3};"
        : "+f"(d[0]), "+f"(d[1]), "+f"(d[2]), "+f"(d[3])
        : "r"(a[0]), "r"(a[1]), "r"(a[2]), "r"(a[3]), "r"(b[0]), "r"(b[1]));
}

// ---------------------------------------------------------------------------
// Big bf16x3 GEMM, hand-rolled mma.sync.m16n8k16 (128x128 tile, 2 blk/SM).
// MODE 0: plain  MODE 1: +bias  MODE 2: +bias + gather/scatter (preds)
// MODE 3: split-K slab variant: grid.z = slab index; per-slab K is the K
//         argument; operands offset by z*K/2 u32; output written to slab
//         C + z*BBS*ldc (no bias, full M=128).
// ---------------------------------------------------------------------------
static constexpr int WB_SMEM = 81920;

template<int MODE>
__global__ void __launch_bounds__(256, 2)
gemm_wb(const unsigned int* __restrict__ Ah, const unsigned int* __restrict__ Al,
        const unsigned int* __restrict__ Bh, const unsigned int* __restrict__ Bl,
        const float* __restrict__ bias, float* __restrict__ C,
        int K, int lda32, int ldb32, int ldc) {
    extern __shared__ char smem[];
    const int tid = threadIdx.x;
    const int warp = tid >> 5;
    const int lane = tid & 31;
    const int m0 = (MODE == 3) ? 0 : blockIdx.y * 128;
    const int n0 = blockIdx.x * 128;
    int count = 0;
    if (MODE == 2) {
        count = d_cnt;
        if (m0 >= count) return;
    }
    const int ko32 = (MODE == 3) ? blockIdx.z * (K >> 1) : 0;
    float* Cb = (MODE == 3) ? C + (size_t)blockIdx.z * BBS * ldc : C;

    const int lr = tid >> 1;
    const int lc = (tid & 1) * 8;
    int arow = m0 + lr;
    if (MODE == 2) arow = (arow < count) ? d_rowidx[arow] : d_rowidx[0];
    const unsigned int* gA0 = Ah + (size_t)arow * lda32 + ko32 + lc;
    const unsigned int* gA1 = Al + (size_t)arow * lda32 + ko32 + lc;
    const unsigned int* gB0 = Bh + (size_t)(n0 + lr) * ldb32 + ko32 + lc;
    const unsigned int* gB1 = Bl + (size_t)(n0 + lr) * ldb32 + ko32 + lc;

    const unsigned int sbase = smem_u32(smem);
    const unsigned int drow = (unsigned)(lr * 80 + lc * 4);

    const int wm = (warp >> 1) * 32;
    const int wn = (warp & 1) * 64;

    // per-lane ldmatrix address components (elements stride 40 -> 80 bytes)
    const int li = lane & 7;
    const int lt = lane >> 3;
    const unsigned int aRow0 =
        (unsigned)((wm + li + ((lt & 1) << 3)) * 80 + ((lt >> 1) << 4));
    const unsigned int aRow1 = aRow0 + 16 * 80;
    const unsigned int bRow0 =
        (unsigned)((wn + li) * 80 + ((lt & 1) << 4));

    float acc[2][8][4];
    #pragma unroll
    for (int i = 0; i < 2; ++i)
        #pragma unroll
        for (int j = 0; j < 8; ++j)
            #pragma unroll
            for (int q = 0; q < 4; ++q) acc[i][j][q] = 0.f;

    const int nch = K >> 5;
    {
        unsigned int d0 = sbase + drow;
        cp16(d0,             gA0); cp16(d0 + 16,         gA0 + 4);
        cp16(d0 + 10240,     gA1); cp16(d0 + 10240 + 16, gA1 + 4);
        cp16(d0 + 20480,     gB0); cp16(d0 + 20480 + 16, gB0 + 4);
        cp16(d0 + 30720,     gB1); cp16(d0 + 30720 + 16, gB1 + 4);
        asm volatile("cp.async.commit_group;" ::: "memory");
    }

    for (int ch = 0; ch < nch; ++ch) {
        const int buf = ch & 1;
        if (ch + 1 < nch) {
            const int kw = (ch + 1) * 16;
            unsigned int d0 = sbase + (buf ^ 1) * 40960 + drow;
            cp16(d0,             gA0 + kw); cp16(d0 + 16,         gA0 + kw + 4);
            cp16(d0 + 10240,     gA1 + kw); cp16(d0 + 10240 + 16, gA1 + kw + 4);
            cp16(d0 + 20480,     gB0 + kw); cp16(d0 + 20480 + 16, gB0 + kw + 4);
            cp16(d0 + 30720,     gB1 + kw); cp16(d0 + 30720 + 16, gB1 + kw + 4);
            asm volatile("cp.async.commit_group;" ::: "memory");
            asm volatile("cp.async.wait_group 1;" ::: "memory");
        } else {
            asm volatile("cp.async.wait_group 0;" ::: "memory");
        }
        __syncthreads();

        const unsigned int base = sbase + buf * 40960;

        #pragma unroll
        for (int kk = 0; kk < 32; kk += 16) {
            const unsigned int kb = (unsigned)(kk * 2);
            unsigned int ah0[4], ah1[4], al0[4], al1[4];
            ldsm4(ah0, base + aRow0 + kb);
            ldsm4(ah1, base + aRow1 + kb);
            ldsm4(al0, base + 10240 + aRow0 + kb);
            ldsm4(al1, base + 10240 + aRow1 + kb);

            unsigned int bh0[2], bl0[2], bh1[2], bl1[2];
            ldsm2(bh0, base + 20480 + bRow0 + kb);
            ldsm2(bl0, base + 30720 + bRow0 + kb);

            #pragma unroll
            for (int j = 0; j < 8; ++j) {
                unsigned int* bhc = (j & 1) ? bh1 : bh0;
                unsigned int* blc = (j & 1) ? bl1 : bl0;
                if (j < 7) {
                    unsigned int* bhn = (j & 1) ? bh0 : bh1;
                    unsigned int* bln = (j & 1) ? bl0 : bl1;
                    unsigned int off = (unsigned)((j + 1) * 640);
                    ldsm2(bhn, base + 20480 + bRow0 + off + kb);
                    ldsm2(bln, base + 30720 + bRow0 + off + kb);
                }
                mma16816(acc[0][j], ah0, bhc);
                mma16816(acc[1][j], ah1, bhc);
                mma16816(acc[0][j], al0, bhc);
                mma16816(acc[1][j], al1, bhc);
                mma16816(acc[0][j], ah0, blc);
                mma16816(acc[1][j], ah1, blc);
            }
        }
        __syncthreads();
    }

    // stage accumulators through smem, then masked/scattered scalar stores
    float* outs = (float*)smem;
    {
        const int r = lane >> 2;
        const int c = (lane & 3) * 2;
        #pragma unroll
        for (int mi = 0; mi < 2; ++mi)
            #pragma unroll
            for (int j = 0; j < 8; ++j) {
                float* o = outs + (size_t)(wm + mi * 16 + r) * 128
                         + wn + j * 8 + c;
                o[0] = acc[mi][j][0];
                o[1] = acc[mi][j][1];
                o[8 * 128] = acc[mi][j][2];
                o[8 * 128 + 1] = acc[mi][j][3];
            }
    }
    __syncthreads();

    for (int i = tid; i < 128 * 128; i += 256) {
        int m = i >> 7, n = i & 127;
        float v = outs[i];
        int gm = m0 + m, gn = n0 + n;
        if (MODE == 1 || MODE == 2) v += bias[gn];
        if (MODE == 2) {
            if (gm >= count) continue;
            Cb[(long long)d_outrow[gm] * ldc + gn] = v;
        } else {
            Cb[(size_t)gm * ldc + gn] = v;
        }
    }
}

// ---------------------------------------------------------------------------
// fp32 -> bf16 hi/lo conversion (2 elems per thread)
// ---------------------------------------------------------------------------
__global__ void conv_kernel(const float* __restrict__ src,
                            unsigned int* __restrict__ dh,
                            unsigned int* __restrict__ dl,
                            int cols2, int src_ld) {
    size_t idx = (size_t)blockIdx.x * 256 + threadIdx.x;
    size_t row = idx / cols2;
    int cp = (int)(idx - row * cols2);
    const float* s = src + row * (size_t)src_ld + (size_t)cp * 2;
    float a = s[0], b = s[1];
    dh[row * cols2 + cp] = pack_hi(a, b);
    dl[row * cols2 + cp] = pack_lo(a, b);
}

// ---------------------------------------------------------------------------
// Setup / gather / small kernels (unchanged)
// ---------------------------------------------------------------------------
__global__ void setup_kernel(const int* __restrict__ caplen,
                             const int* __restrict__ caps,
                             float* __restrict__ out) {
    __shared__ int lens_s[BBS];
    __shared__ int sort_s[BBS];
    __shared__ int dl_s[BBS];
    int i = threadIdx.x;
    int li = caplen[i];
    lens_s[i] = li;
    __syncthreads();
    int rank = 0;
    for (int j = 0; j < BBS; ++j) {
        int lj = lens_s[j];
        if (lj > li || (lj == li && j < i)) rank++;
    }
    sort_s[rank] = i;
    __syncthreads();
    int src = sort_s[i];
    d_sort[i] = src;
    int dl = lens_s[src] - 1;
    d_declen[i] = dl;
    dl_s[i] = dl;
    out[O_DECL + i] = (float)dl;
    out[O_SORT + i] = (float)src;
    for (int t = 0; t < CAPL; ++t) {
        int tok = caps[src * CAPL + t];
        out[O_CAPS + (long long)i * CAPL + t] = (float)tok;
        if (t < TTS) d_tokens[t * BBS + i] = tok;
    }
    float dlf = (float)dl;
    for (int s = 0; s < TTS; ++s)
        out[O_RPOS + (long long)i * TTS + s] =
            (s < dl) ? ((float)(s + 1) / dlf) : 0.0f;
    __syncthreads();
    if (i == 0) {
        int c = 0;
        for (int t = 0; t < TTS; ++t) {
            int n = 0;
            while (n < BBS && dl_s[n] > t) n++;
            d_nact[t] = n;
            for (int b = 0; b < n; ++b) {
                d_rowidx[c] = t * BBS + b;
                d_outrow[c] = b * TTS + t;
                c++;
            }
        }
        d_cnt = c;
    }
}

__global__ void gather_enc_kernel(const float* __restrict__ enc) {
    int g = blockIdx.x * 256 + threadIdx.x;
    int r = g >> 9, w = g & 511;
    int b = r / PPS, p = r % PPS;
    int srow = d_sort[b] * PPS + p;
    float4 v = ((const float4*)enc)[(size_t)srow * 512 + w];
    ((float4*)d_encs)[(size_t)r * 512 + w] = v;
    size_t o = (size_t)r * 1024 + (size_t)w * 2;
    d_ench[o]     = pack_hi(v.x, v.y);
    d_ench[o + 1] = pack_hi(v.z, v.w);
    d_encl[o]     = pack_lo(v.x, v.y);
    d_encl[o + 1] = pack_lo(v.z, v.w);
}

__global__ void mean_kernel() {
    int idx = blockIdx.x * 256 + threadIdx.x;
    int b = idx / ENCD, e = idx % ENCD;
    const float* base = d_encs + (size_t)b * PPS * ENCD + e;
    float s = 0.f;
    #pragma unroll 4
    for (int p = 0; p < PPS; ++p) s += base[(size_t)p * ENCD];
    d_mean[idx] = s * (1.0f / (float)PPS);
}

__global__ void w1copy_kernel(const float* __restrict__ l1Wih,
                              const float* __restrict__ l1Whh) {
    int g = blockIdx.x * 256 + threadIdx.x;
    int j = g / (2048 / 4);
    int c = (g % (2048 / 4)) * 4;
    float4 v;
    if (c < 1024) v = *(const float4*)(l1Wih + (size_t)j * 4096 + 1024 + c);
    else          v = *(const float4*)(l1Whh + (size_t)j * 1024 + (c - 1024));
    *(float4*)(d_W1cat + (size_t)j * 2048 + c) = v;
}

__global__ void w2copy_kernel(const float* __restrict__ l2Wih,
                              const float* __restrict__ l2Whh) {
    int g = blockIdx.x * 256 + threadIdx.x;
    int j = g / (4096 / 4);
    int c = (g % (4096 / 4)) * 4;
    float4 v;
    if (c < 3072) v = *(const float4*)(l2Wih + (size_t)j * 3072 + c);
    else          v = *(const float4*)(l2Whh + (size_t)j * 1024 + (c - 3072));
    *(float4*)(d_W2cat + (size_t)j * 4096 + c) = v;
}

__global__ void w3copy_kernel(const float* __restrict__ daW,
                              const float* __restrict__ fbW) {
    int g = blockIdx.x * 256 + threadIdx.x;
    int j = g / (1024 / 4);
    int c = (g % (1024 / 4)) * 4;
    float4 v;
    if (j < 1024) v = *(const float4*)(daW + (size_t)j * 1024 + c);
    else          v = *(const float4*)(fbW + (size_t)(j - 1024) * 1024 + c);
    *(float4*)(d_W3cat + (size_t)j * 1024 + c) = v;
}

__global__ void bias_kernel(const float* __restrict__ l1bih,
                            const float* __restrict__ l1bhh,
                            const float* __restrict__ l2bih,
                            const float* __restrict__ l2bhh,
                            const float* __restrict__ dab,
                            const float* __restrict__ fbb) {
    int j = blockIdx.x * 256 + threadIdx.x;
    d_b1sum[j] = l1bih[j] + l1bhh[j];
    d_b2sum[j] = l2bih[j] + l2bhh[j];
    if (j < 3072) d_b3cat[j] = (j < 1024) ? dab[j] : fbb[j - 1024];
}

__global__ void embg_kernel(const float* __restrict__ emb) {
    int m = blockIdx.x;
    int tok = d_tokens[m];
    const float2* src = (const float2*)(emb + (size_t)tok * DHID);
    #pragma unroll
    for (int q = 0; q < 2; ++q) {
        int i = threadIdx.x + 256 * q;
        float2 v = src[i];
        d_embgh[(size_t)m * 512 + i] = pack_hi(v.x, v.y);
        d_embgl[(size_t)m * 512 + i] = pack_lo(v.x, v.y);
    }
}

__global__ void zero_states_kernel() {
    int idx = blockIdx.x * 256 + threadIdx.x;
    d_x2h[idx] = 0u; d_x2l[idx] = 0u;
    if (idx < BBS * 1024) { d_x1h[idx] = 0u; d_x1l[idx] = 0u; }
    if (idx < BBS * DHID) { d_c1[idx] = 0.f; d_c2[idx] = 0.f; }
}

__global__ void zero_pred_kernel(float* __restrict__ out) {
    size_t g = (size_t)blockIdx.x * 256 + threadIdx.x;
    ((float4*)out)[g] = make_float4(0.f, 0.f, 0.f, 0.f);
}

// ---------------------------------------------------------------------------
// Plain SIMT split-K GEMM (base1 only; runs once)
// ---------------------------------------------------------------------------
__global__ void __launch_bounds__(128)
gemm32sk(const float* __restrict__ A,
         const float* __restrict__ Bm,
         const float* __restrict__ bias,
         float* __restrict__ C,
         int N, int Kc, int lda, int ldb) {
    const int m0 = blockIdx.y * 32;
    __shared__ float As[16][36];
    __shared__ float Bs[16][132];
    const int tid = threadIdx.x;
    const int n0 = blockIdx.x * 128;

    const int ar = tid >> 2;
    const int ac = (tid & 3) * 4;
    const float* Aptr = A + (size_t)(m0 + ar) * lda + ac;
    const float* Bptr = Bm + (size_t)(n0 + tid) * ldb;

    const int ty = tid >> 4;
    const int tx = tid & 15;

    float acc[4][8];
    #pragma unroll
    for (int i = 0; i < 4; ++i)
        #pragma unroll
        for (int j = 0; j < 8; ++j) acc[i][j] = 0.f;

    float4 pav = *(const float4*)(Aptr);
    float4 pb[4];
    #pragma unroll
    for (int j = 0; j < 4; ++j) pb[j] = *(const float4*)(Bptr + j * 4);

    for (int k0 = 0; k0 < Kc; k0 += 16) {
        As[ac + 0][ar] = pav.x; As[ac + 1][ar] = pav.y;
        As[ac + 2][ar] = pav.z; As[ac + 3][ar] = pav.w;
        #pragma unroll
        for (int j = 0; j < 4; ++j) {
            Bs[j * 4 + 0][tid] = pb[j].x; Bs[j * 4 + 1][tid] = pb[j].y;
            Bs[j * 4 + 2][tid] = pb[j].z; Bs[j * 4 + 3][tid] = pb[j].w;
        }
        __syncthreads();
        if (k0 + 16 < Kc) {
            pav = *(const float4*)(Aptr + k0 + 16);
            #pragma unroll
            for (int j = 0; j < 4; ++j)
                pb[j] = *(const float4*)(Bptr + k0 + 16 + j * 4);
        }
        #pragma unroll
        for (int kk = 0; kk < 16; ++kk) {
            float a[4], b[8];
            *(float4*)(a)     = *(const float4*)&As[kk][ty * 4];
            *(float4*)(b)     = *(const float4*)&Bs[kk][tx * 4];
            *(float4*)(b + 4) = *(const float4*)&Bs[kk][64 + tx * 4];
            #pragma unroll
            for (int i = 0; i < 4; ++i)
                #pragma unroll
                for (int j = 0; j < 8; ++j)
                    acc[i][j] = fmaf(a[i], b[j], acc[i][j]);
        }
        __syncthreads();
    }

    float bv[8];
    #pragma unroll
    for (int j = 0; j < 8; ++j) {
        int n = (j < 4) ? (n0 + tx * 4 + j) : (n0 + 64 + tx * 4 + j - 4);
        bv[j] = bias[n];
    }

    #pragma unroll
    for (int i = 0; i < 4; ++i) {
        int m = m0 + ty * 4 + i;
        float* dst = C + (size_t)m * N + n0;
        float4 v0, v1;
        v0.x = acc[i][0] + bv[0]; v0.y = acc[i][1] + bv[1];
        v0.z = acc[i][2] + bv[2]; v0.w = acc[i][3] + bv[3];
        v1.x = acc[i][4] + bv[4]; v1.y = acc[i][5] + bv[5];
        v1.z = acc[i][6] + bv[6]; v1.w = acc[i][7] + bv[7];
        *(float4*)(dst + tx * 4)      = v0;
        *(float4*)(dst + 64 + tx * 4) = v1;
    }
}

// ---------------------------------------------------------------------------
// LSTM pointwise: sums 8 split-K slabs, writes bf16 states.
// ---------------------------------------------------------------------------
__global__ void lstm1_kernel(int t, const float* __restrict__ econ_t) {
    int idx = blockIdx.x * 256 + threadIdx.x;
    int b = idx >> 9, q = idx & 511;
    if (t >= d_declen[b]) return;
    size_t base = (size_t)b * 4096;
    float2 g[4];
    #pragma unroll
    for (int qt = 0; qt < 4; ++qt) {
        int j = qt * 1024 + q * 2;
        float2 v = *(const float2*)(d_base1 + base + j);
        float2 e = *(const float2*)(econ_t + base + j);
        v.x += e.x; v.y += e.y;
        #pragma unroll
        for (int s = 0; s < 8; ++s) {
            float2 p = *(const float2*)(d_gp + (size_t)s * BBS * 4096 + base + j);
            v.x += p.x; v.y += p.y;
        }
        g[qt] = v;
    }
    float2 c = *(const float2*)(d_c1 + (size_t)b * 1024 + q * 2);
    float cn0 = sigf(g[1].x) * c.x + sigf(g[0].x) * tanhf(g[2].x);
    float cn1 = sigf(g[1].y) * c.y + sigf(g[0].y) * tanhf(g[2].y);
    float hn0 = sigf(g[3].x) * tanhf(cn0);
    float hn1 = sigf(g[3].y) * tanhf(cn1);
    *(float2*)(d_c1 + (size_t)b * 1024 + q * 2) = make_float2(cn0, cn1);
    unsigned int hi = pack_hi(hn0, hn1), lo = pack_lo(hn0, hn1);
    d_x1h[b * 1024 + 512 + q] = hi;  d_x1l[b * 1024 + 512 + q] = lo;
    d_x2h[b * 2048 + 1024 + q] = hi; d_x2l[b * 2048 + 1024 + q] = lo;
}

__global__ void lstm2_kernel(int t) {
    int idx = blockIdx.x * 256 + threadIdx.x;
    int b = idx >> 9, q = idx & 511;
    if (t >= d_declen[b]) return;
    size_t base = (size_t)b * 4096;
    float2 g[4];
    #pragma unroll
    for (int qt = 0; qt < 4; ++qt) {
        int j = qt * 1024 + q * 2;
        float2 v = *(const float2*)(d_b2sum + j);
        #pragma unroll
        for (int s = 0; s < 8; ++s) {
            float2 p = *(const float2*)(d_gp + (size_t)s * BBS * 4096 + base + j);
            v.x += p.x; v.y += p.y;
        }
        g[qt] = v;
    }
    float2 c = *(const float2*)(d_c2 + (size_t)b * 1024 + q * 2);
    float cn0 = sigf(g[1].x) * c.x + sigf(g[0].x) * tanhf(g[2].x);
    float cn1 = sigf(g[1].y) * c.y + sigf(g[0].y) * tanhf(g[2].y);
    float hn0 = sigf(g[3].x) * tanhf(cn0);
    float hn1 = sigf(g[3].y) * tanhf(cn1);
    *(float2*)(d_c2 + (size_t)b * 1024 + q * 2) = make_float2(cn0, cn1);
    size_t hrow = (size_t)(t * BBS + b);
    *(float2*)(d_h2all + hrow * 1024 + q * 2) = make_float2(hn0, hn1);
    unsigned int hi = pack_hi(hn0, hn1), lo = pack_lo(hn0, hn1);
    d_h2h[hrow * 512 + q] = hi;      d_h2l[hrow * 512 + q] = lo;
    d_x1h[b * 1024 + q] = hi;        d_x1l[b * 1024 + q] = lo;
    d_x2h[b * 2048 + 1536 + q] = hi; d_x2l[b * 2048 + 1536 + q] = lo;
}

// ---------------------------------------------------------------------------
// Fused attention; att2/gate = b3 + 4 split-K partial slabs; writes bf16 att.
// ---------------------------------------------------------------------------
__global__ void attn_kernel(const float* __restrict__ fullW,
                            const float* __restrict__ fullb, int t) {
    const int b = blockIdx.x;
    if (t >= d_declen[b]) return;
    __shared__ float s_a2[DHID];
    __shared__ float s_w [DHID];
    __shared__ float s_sc[PPS];
    __shared__ float s_red[256];
    const int tid = threadIdx.x;
    const int lane = tid & 31, warp = tid >> 5;
    const size_t abase = (size_t)b * 3072;

    for (int i = tid; i < DHID; i += 256) {
        float v = d_b3cat[i];
        #pragma unroll
        for (int s = 0; s < 4; ++s)
            v += d_ap[(size_t)s * BBS * 3072 + abase + i];
        s_a2[i] = v;
        s_w[i]  = fullW[i];
    }
    __syncthreads();

    const float b0 = fullb[0];
    for (int p = warp; p < PPS; p += 8) {
        const float* row = d_att1 + ((size_t)b * PPS + p) * DHID;
        float s = 0.f;
        #pragma unroll 8
        for (int a = lane; a < DHID; a += 32)
            s += tanh_fast(row[a] + s_a2[a]) * s_w[a];
        #pragma unroll
        for (int o = 16; o > 0; o >>= 1)
            s += __shfl_down_sync(0xffffffffu, s, o);
        if (lane == 0) s_sc[p] = s + b0;
    }
    __syncthreads();

    s_red[tid] = (tid < PPS) ? s_sc[tid] : -INFINITY;
    __syncthreads();
    for (int s = 128; s > 0; s >>= 1) {
        if (tid < s) s_red[tid] = fmaxf(s_red[tid], s_red[tid + s]);
        __syncthreads();
    }
    float mx = s_red[0];
    __syncthreads();
    float e = 0.f;
    if (tid < PPS) e = __expf(s_sc[tid] - mx);
    s_red[tid] = e;
    __syncthreads();
    for (int s = 128; s > 0; s >>= 1) {
        if (tid < s) s_red[tid] += s_red[tid + s];
        __syncthreads();
    }
    float inv = 1.0f / s_red[0];
    __syncthreads();
    if (tid < PPS) s_sc[tid] = e * inv;
    __syncthreads();

    const float* encb = d_encs + (size_t)b * PPS * ENCD;
    for (int e2 = tid; e2 < ENCD / 2; e2 += 256) {
        int ei = e2 * 2;
        float a0 = 0.f, a1 = 0.f;
        const float* col = encb + ei;
        #pragma unroll 4
        for (int p = 0; p < PPS; ++p) {
            float al = s_sc[p];
            a0 = fmaf(al, col[(size_t)p * ENCD], a0);
            a1 = fmaf(al, col[(size_t)p * ENCD + 1], a1);
        }
        float gl0 = d_b3cat[1024 + ei];
        float gl1 = d_b3cat[1024 + ei + 1];
        #pragma unroll
        for (int s = 0; s < 4; ++s) {
            gl0 += d_ap[(size_t)s * BBS * 3072 + abase + 1024 + ei];
            gl1 += d_ap[(size_t)s * BBS * 3072 + abase + 1024 + ei + 1];
        }
        float v0 = sigf(gl0) * a0, v1 = sigf(gl1) * a1;
        d_x2h[b * 2048 + e2] = pack_hi(v0, v1);
        d_x2l[b * 2048 + e2] = pack_lo(v0, v1);
    }
}

__global__ void rpm_kernel(const float* __restrict__ rpmW,
                           float* __restrict__ out) {
    int m = blockIdx.x * 8 + (threadIdx.x >> 5);
    if (m >= TTS * BBS) return;
    int lane = threadIdx.x & 31;
    int t = m / BBS, b = m % BBS;
    const float* h = d_h2all + (size_t)m * DHID;
    float s = 0.f;
    #pragma unroll 8
    for (int k = lane; k < DHID; k += 32) s += h[k] * rpmW[k];
    #pragma unroll
    for (int o = 16; o > 0; o >>= 1)
        s += __shfl_down_sync(0xffffffffu, s, o);
    if (lane == 0)
        out[O_PPOS + (long long)b * TTS + t] =
            (t < d_declen[b]) ? sigf(s) : 0.f;
}

// ---------------------------------------------------------------------------
// Launch
// ---------------------------------------------------------------------------
extern "C" void kernel_launch(void* const* d_in, const int* in_sizes, int n_in,
                              void* d_out, int out_size) {
    const float* enc_out = (const float*)d_in[0];
    const int*   caps    = (const int*)  d_in[1];
    const int*   caplen  = (const int*)  d_in[2];
    const float* emb     = (const float*)d_in[3];
    const float* eaW     = (const float*)d_in[4];
    const float* eab     = (const float*)d_in[5];
    const float* daW     = (const float*)d_in[6];
    const float* dab     = (const float*)d_in[7];
    const float* faW     = (const float*)d_in[8];
    const float* fab     = (const float*)d_in[9];
    const float* fbW     = (const float*)d_in[10];
    const float* fbb     = (const float*)d_in[11];
    const float* l1Wih   = (const float*)d_in[12];
    const float* l1Whh   = (const float*)d_in[13];
    const float* l1bih   = (const float*)d_in[14];
    const float* l1bhh   = (const float*)d_in[15];
    const float* l2Wih   = (const float*)d_in[16];
    const float* l2Whh   = (const float*)d_in[17];
    const float* l2bih   = (const float*)d_in[18];
    const float* l2bhh   = (const float*)d_in[19];
    const float* ramW    = (const float*)d_in[20];
    const float* ramb    = (const float*)d_in[21];
    const float* rpmW    = (const float*)d_in[22];
    float* out = (float*)d_out;

    float* p_att1;  cudaGetSymbolAddress((void**)&p_att1,  d_att1);
    float* p_econ;  cudaGetSymbolAddress((void**)&p_econ,  d_econ);
    float* p_W1c;   cudaGetSymbolAddress((void**)&p_W1c,   d_W1cat);
    float* p_W2c;   cudaGetSymbolAddress((void**)&p_W2c,   d_W2cat);
    float* p_W3c;   cudaGetSymbolAddress((void**)&p_W3c,   d_W3cat);
    float* p_b1;    cudaGetSymbolAddress((void**)&p_b1,    d_b1sum);
    float* p_base1; cudaGetSymbolAddress((void**)&p_base1, d_base1);
    float* p_gp;    cudaGetSymbolAddress((void**)&p_gp,    d_gp);
    float* p_ap;    cudaGetSymbolAddress((void**)&p_ap,    d_ap);
    float* p_mean;  cudaGetSymbolAddress((void**)&p_mean,  d_mean);
    unsigned int *p_ench, *p_encl, *p_eaWh, *p_eaWl, *p_W1eh, *p_W1el;
    unsigned int *p_embgh, *p_embgl, *p_ramWh, *p_ramWl, *p_h2h, *p_h2l;
    unsigned int *p_W1h, *p_W1l, *p_W2h, *p_W2l, *p_W3h, *p_W3l;
    unsigned int *p_x1h, *p_x1l, *p_x2h, *p_x2l;
    cudaGetSymbolAddress((void**)&p_ench,  d_ench);
    cudaGetSymbolAddress((void**)&p_encl,  d_encl);
    cudaGetSymbolAddress((void**)&p_eaWh,  d_eaWh);
    cudaGetSymbolAddress((void**)&p_eaWl,  d_eaWl);
    cudaGetSymbolAddress((void**)&p_W1eh,  d_W1eh);
    cudaGetSymbolAddress((void**)&p_W1el,  d_W1el);
    cudaGetSymbolAddress((void**)&p_embgh, d_embgh);
    cudaGetSymbolAddress((void**)&p_embgl, d_embgl);
    cudaGetSymbolAddress((void**)&p_ramWh, d_ramWh);
    cudaGetSymbolAddress((void**)&p_ramWl, d_ramWl);
    cudaGetSymbolAddress((void**)&p_h2h,   d_h2h);
    cudaGetSymbolAddress((void**)&p_h2l,   d_h2l);
    cudaGetSymbolAddress((void**)&p_W1h,   d_W1h);
    cudaGetSymbolAddress((void**)&p_W1l,   d_W1l);
    cudaGetSymbolAddress((void**)&p_W2h,   d_W2h);
    cudaGetSymbolAddress((void**)&p_W2l,   d_W2l);
    cudaGetSymbolAddress((void**)&p_W3h,   d_W3h);
    cudaGetSymbolAddress((void**)&p_W3l,   d_W3l);
    cudaGetSymbolAddress((void**)&p_x1h,   d_x1h);
    cudaGetSymbolAddress((void**)&p_x1l,   d_x1l);
    cudaGetSymbolAddress((void**)&p_x2h,   d_x2h);
    cudaGetSymbolAddress((void**)&p_x2l,   d_x2l);

    cudaFuncSetAttribute(gemm_wb<0>, cudaFuncAttributeMaxDynamicSharedMemorySize,
                         WB_SMEM);
    cudaFuncSetAttribute(gemm_wb<1>, cudaFuncAttributeMaxDynamicSharedMemorySize,
                         WB_SMEM);
    cudaFuncSetAttribute(gemm_wb<2>, cudaFuncAttributeMaxDynamicSharedMemorySize,
                         WB_SMEM);
    cudaFuncSetAttribute(gemm_wb<3>, cudaFuncAttributeMaxDynamicSharedMemorySize,
                         WB_SMEM);

    // 1-3: sort, gather(+bf16 split), convert eaW
    setup_kernel<<<1, BBS>>>(caplen, caps, out);
    gather_enc_kernel<<<50176, 256>>>(enc_out);
    conv_kernel<<<(1024 * 1024) / 256, 256>>>(eaW, p_eaWh, p_eaWl, 1024, 2048);

    // 4: att1 (bf16x3 mma.sync): 25088 x 1024, K=2048  <- profiled slot
    gemm_wb<1><<<dim3(1024 / 128, (BBS * PPS) / 128), 256, WB_SMEM>>>(
        p_ench, p_encl, p_eaWh, p_eaWl, eab, p_att1, 2048, 1024, 1024, 1024);

    // 5+: mean, zero pred, biases, weight concats + conversions
    mean_kernel<<<(BBS * ENCD) / 256, 256>>>();
    zero_pred_kernel<<<84000, 256>>>(out + O_PRED);
    bias_kernel<<<16, 256>>>(l1bih, l1bhh, l2bih, l2bhh, dab, fbb);
    w1copy_kernel<<<8192, 256>>>(l1Wih, l1Whh);
    w2copy_kernel<<<16384, 256>>>(l2Wih, l2Whh);
    w3copy_kernel<<<3072, 256>>>(daW, fbW);
    conv_kernel<<<(4096 * 512) / 256, 256>>>(l1Wih, p_W1eh, p_W1el, 512, 4096);
    conv_kernel<<<(4096 * 1024) / 256, 256>>>(p_W1c, p_W1h, p_W1l, 1024, 2048);
    conv_kernel<<<(4096 * 2048) / 256, 256>>>(p_W2c, p_W2h, p_W2l, 2048, 4096);
    conv_kernel<<<(3072 * 512) / 256, 256>>>(p_W3c, p_W3h, p_W3l, 512, 1024);

    // embeddings (bf16 split)
    embg_kernel<<<TTS * BBS, 256>>>(emb);

    // econ (bf16x3): 2688 x 4096, K=1024
    gemm_wb<0><<<dim3(4096 / 128, (TTS * BBS) / 128), 256, WB_SMEM>>>(
        p_embgh, p_embgl, p_W1eh, p_W1el, nullptr, p_econ, 1024, 512, 512, 4096);

    // ramW conversion (for preds later)
    conv_kernel<<<(VOC * 512) / 256, 256>>>(ramW, p_ramWh, p_ramWl, 512, 1024);

    // base1 = mean_enc @ Wih[:,2048:].T + (bih+bhh)
    gemm32sk<<<dim3(4096 / 128, 4), 128>>>(
        p_mean, l1Wih + 2048, p_b1, p_base1, 4096, 2048, 2048, 4096);

    zero_states_kernel<<<(BBS * 2048) / 256, 256>>>();

    // sequential decode: full-M 128x128 HMMA split-K (MODE 3) per GEMM.
    // Per-slab K: gates1 2048/8=256, att2 1024/4=256, gates2 4096/8=512.
    for (int t = 0; t < TTS; ++t) {
        gemm_wb<3><<<dim3(4096 / 128, 1, 8), 256, WB_SMEM>>>(
            p_x1h, p_x1l, p_W1h, p_W1l, nullptr, p_gp, 256, 1024, 1024, 4096);

        lstm1_kernel<<<(BBS * DHID / 2) / 256, 256>>>(
            t, p_econ + (size_t)t * BBS * 4096);

        gemm_wb<3><<<dim3(3072 / 128, 1, 4), 256, WB_SMEM>>>(
            p_x2h + 1024, p_x2l + 1024, p_W3h, p_W3l, nullptr, p_ap,
            256, 2048, 512, 3072);

        attn_kernel<<<BBS, 256>>>(faW, fab, t);

        gemm_wb<3><<<dim3(4096 / 128, 1, 8), 256, WB_SMEM>>>(
            p_x2h, p_x2l, p_W2h, p_W2l, nullptr, p_gp, 512, 2048, 2048, 4096);

        lstm2_kernel<<<(BBS * DHID / 2) / 256, 256>>>(t);
    }

    // preds (bf16x3, compact gather/scatter)
    gemm_wb<2><<<dim3(VOC / 128, (TTS * BBS + 127) / 128), 256, WB_SMEM>>>(
        p_h2h, p_h2l, p_ramWh, p_ramWl, ramb, out + O_PRED, 1024, 512, 512, VOC);

    // predicted_pos
    rpm_kernel<<<(TTS * BBS + 7) / 8, 256>>>(rpmW, out);
}